// round 1
// baseline (speedup 1.0000x reference)
#include <cuda_runtime.h>
#include <math.h>
#include <stdint.h>

// Problem constants
#define BB 2
#define TT 1024
#define DD 2048
#define HH 16
#define DHD 128          // head dim
#define DHALF 1024       // d/2 (router hidden)

// GEMM tile config
#define BM 128
#define BN 128
#define BK 16

#define NEG_BIG (-3.4028234663852886e38f)

// -------- scratch (device globals; no allocation allowed) --------
__device__ float g_q[(size_t)BB*TT*DD];            // 16 MB
__device__ float g_l2[(size_t)BB*TT*DD];           // 16 MB
__device__ float g_hdn[(size_t)BB*TT*DHALF];       // 8 MB
__device__ float g_fused[(size_t)BB*TT*DD];        // 16 MB
__device__ float g_scores[(size_t)BB*HH*TT*TT];    // 128 MB
__device__ float g_ao[(size_t)BB*HH*TT*DHD];       // 16 MB

// ---------------------------------------------------------------
// EMA over time: s_t = beta*s_{t-1} + (1-beta)*x_t, per (b, channel)
// ---------------------------------------------------------------
__global__ void ema_kernel(const float* __restrict__ x, float* __restrict__ l2) {
    int idx = blockIdx.x * blockDim.x + threadIdx.x;   // 0 .. BB*DD-1
    if (idx >= BB * DD) return;
    int b = idx / DD, c = idx % DD;
    const float beta = 0.9f;
    const float omb  = 1.0f - beta;
    const float* xp = x + (size_t)b * TT * DD + c;
    float* op = l2 + (size_t)b * TT * DD + c;
    float s = 0.0f;
    #pragma unroll 4
    for (int t = 0; t < TT; ++t) {
        s = beta * s + omb * xp[(size_t)t * DD];
        op[(size_t)t * DD] = s;
    }
}

// ---------------------------------------------------------------
// Router head: lam = softmax(hdn @ rw2^T + rb2) ; one warp per row
// ---------------------------------------------------------------
__global__ void router_kernel(const float* __restrict__ hdn,
                              const float* __restrict__ rw2,
                              const float* __restrict__ rb2,
                              float* __restrict__ lam) {
    int row  = blockIdx.x * (blockDim.x / 32) + (threadIdx.x / 32);
    int lane = threadIdx.x & 31;
    if (row >= BB * TT) return;
    const float* hp = hdn + (size_t)row * DHALF;
    float a0 = 0.f, a1 = 0.f, a2 = 0.f;
    for (int i = lane; i < DHALF; i += 32) {
        float h = hp[i];
        a0 += h * rw2[0 * DHALF + i];
        a1 += h * rw2[1 * DHALF + i];
        a2 += h * rw2[2 * DHALF + i];
    }
    #pragma unroll
    for (int o = 16; o > 0; o >>= 1) {
        a0 += __shfl_xor_sync(0xffffffffu, a0, o);
        a1 += __shfl_xor_sync(0xffffffffu, a1, o);
        a2 += __shfl_xor_sync(0xffffffffu, a2, o);
    }
    if (lane == 0) {
        float z0 = a0 + rb2[0], z1 = a1 + rb2[1], z2 = a2 + rb2[2];
        float m = fmaxf(z0, fmaxf(z1, z2));
        float e0 = expf(z0 - m), e1 = expf(z1 - m), e2 = expf(z2 - m);
        float inv = 1.0f / (e0 + e1 + e2);
        lam[(size_t)row * 3 + 0] = e0 * inv;
        lam[(size_t)row * 3 + 1] = e1 * inv;
        lam[(size_t)row * 3 + 2] = e2 * inv;
    }
}

// ---------------------------------------------------------------
// fused = lam0*x + lam1*l2 + lam2*l3mem
// ---------------------------------------------------------------
__global__ void fuse_kernel(const float* __restrict__ x,
                            const float* __restrict__ l2,
                            const float* __restrict__ l3,
                            const float* __restrict__ lam,
                            float* __restrict__ fused) {
    size_t i = (size_t)blockIdx.x * blockDim.x + threadIdx.x;
    if (i >= (size_t)BB * TT * DD) return;
    int c = (int)(i % DD);
    size_t row = i / DD;      // b*T + t
    int b = (int)(row / TT);
    float a0 = lam[row * 3 + 0];
    float a1 = lam[row * 3 + 1];
    float a2 = lam[row * 3 + 2];
    fused[i] = a0 * x[i] + a1 * l2[i] + a2 * l3[(size_t)b * DD + c];
}

// ---------------------------------------------------------------
// Generic tiled SGEMM:  C[M,N] = A[M,K] @ B[N,K]^T
//   EPI 0: plain store (ldc = N)
//   EPI 1: silu(acc + bias[n])
//   EPI 2: head-transpose store into [b,h,t,dh]
//   GATHER: A is attention output [b,h,t,dh] gathered as [b*t, d]
// All dims multiples of tile sizes (no bounds checks needed).
// ---------------------------------------------------------------
template <int EPI, bool GATHER>
__global__ void __launch_bounds__(256) sgemm_bt(const float* __restrict__ A,
                                                const float* __restrict__ Bm,
                                                const float* __restrict__ bias,
                                                float* __restrict__ C,
                                                int M, int N, int K,
                                                int lda, int ldb) {
    __shared__ float As[BK][BM + 4];
    __shared__ float Bs[BK][BN + 4];
    int tid = threadIdx.x;
    int tx = tid & 15, ty = tid >> 4;
    int row0 = blockIdx.y * BM, col0 = blockIdx.x * BN;

    float acc[8][8];
    #pragma unroll
    for (int i = 0; i < 8; ++i)
        #pragma unroll
        for (int j = 0; j < 8; ++j) acc[i][j] = 0.f;

    for (int k0 = 0; k0 < K; k0 += BK) {
        #pragma unroll
        for (int it = 0; it < 2; ++it) {
            int e = tid + it * 256;
            int m = e >> 2;
            int k4 = (e & 3) * 4;
            float4 v;
            if (!GATHER) {
                v = *reinterpret_cast<const float4*>(A + (size_t)(row0 + m) * lda + k0 + k4);
            } else {
                int gm = row0 + m;
                int gk = k0 + k4;
                int b = gm / TT, t = gm % TT;
                int h = gk / DHD, c = gk % DHD;
                v = *reinterpret_cast<const float4*>(
                        A + ((((size_t)b * HH + h) * TT + t) * DHD + c));
            }
            As[k4 + 0][m] = v.x; As[k4 + 1][m] = v.y;
            As[k4 + 2][m] = v.z; As[k4 + 3][m] = v.w;
        }
        #pragma unroll
        for (int it = 0; it < 2; ++it) {
            int e = tid + it * 256;
            int n = e >> 2;
            int k4 = (e & 3) * 4;
            float4 v = *reinterpret_cast<const float4*>(Bm + (size_t)(col0 + n) * ldb + k0 + k4);
            Bs[k4 + 0][n] = v.x; Bs[k4 + 1][n] = v.y;
            Bs[k4 + 2][n] = v.z; Bs[k4 + 3][n] = v.w;
        }
        __syncthreads();
        #pragma unroll
        for (int kk = 0; kk < BK; ++kk) {
            float4 a0 = *reinterpret_cast<const float4*>(&As[kk][ty * 8]);
            float4 a1 = *reinterpret_cast<const float4*>(&As[kk][ty * 8 + 4]);
            float4 b0 = *reinterpret_cast<const float4*>(&Bs[kk][tx * 8]);
            float4 b1 = *reinterpret_cast<const float4*>(&Bs[kk][tx * 8 + 4]);
            float ar[8] = {a0.x, a0.y, a0.z, a0.w, a1.x, a1.y, a1.z, a1.w};
            float br[8] = {b0.x, b0.y, b0.z, b0.w, b1.x, b1.y, b1.z, b1.w};
            #pragma unroll
            for (int i = 0; i < 8; ++i)
                #pragma unroll
                for (int j = 0; j < 8; ++j)
                    acc[i][j] += ar[i] * br[j];
        }
        __syncthreads();
    }

    #pragma unroll
    for (int i = 0; i < 8; ++i) {
        int m = row0 + ty * 8 + i;
        #pragma unroll
        for (int j = 0; j < 8; ++j) {
            int n = col0 + tx * 8 + j;
            float v = acc[i][j];
            if (EPI == 0) {
                C[(size_t)m * N + n] = v;
            } else if (EPI == 1) {
                v += bias[n];
                C[(size_t)m * N + n] = v / (1.0f + expf(-v));   // silu
            } else {  // EPI == 2: head-transpose store
                int b = m / TT, t = m % TT;
                int h = n / DHD, c = n % DHD;
                C[(((size_t)b * HH + h) * TT + t) * DHD + c] = v;
            }
        }
    }
}

// ---------------------------------------------------------------
// scores[bh][q][k] = (qh . kh) * scale, causal masked.
// A = q view (lda=DD, per-head column offset), B = kh [t,dh], K=128.
// ---------------------------------------------------------------
__global__ void __launch_bounds__(256) scores_kernel(const float* __restrict__ q,
                                                     const float* __restrict__ kh,
                                                     float* __restrict__ s,
                                                     float scale) {
    int z = blockIdx.z;
    int b = z / HH, h = z % HH;
    const float* A  = q  + (size_t)b * TT * DD + (size_t)h * DHD;   // lda = DD
    const float* Bm = kh + (size_t)z * TT * DHD;                    // ldb = DHD
    float* C = s + (size_t)z * TT * TT;

    int tid = threadIdx.x;
    int tx = tid & 15, ty = tid >> 4;
    int row0 = blockIdx.y * BM, col0 = blockIdx.x * BN;

    // fully-masked block: just fill
    if (col0 > row0 + BM - 1) {
        for (int e = tid; e < BM * BN; e += 256) {
            int m = e >> 7, n = e & 127;
            C[(size_t)(row0 + m) * TT + col0 + n] = NEG_BIG;
        }
        return;
    }

    __shared__ float As[BK][BM + 4];
    __shared__ float Bs[BK][BN + 4];
    float acc[8][8];
    #pragma unroll
    for (int i = 0; i < 8; ++i)
        #pragma unroll
        for (int j = 0; j < 8; ++j) acc[i][j] = 0.f;

    for (int k0 = 0; k0 < DHD; k0 += BK) {
        #pragma unroll
        for (int it = 0; it < 2; ++it) {
            int e = tid + it * 256;
            int m = e >> 2;
            int k4 = (e & 3) * 4;
            float4 v = *reinterpret_cast<const float4*>(A + (size_t)(row0 + m) * DD + k0 + k4);
            As[k4 + 0][m] = v.x; As[k4 + 1][m] = v.y;
            As[k4 + 2][m] = v.z; As[k4 + 3][m] = v.w;
        }
        #pragma unroll
        for (int it = 0; it < 2; ++it) {
            int e = tid + it * 256;
            int n = e >> 2;
            int k4 = (e & 3) * 4;
            float4 v = *reinterpret_cast<const float4*>(Bm + (size_t)(col0 + n) * DHD + k0 + k4);
            Bs[k4 + 0][n] = v.x; Bs[k4 + 1][n] = v.y;
            Bs[k4 + 2][n] = v.z; Bs[k4 + 3][n] = v.w;
        }
        __syncthreads();
        #pragma unroll
        for (int kk = 0; kk < BK; ++kk) {
            float4 a0 = *reinterpret_cast<const float4*>(&As[kk][ty * 8]);
            float4 a1 = *reinterpret_cast<const float4*>(&As[kk][ty * 8 + 4]);
            float4 b0 = *reinterpret_cast<const float4*>(&Bs[kk][tx * 8]);
            float4 b1 = *reinterpret_cast<const float4*>(&Bs[kk][tx * 8 + 4]);
            float ar[8] = {a0.x, a0.y, a0.z, a0.w, a1.x, a1.y, a1.z, a1.w};
            float br[8] = {b0.x, b0.y, b0.z, b0.w, b1.x, b1.y, b1.z, b1.w};
            #pragma unroll
            for (int i = 0; i < 8; ++i)
                #pragma unroll
                for (int j = 0; j < 8; ++j)
                    acc[i][j] += ar[i] * br[j];
        }
        __syncthreads();
    }

    #pragma unroll
    for (int i = 0; i < 8; ++i) {
        int m = row0 + ty * 8 + i;
        #pragma unroll
        for (int j = 0; j < 8; ++j) {
            int n = col0 + tx * 8 + j;
            float v = acc[i][j] * scale;
            if (n > m) v = NEG_BIG;
            C[(size_t)m * TT + n] = v;
        }
    }
}

// ---------------------------------------------------------------
// Row softmax over 1024 entries (masked entries are -3.4e38 -> exp 0)
// One block (256 threads) per row.
// ---------------------------------------------------------------
__global__ void softmax_kernel(float* __restrict__ s) {
    size_t row = blockIdx.x;
    float* p = s + row * TT;
    __shared__ float red[256];
    int tid = threadIdx.x;

    float v[4];
    float m = NEG_BIG;
    #pragma unroll
    for (int j = 0; j < 4; ++j) {
        v[j] = p[tid + j * 256];
        m = fmaxf(m, v[j]);
    }
    red[tid] = m; __syncthreads();
    for (int o = 128; o > 0; o >>= 1) {
        if (tid < o) red[tid] = fmaxf(red[tid], red[tid + o]);
        __syncthreads();
    }
    m = red[0];
    __syncthreads();

    float sum = 0.f;
    #pragma unroll
    for (int j = 0; j < 4; ++j) {
        v[j] = expf(v[j] - m);
        sum += v[j];
    }
    red[tid] = sum; __syncthreads();
    for (int o = 128; o > 0; o >>= 1) {
        if (tid < o) red[tid] += red[tid + o];
        __syncthreads();
    }
    float inv = 1.0f / red[0];
    #pragma unroll
    for (int j = 0; j < 4; ++j) p[tid + j * 256] = v[j] * inv;
}

// ---------------------------------------------------------------
// ao[bh] = attn[bh] @ vh[bh];  A [1024,1024], B [K=1024, N=128] (row-major)
// Causal: A[m,k]=0 for k>m -> truncate K loop at row0+BM.
// ---------------------------------------------------------------
__global__ void __launch_bounds__(256) attnout_kernel(const float* __restrict__ s,
                                                      const float* __restrict__ vh,
                                                      float* __restrict__ ao) {
    int z = blockIdx.z;
    const float* A  = s  + (size_t)z * TT * TT;   // lda = TT
    const float* Bm = vh + (size_t)z * TT * DHD;  // [K, N] with ldb = DHD
    float* C = ao + (size_t)z * TT * DHD;

    int tid = threadIdx.x;
    int tx = tid & 15, ty = tid >> 4;
    int row0 = blockIdx.y * BM, col0 = blockIdx.x * BN;   // col0 == 0 (N=128)

    __shared__ float As[BK][BM + 4];
    __shared__ float Bs[BK][BN + 4];
    float acc[8][8];
    #pragma unroll
    for (int i = 0; i < 8; ++i)
        #pragma unroll
        for (int j = 0; j < 8; ++j) acc[i][j] = 0.f;

    int kend = row0 + BM;   // beyond this, attn weights are exactly 0
    if (kend > TT) kend = TT;

    for (int k0 = 0; k0 < kend; k0 += BK) {
        #pragma unroll
        for (int it = 0; it < 2; ++it) {
            int e = tid + it * 256;
            int m = e >> 2;
            int k4 = (e & 3) * 4;
            float4 v = *reinterpret_cast<const float4*>(A + (size_t)(row0 + m) * TT + k0 + k4);
            As[k4 + 0][m] = v.x; As[k4 + 1][m] = v.y;
            As[k4 + 2][m] = v.z; As[k4 + 3][m] = v.w;
        }
        #pragma unroll
        for (int it = 0; it < 2; ++it) {
            int e = tid + it * 256;
            int k = e >> 5;            // 0..15
            int n4 = (e & 31) * 4;     // 0..124
            float4 v = *reinterpret_cast<const float4*>(Bm + (size_t)(k0 + k) * DHD + col0 + n4);
            *reinterpret_cast<float4*>(&Bs[k][n4]) = v;
        }
        __syncthreads();
        #pragma unroll
        for (int kk = 0; kk < BK; ++kk) {
            float4 a0 = *reinterpret_cast<const float4*>(&As[kk][ty * 8]);
            float4 a1 = *reinterpret_cast<const float4*>(&As[kk][ty * 8 + 4]);
            float4 b0 = *reinterpret_cast<const float4*>(&Bs[kk][tx * 8]);
            float4 b1 = *reinterpret_cast<const float4*>(&Bs[kk][tx * 8 + 4]);
            float ar[8] = {a0.x, a0.y, a0.z, a0.w, a1.x, a1.y, a1.z, a1.w};
            float br[8] = {b0.x, b0.y, b0.z, b0.w, b1.x, b1.y, b1.z, b1.w};
            #pragma unroll
            for (int i = 0; i < 8; ++i)
                #pragma unroll
                for (int j = 0; j < 8; ++j)
                    acc[i][j] += ar[i] * br[j];
        }
        __syncthreads();
    }

    #pragma unroll
    for (int i = 0; i < 8; ++i) {
        int m = row0 + ty * 8 + i;
        #pragma unroll
        for (int j = 0; j < 8; ++j) {
            int n = col0 + tx * 8 + j;
            C[(size_t)m * DHD + n] = acc[i][j];
        }
    }
}

// ---------------------------------------------------------------
extern "C" void kernel_launch(void* const* d_in, const int* in_sizes, int n_in,
                              void* d_out, int out_size) {
    const float* x   = (const float*)d_in[0];
    const float* l3  = (const float*)d_in[1];
    const float* wq  = (const float*)d_in[2];
    const float* wk  = (const float*)d_in[3];
    const float* wv  = (const float*)d_in[4];
    const float* wo  = (const float*)d_in[5];
    const float* rw1 = (const float*)d_in[6];
    const float* rb1 = (const float*)d_in[7];
    const float* rw2 = (const float*)d_in[8];
    const float* rb2 = (const float*)d_in[9];

    float* out     = (float*)d_out;                       // [b,t,d]
    float* kh_out  = out    + (size_t)BB * TT * DD;       // [b,h,t,dh]
    float* vh_out  = kh_out + (size_t)BB * TT * DD;       // [b,h,t,dh]
    float* lam_out = vh_out + (size_t)BB * TT * DD;       // [b,t,3]

    float *q, *l2, *hdn, *fused, *scores, *ao;
    cudaGetSymbolAddress((void**)&q,      g_q);
    cudaGetSymbolAddress((void**)&l2,     g_l2);
    cudaGetSymbolAddress((void**)&hdn,    g_hdn);
    cudaGetSymbolAddress((void**)&fused,  g_fused);
    cudaGetSymbolAddress((void**)&scores, g_scores);
    cudaGetSymbolAddress((void**)&ao,     g_ao);

    const int M = BB * TT;           // 2048
    const float scale = 1.0f / sqrtf((float)DHD);

    // 1. EMA level
    ema_kernel<<<(BB * DD + 255) / 256, 256>>>(x, l2);

    // 2. q = x @ wq^T
    sgemm_bt<0, false><<<dim3(DD / BN, M / BM), 256>>>(x, wq, nullptr, q, M, DD, DD, DD, DD);

    // 3. hdn = silu(q @ rw1^T + rb1)
    sgemm_bt<1, false><<<dim3(DHALF / BN, M / BM), 256>>>(q, rw1, rb1, hdn, M, DHALF, DD, DD, DD);

    // 4. lam = softmax(hdn @ rw2^T + rb2)
    router_kernel<<<(M + 7) / 8, 256>>>(hdn, rw2, rb2, lam_out);

    // 5. fused levels
    {
        size_t n = (size_t)BB * TT * DD;
        fuse_kernel<<<(unsigned)((n + 255) / 256), 256>>>(x, l2, l3, lam_out, fused);
    }

    // 6/7. kh, vh = heads(fused @ wk^T / wv^T)  (written directly into d_out)
    sgemm_bt<2, false><<<dim3(DD / BN, M / BM), 256>>>(fused, wk, nullptr, kh_out, M, DD, DD, DD, DD);
    sgemm_bt<2, false><<<dim3(DD / BN, M / BM), 256>>>(fused, wv, nullptr, vh_out, M, DD, DD, DD, DD);

    // 8. scores (batched over b*h, causal masked, scaled)
    scores_kernel<<<dim3(TT / BN, TT / BM, BB * HH), 256>>>(q, kh_out, scores, scale);

    // 9. row softmax
    softmax_kernel<<<BB * HH * TT, 256>>>(scores);

    // 10. ao = attn @ vh
    attnout_kernel<<<dim3(DHD / BN, TT / BM, BB * HH), 256>>>(scores, vh_out, ao);

    // 11. out = concat_heads(ao) @ wo^T
    sgemm_bt<0, true><<<dim3(DD / BN, M / BM), 256>>>(ao, wo, nullptr, out, M, DD, DD, DD, DD);
}

// round 3
// speedup vs baseline: 1.2443x; 1.2443x over previous
#include <cuda_runtime.h>
#include <cuda_bf16.h>
#include <math.h>
#include <stdint.h>

#define BB 2
#define TT 1024
#define DD 2048
#define HH 16
#define DHD 128
#define DHALF 1024
#define NEG_BIG (-3.4028234663852886e38f)

#define BM 128
#define BN 128
#define BKS 32

// GEMM modes
#define M_Q 0
#define M_HDN 1
#define M_KV 2
#define M_OUT 3
#define M_SCORES 4
#define M_ATTNOUT 5

// ---------------- device scratch (no runtime allocation allowed) ----------------
__device__ float g_l2[(size_t)BB*TT*DD];
__device__ float g_hdn[(size_t)BB*TT*DHALF];
__device__ float g_scores[(size_t)BB*HH*TT*TT];   // 128 MB logits

#define DECL_SPLIT(name, count) \
    __device__ __nv_bfloat16 name##_h[count]; \
    __device__ __nv_bfloat16 name##_l[count];

DECL_SPLIT(g_xs,   (size_t)BB*TT*DD)
DECL_SPLIT(g_wqs,  (size_t)DD*DD)
DECL_SPLIT(g_wks,  (size_t)DD*DD)
DECL_SPLIT(g_wvs,  (size_t)DD*DD)
DECL_SPLIT(g_wos,  (size_t)DD*DD)
DECL_SPLIT(g_rw1s, (size_t)DHALF*DD)
DECL_SPLIT(g_qs,   (size_t)BB*TT*DD)
DECL_SPLIT(g_fs,   (size_t)BB*TT*DD)
DECL_SPLIT(g_khs,  (size_t)BB*TT*DD)
DECL_SPLIT(g_vhs,  (size_t)BB*TT*DD)
DECL_SPLIT(g_attns,(size_t)BB*HH*TT*TT)
DECL_SPLIT(g_aos,  (size_t)BB*TT*DD)

// ---------------- helpers ----------------
__device__ __forceinline__ void split2(float v, __nv_bfloat16* hi, __nv_bfloat16* lo) {
    __nv_bfloat16 h = __float2bfloat16(v);
    *hi = h;
    *lo = __float2bfloat16(v - __bfloat162float(h));
}

__device__ __forceinline__ uint32_t s2u(const void* p) {
    return (uint32_t)__cvta_generic_to_shared(p);
}

__device__ __forceinline__ void ldsm4(uint32_t* r, uint32_t addr) {
    asm volatile("ldmatrix.sync.aligned.m8n8.x4.shared.b16 {%0,%1,%2,%3}, [%4];"
                 : "=r"(r[0]), "=r"(r[1]), "=r"(r[2]), "=r"(r[3]) : "r"(addr));
}
__device__ __forceinline__ void ldsm2(uint32_t* r, uint32_t addr) {
    asm volatile("ldmatrix.sync.aligned.m8n8.x2.shared.b16 {%0,%1}, [%2];"
                 : "=r"(r[0]), "=r"(r[1]) : "r"(addr));
}
__device__ __forceinline__ void ldsm2t(uint32_t* r, uint32_t addr) {
    asm volatile("ldmatrix.sync.aligned.m8n8.x2.trans.shared.b16 {%0,%1}, [%2];"
                 : "=r"(r[0]), "=r"(r[1]) : "r"(addr));
}
__device__ __forceinline__ void mma16816(float* c, const uint32_t* a, const uint32_t* b) {
    asm volatile("mma.sync.aligned.m16n8k16.row.col.f32.bf16.bf16.f32 "
                 "{%0,%1,%2,%3}, {%4,%5,%6,%7}, {%8,%9}, {%0,%1,%2,%3};"
                 : "+f"(c[0]), "+f"(c[1]), "+f"(c[2]), "+f"(c[3])
                 : "r"(a[0]), "r"(a[1]), "r"(a[2]), "r"(a[3]), "r"(b[0]), "r"(b[1]));
}

// ---------------- elementwise kernels ----------------
__global__ void split_kernel(const float* __restrict__ s,
                             __nv_bfloat16* __restrict__ hi,
                             __nv_bfloat16* __restrict__ lo, size_t n) {
    size_t i = (size_t)blockIdx.x * blockDim.x + threadIdx.x;
    if (i < n) split2(s[i], &hi[i], &lo[i]);
}

__global__ void ema_kernel(const float* __restrict__ x, float* __restrict__ l2) {
    int idx = blockIdx.x * blockDim.x + threadIdx.x;
    if (idx >= BB * DD) return;
    int b = idx / DD, c = idx % DD;
    const float beta = 0.9f, omb = 1.0f - beta;
    const float* xp = x + (size_t)b * TT * DD + c;
    float* op = l2 + (size_t)b * TT * DD + c;
    float s = 0.0f;
    #pragma unroll 4
    for (int t = 0; t < TT; ++t) {
        s = beta * s + omb * xp[(size_t)t * DD];
        op[(size_t)t * DD] = s;
    }
}

__global__ void router_kernel(const float* __restrict__ hdn,
                              const float* __restrict__ rw2,
                              const float* __restrict__ rb2,
                              float* __restrict__ lam) {
    int row  = blockIdx.x * (blockDim.x / 32) + (threadIdx.x / 32);
    int lane = threadIdx.x & 31;
    if (row >= BB * TT) return;
    const float* hp = hdn + (size_t)row * DHALF;
    float a0 = 0.f, a1 = 0.f, a2 = 0.f;
    for (int i = lane; i < DHALF; i += 32) {
        float h = hp[i];
        a0 += h * rw2[0 * DHALF + i];
        a1 += h * rw2[1 * DHALF + i];
        a2 += h * rw2[2 * DHALF + i];
    }
    #pragma unroll
    for (int o = 16; o > 0; o >>= 1) {
        a0 += __shfl_xor_sync(0xffffffffu, a0, o);
        a1 += __shfl_xor_sync(0xffffffffu, a1, o);
        a2 += __shfl_xor_sync(0xffffffffu, a2, o);
    }
    if (lane == 0) {
        float z0 = a0 + rb2[0], z1 = a1 + rb2[1], z2 = a2 + rb2[2];
        float m = fmaxf(z0, fmaxf(z1, z2));
        float e0 = expf(z0 - m), e1 = expf(z1 - m), e2 = expf(z2 - m);
        float inv = 1.0f / (e0 + e1 + e2);
        lam[(size_t)row * 3 + 0] = e0 * inv;
        lam[(size_t)row * 3 + 1] = e1 * inv;
        lam[(size_t)row * 3 + 2] = e2 * inv;
    }
}

__global__ void fuse_split_kernel(const float* __restrict__ x,
                                  const float* __restrict__ l2,
                                  const float* __restrict__ l3,
                                  const float* __restrict__ lam,
                                  __nv_bfloat16* __restrict__ fhi,
                                  __nv_bfloat16* __restrict__ flo) {
    size_t i = (size_t)blockIdx.x * blockDim.x + threadIdx.x;
    if (i >= (size_t)BB * TT * DD) return;
    int c = (int)(i % DD);
    size_t row = i / DD;
    int b = (int)(row / TT);
    float a0 = lam[row * 3 + 0];
    float a1 = lam[row * 3 + 1];
    float a2 = lam[row * 3 + 2];
    float f = a0 * x[i] + a1 * l2[i] + a2 * l3[(size_t)b * DD + c];
    split2(f, &fhi[i], &flo[i]);
}

// softmax over 1024 logits (fp32 in), writes bf16 hi/lo probability split
__global__ void softmax_split_kernel(const float* __restrict__ s,
                                     __nv_bfloat16* __restrict__ ahi,
                                     __nv_bfloat16* __restrict__ alo) {
    size_t row = blockIdx.x;
    const float* p = s + row * TT;
    __shared__ float red[256];
    int tid = threadIdx.x;

    float v[4];
    float m = NEG_BIG;
    #pragma unroll
    for (int j = 0; j < 4; ++j) {
        v[j] = p[tid + j * 256];
        m = fmaxf(m, v[j]);
    }
    red[tid] = m; __syncthreads();
    for (int o = 128; o > 0; o >>= 1) {
        if (tid < o) red[tid] = fmaxf(red[tid], red[tid + o]);
        __syncthreads();
    }
    m = red[0];
    __syncthreads();

    float sum = 0.f;
    #pragma unroll
    for (int j = 0; j < 4; ++j) {
        v[j] = expf(v[j] - m);
        sum += v[j];
    }
    red[tid] = sum; __syncthreads();
    for (int o = 128; o > 0; o >>= 1) {
        if (tid < o) red[tid] += red[tid + o];
        __syncthreads();
    }
    float inv = 1.0f / red[0];
    #pragma unroll
    for (int j = 0; j < 4; ++j) {
        size_t idx = row * TT + tid + j * 256;
        split2(v[j] * inv, &ahi[idx], &alo[idx]);
    }
}

// ---------------- split bf16 tensor-core GEMM ----------------
// C[M,N] = (Ahi+Alo)[M,K] @ Bexpanded, 3-term split: hihi + hilo + lohi.
// Normal modes: B given as [N][K] row-major (i.e. B^T).
// M_ATTNOUT:    B given as [K][N] row-major (vh: n contiguous) -> trans ldmatrix.
template<int MODE>
__global__ void __launch_bounds__(256) mma_gemm(
    const __nv_bfloat16* __restrict__ Ahi, const __nv_bfloat16* __restrict__ Alo,
    const __nv_bfloat16* __restrict__ Bhi, const __nv_bfloat16* __restrict__ Blo,
    const float* __restrict__ bias,
    float* __restrict__ Cf,
    __nv_bfloat16* __restrict__ Chi, __nv_bfloat16* __restrict__ Clo,
    int M, int N, int K, int lda, int ldb, float scale)
{
    __shared__ __align__(16) __nv_bfloat16 sA[2][BM][40];
    // flat B smem: normal layout [n][40] (5120 elems/split); attnout layout [k][136] (4352)
    __shared__ __align__(16) __nv_bfloat16 sB[2][BM * 40];

    int tid = threadIdx.x;
    int lane = tid & 31;
    int warp = tid >> 5;
    int wm = warp >> 2;   // 0..1  (64 rows each)
    int wn = warp & 3;    // 0..3  (32 cols each)
    int row0 = blockIdx.y * BM;
    int col0 = blockIdx.x * BN;

    size_t aoff0 = 0, boff0 = 0, coff0 = 0;
    if (MODE == M_SCORES) {
        int z = blockIdx.z; int b = z / HH, h = z % HH;
        aoff0 = (size_t)b * TT * DD + (size_t)h * DHD;
        boff0 = (size_t)z * TT * DHD;
        coff0 = (size_t)z * TT * TT;
        if (col0 > row0 + (BM - 1)) {   // fully masked tile
            for (int e = tid; e < BM * BN; e += 256) {
                int m = e >> 7, n = e & 127;
                Cf[coff0 + (size_t)(row0 + m) * TT + col0 + n] = NEG_BIG;
            }
            return;
        }
    } else if (MODE == M_ATTNOUT) {
        int z = blockIdx.z;
        aoff0 = (size_t)z * TT * TT;
        boff0 = (size_t)z * TT * DHD;
        coff0 = (size_t)z * TT * DHD;
    }

    int kend = K;
    if (MODE == M_ATTNOUT) { kend = row0 + BM; if (kend > K) kend = K; }

    float acc[4][4][4];
    #pragma unroll
    for (int a = 0; a < 4; ++a)
        #pragma unroll
        for (int b = 0; b < 4; ++b)
            #pragma unroll
            for (int c = 0; c < 4; ++c) acc[a][b][c] = 0.f;

    for (int k0 = 0; k0 < kend; k0 += BKS) {
        // ---- A tile: [BM rows][BKS cols], row-major in k ----
        #pragma unroll
        for (int it = 0; it < 2; ++it) {
            int e = tid + it * 256;          // 0..511
            int r = e >> 2;                  // 0..127
            int kc = (e & 3) * 8;            // 0,8,16,24
            size_t ao;
            if (MODE == M_OUT) {             // gather attn-out [b,h,t,dh] as [b*t, d]
                int gm = row0 + r, gk = k0 + kc;
                int b = gm >> 10, t = gm & (TT - 1);
                int h = gk >> 7, c = gk & (DHD - 1);
                ao = (((size_t)b * HH + h) * TT + t) * DHD + c;
            } else {
                ao = aoff0 + (size_t)(row0 + r) * lda + k0 + kc;
            }
            *reinterpret_cast<uint4*>(&sA[0][r][kc]) = *reinterpret_cast<const uint4*>(Ahi + ao);
            *reinterpret_cast<uint4*>(&sA[1][r][kc]) = *reinterpret_cast<const uint4*>(Alo + ao);
        }
        // ---- B tile ----
        if (MODE == M_ATTNOUT) {
            // vh tile is [k][n], n contiguous: copy coalesced into [k][136]
            #pragma unroll
            for (int it = 0; it < 2; ++it) {
                int e = tid + it * 256;      // 0..511
                int k = e >> 4;              // 0..31
                int n8 = (e & 15) * 8;       // 0..120
                size_t bo = boff0 + (size_t)(k0 + k) * ldb + col0 + n8;
                *reinterpret_cast<uint4*>(&sB[0][k * 136 + n8]) =
                    *reinterpret_cast<const uint4*>(Bhi + bo);
                *reinterpret_cast<uint4*>(&sB[1][k * 136 + n8]) =
                    *reinterpret_cast<const uint4*>(Blo + bo);
            }
        } else {
            #pragma unroll
            for (int it = 0; it < 2; ++it) {
                int e = tid + it * 256;
                int r = e >> 2;
                int kc = (e & 3) * 8;
                size_t bo = boff0 + (size_t)(col0 + r) * ldb + k0 + kc;
                *reinterpret_cast<uint4*>(&sB[0][r * 40 + kc]) =
                    *reinterpret_cast<const uint4*>(Bhi + bo);
                *reinterpret_cast<uint4*>(&sB[1][r * 40 + kc]) =
                    *reinterpret_cast<const uint4*>(Blo + bo);
            }
        }
        __syncthreads();

        #pragma unroll
        for (int ks = 0; ks < BKS; ks += 16) {
            uint32_t afr[2][4][4];
            uint32_t bfr[2][4][2];
            #pragma unroll
            for (int mt = 0; mt < 4; ++mt) {
                int r = wm * 64 + mt * 16 + (lane & 15);
                int c = ks + (lane >> 4) * 8;
                ldsm4(afr[0][mt], s2u(&sA[0][r][c]));
                ldsm4(afr[1][mt], s2u(&sA[1][r][c]));
            }
            #pragma unroll
            for (int nt = 0; nt < 4; ++nt) {
                if (MODE == M_ATTNOUT) {
                    // trans-load from [k][n] tile: rows ks+(lane&15), col = n0
                    int rr = ks + (lane & 15);
                    int cc = wn * 32 + nt * 8;
                    ldsm2t(bfr[0][nt], s2u(&sB[0][rr * 136 + cc]));
                    ldsm2t(bfr[1][nt], s2u(&sB[1][rr * 136 + cc]));
                } else {
                    int r = wn * 32 + nt * 8 + (lane & 7);
                    int c = ks + ((lane >> 3) & 1) * 8;
                    ldsm2(bfr[0][nt], s2u(&sB[0][r * 40 + c]));
                    ldsm2(bfr[1][nt], s2u(&sB[1][r * 40 + c]));
                }
            }
            #pragma unroll
            for (int mt = 0; mt < 4; ++mt)
                #pragma unroll
                for (int nt = 0; nt < 4; ++nt) {
                    mma16816(acc[mt][nt], afr[0][mt], bfr[0][nt]);  // hi*hi
                    mma16816(acc[mt][nt], afr[0][mt], bfr[1][nt]);  // hi*lo
                    mma16816(acc[mt][nt], afr[1][mt], bfr[0][nt]);  // lo*hi
                }
        }
        __syncthreads();
    }

    // epilogue
    int g = lane >> 2, tg = lane & 3;
    #pragma unroll
    for (int mt = 0; mt < 4; ++mt)
        #pragma unroll
        for (int nt = 0; nt < 4; ++nt)
            #pragma unroll
            for (int i = 0; i < 4; ++i) {
                int m = row0 + wm * 64 + mt * 16 + g + (i >> 1) * 8;
                int n = col0 + wn * 32 + nt * 8 + tg * 2 + (i & 1);
                float v = acc[mt][nt][i];
                if (MODE == M_Q) {
                    size_t idx = (size_t)m * N + n;
                    split2(v, &Chi[idx], &Clo[idx]);
                } else if (MODE == M_HDN) {
                    v += bias[n];
                    Cf[(size_t)m * N + n] = v / (1.f + expf(-v));
                } else if (MODE == M_KV) {
                    int b = m >> 10, t = m & (TT - 1);
                    int h = n >> 7, c = n & (DHD - 1);
                    size_t idx = (((size_t)b * HH + h) * TT + t) * DHD + c;
                    Cf[idx] = v;                       // fp32 output (kh/vh in d_out)
                    split2(v, &Chi[idx], &Clo[idx]);   // split operand for attention
                } else if (MODE == M_OUT) {
                    Cf[(size_t)m * N + n] = v;
                } else if (MODE == M_SCORES) {
                    v *= scale;
                    if (n > m) v = NEG_BIG;
                    Cf[coff0 + (size_t)m * TT + n] = v;
                } else {  // M_ATTNOUT
                    size_t idx = coff0 + (size_t)m * DHD + n;
                    split2(v, &Chi[idx], &Clo[idx]);
                }
            }
}

// ---------------- host ----------------
#define SYMADDR(var, sym) cudaGetSymbolAddress((void**)&var, sym)

extern "C" void kernel_launch(void* const* d_in, const int* in_sizes, int n_in,
                              void* d_out, int out_size) {
    const float* x   = (const float*)d_in[0];
    const float* l3  = (const float*)d_in[1];
    const float* wq  = (const float*)d_in[2];
    const float* wk  = (const float*)d_in[3];
    const float* wv  = (const float*)d_in[4];
    const float* wo  = (const float*)d_in[5];
    const float* rw1 = (const float*)d_in[6];
    const float* rb1 = (const float*)d_in[7];
    const float* rw2 = (const float*)d_in[8];
    const float* rb2 = (const float*)d_in[9];

    float* out     = (float*)d_out;                   // [b,t,d]
    float* kh_out  = out    + (size_t)BB * TT * DD;   // [b,h,t,dh]
    float* vh_out  = kh_out + (size_t)BB * TT * DD;   // [b,h,t,dh]
    float* lam_out = vh_out + (size_t)BB * TT * DD;   // [b,t,3]

    float *l2, *hdn, *scores;
    SYMADDR(l2, g_l2); SYMADDR(hdn, g_hdn); SYMADDR(scores, g_scores);

    __nv_bfloat16 *xs_h,*xs_l, *wqs_h,*wqs_l, *wks_h,*wks_l, *wvs_h,*wvs_l,
                  *wos_h,*wos_l, *rw1s_h,*rw1s_l, *qs_h,*qs_l, *fs_h,*fs_l,
                  *khs_h,*khs_l, *vhs_h,*vhs_l, *attns_h,*attns_l, *aos_h,*aos_l;
    SYMADDR(xs_h, g_xs_h);     SYMADDR(xs_l, g_xs_l);
    SYMADDR(wqs_h, g_wqs_h);   SYMADDR(wqs_l, g_wqs_l);
    SYMADDR(wks_h, g_wks_h);   SYMADDR(wks_l, g_wks_l);
    SYMADDR(wvs_h, g_wvs_h);   SYMADDR(wvs_l, g_wvs_l);
    SYMADDR(wos_h, g_wos_h);   SYMADDR(wos_l, g_wos_l);
    SYMADDR(rw1s_h, g_rw1s_h); SYMADDR(rw1s_l, g_rw1s_l);
    SYMADDR(qs_h, g_qs_h);     SYMADDR(qs_l, g_qs_l);
    SYMADDR(fs_h, g_fs_h);     SYMADDR(fs_l, g_fs_l);
    SYMADDR(khs_h, g_khs_h);   SYMADDR(khs_l, g_khs_l);
    SYMADDR(vhs_h, g_vhs_h);   SYMADDR(vhs_l, g_vhs_l);
    SYMADDR(attns_h, g_attns_h); SYMADDR(attns_l, g_attns_l);
    SYMADDR(aos_h, g_aos_h);   SYMADDR(aos_l, g_aos_l);

    const int M = BB * TT;                       // 2048
    const float scale = 1.0f / sqrtf((float)DHD);
    const size_t ND = (size_t)BB * TT * DD;      // 4M
    const size_t NW = (size_t)DD * DD;           // 4M

    // split inputs to bf16 hi/lo
    split_kernel<<<(unsigned)((ND + 255) / 256), 256>>>(x,   xs_h,   xs_l,   ND);
    split_kernel<<<(unsigned)((NW + 255) / 256), 256>>>(wq,  wqs_h,  wqs_l,  NW);
    split_kernel<<<(unsigned)((NW + 255) / 256), 256>>>(wk,  wks_h,  wks_l,  NW);
    split_kernel<<<(unsigned)((NW + 255) / 256), 256>>>(wv,  wvs_h,  wvs_l,  NW);
    split_kernel<<<(unsigned)((NW + 255) / 256), 256>>>(wo,  wos_h,  wos_l,  NW);
    split_kernel<<<(unsigned)((NW / 2 + 255) / 256), 256>>>(rw1, rw1s_h, rw1s_l, NW / 2);

    // EMA level (fp32)
    ema_kernel<<<(BB * DD + 255) / 256, 256>>>(x, l2);

    // q = x @ wq^T  (split out)
    mma_gemm<M_Q><<<dim3(DD / BN, M / BM), 256>>>(
        xs_h, xs_l, wqs_h, wqs_l, nullptr, nullptr, qs_h, qs_l,
        M, DD, DD, DD, DD, 1.f);

    // hdn = silu(q @ rw1^T + rb1)
    mma_gemm<M_HDN><<<dim3(DHALF / BN, M / BM), 256>>>(
        qs_h, qs_l, rw1s_h, rw1s_l, rb1, hdn, nullptr, nullptr,
        M, DHALF, DD, DD, DD, 1.f);

    // lam = softmax(hdn @ rw2^T + rb2)
    router_kernel<<<(M + 7) / 8, 256>>>(hdn, rw2, rb2, lam_out);

    // fused levels (split out)
    fuse_split_kernel<<<(unsigned)((ND + 255) / 256), 256>>>(x, l2, l3, lam_out, fs_h, fs_l);

    // kh/vh: fp32 transposed into d_out + split operand copies
    mma_gemm<M_KV><<<dim3(DD / BN, M / BM), 256>>>(
        fs_h, fs_l, wks_h, wks_l, nullptr, kh_out, khs_h, khs_l,
        M, DD, DD, DD, DD, 1.f);
    mma_gemm<M_KV><<<dim3(DD / BN, M / BM), 256>>>(
        fs_h, fs_l, wvs_h, wvs_l, nullptr, vh_out, vhs_h, vhs_l,
        M, DD, DD, DD, DD, 1.f);

    // scores = causal-masked scaled qh @ kh^T  (fp32 logits)
    mma_gemm<M_SCORES><<<dim3(TT / BN, TT / BM, BB * HH), 256>>>(
        qs_h, qs_l, khs_h, khs_l, nullptr, scores, nullptr, nullptr,
        TT, TT, DHD, DD, DHD, scale);

    // softmax -> split probabilities
    softmax_split_kernel<<<BB * HH * TT, 256>>>(scores, attns_h, attns_l);

    // ao = attn @ vh  (split out, causal K truncation, trans-B)
    mma_gemm<M_ATTNOUT><<<dim3(DHD / BN, TT / BM, BB * HH), 256>>>(
        attns_h, attns_l, vhs_h, vhs_l, nullptr, nullptr, aos_h, aos_l,
        TT, DHD, TT, TT, DHD, 1.f);

    // out = concat_heads(ao) @ wo^T  (gather A, fp32 out)
    mma_gemm<M_OUT><<<dim3(DD / BN, M / BM), 256>>>(
        aos_h, aos_l, wos_h, wos_l, nullptr, out, nullptr, nullptr,
        M, DD, DD, DD, DD, 1.f);
}

// round 4
// speedup vs baseline: 2.2405x; 1.8006x over previous
#include <cuda_runtime.h>
#include <cuda_bf16.h>
#include <math.h>
#include <stdint.h>

#define BB 2
#define TT 1024
#define DD 2048
#define HH 16
#define DHD 128
#define DHALF 1024

#define BM 128
#define BN 128
#define BKS 32

// GEMM modes
#define M_Q 0
#define M_HDN 1
#define M_KV 2
#define M_OUT 3

// ---------------- device scratch ----------------
__device__ float g_l2[(size_t)BB*TT*DD];
__device__ float g_hdn[(size_t)BB*TT*DHALF];

#define DECL_SPLIT(name, count) \
    __device__ __nv_bfloat16 name##_h[count]; \
    __device__ __nv_bfloat16 name##_l[count];

DECL_SPLIT(g_xs,   (size_t)BB*TT*DD)
DECL_SPLIT(g_wqs,  (size_t)DD*DD)
DECL_SPLIT(g_wks,  (size_t)DD*DD)
DECL_SPLIT(g_wvs,  (size_t)DD*DD)
DECL_SPLIT(g_wos,  (size_t)DD*DD)
DECL_SPLIT(g_rw1s, (size_t)DHALF*DD)
DECL_SPLIT(g_qs,   (size_t)BB*TT*DD)
DECL_SPLIT(g_fs,   (size_t)BB*TT*DD)
DECL_SPLIT(g_khs,  (size_t)BB*TT*DD)
DECL_SPLIT(g_vhs,  (size_t)BB*TT*DD)
DECL_SPLIT(g_aos,  (size_t)BB*TT*DD)

// ---------------- helpers ----------------
__device__ __forceinline__ void split2(float v, __nv_bfloat16* hi, __nv_bfloat16* lo) {
    __nv_bfloat16 h = __float2bfloat16(v);
    *hi = h;
    *lo = __float2bfloat16(v - __bfloat162float(h));
}
__device__ __forceinline__ uint32_t s2u(const void* p) {
    return (uint32_t)__cvta_generic_to_shared(p);
}
__device__ __forceinline__ void ldsm4(uint32_t* r, uint32_t addr) {
    asm volatile("ldmatrix.sync.aligned.m8n8.x4.shared.b16 {%0,%1,%2,%3}, [%4];"
                 : "=r"(r[0]), "=r"(r[1]), "=r"(r[2]), "=r"(r[3]) : "r"(addr));
}
__device__ __forceinline__ void ldsm2(uint32_t* r, uint32_t addr) {
    asm volatile("ldmatrix.sync.aligned.m8n8.x2.shared.b16 {%0,%1}, [%2];"
                 : "=r"(r[0]), "=r"(r[1]) : "r"(addr));
}
__device__ __forceinline__ void ldsm2t(uint32_t* r, uint32_t addr) {
    asm volatile("ldmatrix.sync.aligned.m8n8.x2.trans.shared.b16 {%0,%1}, [%2];"
                 : "=r"(r[0]), "=r"(r[1]) : "r"(addr));
}
__device__ __forceinline__ void mma16816(float* c, const uint32_t* a, const uint32_t* b) {
    asm volatile("mma.sync.aligned.m16n8k16.row.col.f32.bf16.bf16.f32 "
                 "{%0,%1,%2,%3}, {%4,%5,%6,%7}, {%8,%9}, {%0,%1,%2,%3};"
                 : "+f"(c[0]), "+f"(c[1]), "+f"(c[2]), "+f"(c[3])
                 : "r"(a[0]), "r"(a[1]), "r"(a[2]), "r"(a[3]), "r"(b[0]), "r"(b[1]));
}
__device__ __forceinline__ void cp16(uint32_t saddr, const void* g) {
    asm volatile("cp.async.cg.shared.global [%0], [%1], 16;" :: "r"(saddr), "l"(g));
}
__device__ __forceinline__ void cp_commit() {
    asm volatile("cp.async.commit_group;");
}
template<int N> __device__ __forceinline__ void cp_wait() {
    asm volatile("cp.async.wait_group %0;" :: "n"(N));
}
__device__ __forceinline__ uint32_t packb2(float lo_k, float hi_k) {
    __nv_bfloat162 t = __floats2bfloat162_rn(lo_k, hi_k);   // .x = low half
    return *reinterpret_cast<uint32_t*>(&t);
}

// ---------------- elementwise kernels ----------------
__global__ void split_kernel(const float* __restrict__ s,
                             __nv_bfloat16* __restrict__ hi,
                             __nv_bfloat16* __restrict__ lo, size_t n) {
    size_t i = (size_t)blockIdx.x * blockDim.x + threadIdx.x;
    if (i < n) split2(s[i], &hi[i], &lo[i]);
}

// split 4 equal-size weight matrices in one launch
__global__ void split4_kernel(const float* __restrict__ a, const float* __restrict__ b,
                              const float* __restrict__ c, const float* __restrict__ d,
                              __nv_bfloat16* __restrict__ ah, __nv_bfloat16* __restrict__ al,
                              __nv_bfloat16* __restrict__ bh, __nv_bfloat16* __restrict__ bl,
                              __nv_bfloat16* __restrict__ ch, __nv_bfloat16* __restrict__ cl,
                              __nv_bfloat16* __restrict__ dh, __nv_bfloat16* __restrict__ dl,
                              size_t n) {
    size_t i = (size_t)blockIdx.x * blockDim.x + threadIdx.x;
    if (i >= n) return;
    split2(a[i], &ah[i], &al[i]);
    split2(b[i], &bh[i], &bl[i]);
    split2(c[i], &ch[i], &cl[i]);
    split2(d[i], &dh[i], &dl[i]);
}

__global__ void ema_kernel(const float* __restrict__ x, float* __restrict__ l2) {
    int idx = blockIdx.x * blockDim.x + threadIdx.x;
    if (idx >= BB * DD) return;
    int b = idx / DD, c = idx % DD;
    const float beta = 0.9f, omb = 1.0f - beta;
    const float* xp = x + (size_t)b * TT * DD + c;
    float* op = l2 + (size_t)b * TT * DD + c;
    float s = 0.0f;
    #pragma unroll 4
    for (int t = 0; t < TT; ++t) {
        s = beta * s + omb * xp[(size_t)t * DD];
        op[(size_t)t * DD] = s;
    }
}

__global__ void router_kernel(const float* __restrict__ hdn,
                              const float* __restrict__ rw2,
                              const float* __restrict__ rb2,
                              float* __restrict__ lam) {
    int row  = blockIdx.x * (blockDim.x / 32) + (threadIdx.x / 32);
    int lane = threadIdx.x & 31;
    if (row >= BB * TT) return;
    const float* hp = hdn + (size_t)row * DHALF;
    float a0 = 0.f, a1 = 0.f, a2 = 0.f;
    for (int i = lane; i < DHALF; i += 32) {
        float h = hp[i];
        a0 += h * rw2[0 * DHALF + i];
        a1 += h * rw2[1 * DHALF + i];
        a2 += h * rw2[2 * DHALF + i];
    }
    #pragma unroll
    for (int o = 16; o > 0; o >>= 1) {
        a0 += __shfl_xor_sync(0xffffffffu, a0, o);
        a1 += __shfl_xor_sync(0xffffffffu, a1, o);
        a2 += __shfl_xor_sync(0xffffffffu, a2, o);
    }
    if (lane == 0) {
        float z0 = a0 + rb2[0], z1 = a1 + rb2[1], z2 = a2 + rb2[2];
        float m = fmaxf(z0, fmaxf(z1, z2));
        float e0 = expf(z0 - m), e1 = expf(z1 - m), e2 = expf(z2 - m);
        float inv = 1.0f / (e0 + e1 + e2);
        lam[(size_t)row * 3 + 0] = e0 * inv;
        lam[(size_t)row * 3 + 1] = e1 * inv;
        lam[(size_t)row * 3 + 2] = e2 * inv;
    }
}

__global__ void fuse_split_kernel(const float* __restrict__ x,
                                  const float* __restrict__ l2,
                                  const float* __restrict__ l3,
                                  const float* __restrict__ lam,
                                  __nv_bfloat16* __restrict__ fhi,
                                  __nv_bfloat16* __restrict__ flo) {
    size_t i = (size_t)blockIdx.x * blockDim.x + threadIdx.x;
    if (i >= (size_t)BB * TT * DD) return;
    int c = (int)(i % DD);
    size_t row = i / DD;
    int b = (int)(row / TT);
    float a0 = lam[row * 3 + 0];
    float a1 = lam[row * 3 + 1];
    float a2 = lam[row * 3 + 2];
    float f = a0 * x[i] + a1 * l2[i] + a2 * l3[(size_t)b * DD + c];
    split2(f, &fhi[i], &flo[i]);
}

// ---------------- pipelined split-bf16 tensor-core GEMM ----------------
// C[M,N] = (Ahi+Alo)[M,K] @ (Bhi+Blo)[N,K]^T  (3-term: hihi + hilo + lohi)
// 2-stage cp.async double buffer. Dynamic smem: 81920 bytes.
#define GEMM_SMEM (2 * 2 * BM * 40 * 2 * 2)   // stages*splits*rows*pitch*2B * (A,B)

template<int MODE>
__global__ void __launch_bounds__(256) mma_gemm(
    const __nv_bfloat16* __restrict__ Ahi, const __nv_bfloat16* __restrict__ Alo,
    const __nv_bfloat16* __restrict__ Bhi, const __nv_bfloat16* __restrict__ Blo,
    const float* __restrict__ bias,
    float* __restrict__ Cf,
    __nv_bfloat16* __restrict__ Chi, __nv_bfloat16* __restrict__ Clo,
    int M, int N, int K, int lda, int ldb)
{
    extern __shared__ __align__(16) char dynsmem[];
    __nv_bfloat16* sA = reinterpret_cast<__nv_bfloat16*>(dynsmem);      // [2st][2sp][128][40]
    __nv_bfloat16* sB = sA + 2 * 2 * BM * 40;

    int tid = threadIdx.x;
    int lane = tid & 31;
    int warp = tid >> 5;
    int wm = warp >> 2;
    int wn = warp & 3;
    int row0 = blockIdx.y * BM;
    int col0 = blockIdx.x * BN;

    float acc[4][4][4];
    #pragma unroll
    for (int a = 0; a < 4; ++a)
        #pragma unroll
        for (int b = 0; b < 4; ++b)
            #pragma unroll
            for (int c = 0; c < 4; ++c) acc[a][b][c] = 0.f;

    auto issue = [&](int k0, int st) {
        #pragma unroll
        for (int it = 0; it < 2; ++it) {
            int e = tid + it * 256;
            int r = e >> 2;
            int kc = (e & 3) * 8;
            size_t ao;
            if (MODE == M_OUT) {
                int gm = row0 + r, gk = k0 + kc;
                int b = gm >> 10, t = gm & (TT - 1);
                int h = gk >> 7, c = gk & (DHD - 1);
                ao = (((size_t)b * HH + h) * TT + t) * DHD + c;
            } else {
                ao = (size_t)(row0 + r) * lda + k0 + kc;
            }
            uint32_t da0 = s2u(&sA[((st * 2 + 0) * BM + r) * 40 + kc]);
            uint32_t da1 = s2u(&sA[((st * 2 + 1) * BM + r) * 40 + kc]);
            cp16(da0, Ahi + ao);
            cp16(da1, Alo + ao);
            size_t bo = (size_t)(col0 + r) * ldb + k0 + kc;
            uint32_t db0 = s2u(&sB[((st * 2 + 0) * BM + r) * 40 + kc]);
            uint32_t db1 = s2u(&sB[((st * 2 + 1) * BM + r) * 40 + kc]);
            cp16(db0, Bhi + bo);
            cp16(db1, Blo + bo);
        }
    };

    int nIter = K / BKS;
    issue(0, 0);
    cp_commit();

    for (int i = 0; i < nIter; ++i) {
        int st = i & 1;
        if (i + 1 < nIter) {
            issue((i + 1) * BKS, (i + 1) & 1);
            cp_commit();
            cp_wait<1>();
        } else {
            cp_wait<0>();
        }
        __syncthreads();

        #pragma unroll
        for (int ks = 0; ks < BKS; ks += 16) {
            uint32_t afr[2][4][4];
            uint32_t bfr[2][4][2];
            #pragma unroll
            for (int mt = 0; mt < 4; ++mt) {
                int r = wm * 64 + mt * 16 + (lane & 15);
                int c = ks + (lane >> 4) * 8;
                ldsm4(afr[0][mt], s2u(&sA[((st * 2 + 0) * BM + r) * 40 + c]));
                ldsm4(afr[1][mt], s2u(&sA[((st * 2 + 1) * BM + r) * 40 + c]));
            }
            #pragma unroll
            for (int nt = 0; nt < 4; ++nt) {
                int r = wn * 32 + nt * 8 + (lane & 7);
                int c = ks + ((lane >> 3) & 1) * 8;
                ldsm2(bfr[0][nt], s2u(&sB[((st * 2 + 0) * BM + r) * 40 + c]));
                ldsm2(bfr[1][nt], s2u(&sB[((st * 2 + 1) * BM + r) * 40 + c]));
            }
            #pragma unroll
            for (int mt = 0; mt < 4; ++mt)
                #pragma unroll
                for (int nt = 0; nt < 4; ++nt) {
                    mma16816(acc[mt][nt], afr[0][mt], bfr[0][nt]);
                    mma16816(acc[mt][nt], afr[0][mt], bfr[1][nt]);
                    mma16816(acc[mt][nt], afr[1][mt], bfr[0][nt]);
                }
        }
        __syncthreads();
    }

    int g = lane >> 2, tg = lane & 3;
    #pragma unroll
    for (int mt = 0; mt < 4; ++mt)
        #pragma unroll
        for (int nt = 0; nt < 4; ++nt)
            #pragma unroll
            for (int i = 0; i < 4; ++i) {
                int m = row0 + wm * 64 + mt * 16 + g + (i >> 1) * 8;
                int n = col0 + wn * 32 + nt * 8 + tg * 2 + (i & 1);
                float v = acc[mt][nt][i];
                if (MODE == M_Q) {
                    size_t idx = (size_t)m * N + n;
                    split2(v, &Chi[idx], &Clo[idx]);
                } else if (MODE == M_HDN) {
                    v += bias[n];
                    Cf[(size_t)m * N + n] = v / (1.f + expf(-v));
                } else if (MODE == M_KV) {
                    int b = m >> 10, t = m & (TT - 1);
                    int h = n >> 7, c = n & (DHD - 1);
                    size_t idx = (((size_t)b * HH + h) * TT + t) * DHD + c;
                    Cf[idx] = v;
                    split2(v, &Chi[idx], &Clo[idx]);
                } else {  // M_OUT
                    Cf[(size_t)m * N + n] = v;
                }
            }
}

// ---------------- flash attention ----------------
// One block per (z = b*H+h, 128-row q block). 8 warps, each owns 16 q rows.
// Online softmax in registers; O accumulated fp32; writes split ao.
#define FL_PITCH 136
#define FL_TILE  (128 * FL_PITCH)             // elems per tile buffer
#define FLASH_SMEM (6 * FL_TILE * 2)          // Qh Ql Kh Kl Vh Vl -> 208896 B

__global__ void __launch_bounds__(256) flash_kernel(
    const __nv_bfloat16* __restrict__ qh_, const __nv_bfloat16* __restrict__ ql_,
    const __nv_bfloat16* __restrict__ khh, const __nv_bfloat16* __restrict__ khl,
    const __nv_bfloat16* __restrict__ vhh, const __nv_bfloat16* __restrict__ vhl,
    __nv_bfloat16* __restrict__ aoh, __nv_bfloat16* __restrict__ aol,
    float scale)
{
    extern __shared__ __align__(16) char fsm[];
    __nv_bfloat16* sQh = reinterpret_cast<__nv_bfloat16*>(fsm);
    __nv_bfloat16* sQl = sQh + FL_TILE;
    __nv_bfloat16* sKh = sQl + FL_TILE;
    __nv_bfloat16* sKl = sKh + FL_TILE;
    __nv_bfloat16* sVh = sKl + FL_TILE;
    __nv_bfloat16* sVl = sVh + FL_TILE;

    int tid = threadIdx.x;
    int lane = tid & 31;
    int wid = tid >> 5;
    int g = lane >> 2, tg = lane & 3;

    int qb = blockIdx.x;
    int z = blockIdx.y;
    int b = z / HH, h = z % HH;
    int row0 = qb * 128;

    const __nv_bfloat16* qbh = qh_ + (size_t)b * TT * DD + (size_t)h * DHD;  // stride DD
    const __nv_bfloat16* qbl = ql_ + (size_t)b * TT * DD + (size_t)h * DHD;
    const __nv_bfloat16* kbh = khh + (size_t)z * TT * DHD;
    const __nv_bfloat16* kbl = khl + (size_t)z * TT * DHD;
    const __nv_bfloat16* vbh = vhh + (size_t)z * TT * DHD;
    const __nv_bfloat16* vbl = vhl + (size_t)z * TT * DHD;

    // stage Q tile
    for (int e = tid; e < 128 * 16; e += 256) {
        int r = e >> 4, c8 = (e & 15) * 8;
        *reinterpret_cast<uint4*>(&sQh[r * FL_PITCH + c8]) =
            *reinterpret_cast<const uint4*>(qbh + (size_t)(row0 + r) * DD + c8);
        *reinterpret_cast<uint4*>(&sQl[r * FL_PITCH + c8]) =
            *reinterpret_cast<const uint4*>(qbl + (size_t)(row0 + r) * DD + c8);
    }

    float accO[16][4];
    #pragma unroll
    for (int i = 0; i < 16; ++i)
        #pragma unroll
        for (int j = 0; j < 4; ++j) accO[i][j] = 0.f;
    float mrun0 = -INFINITY, mrun1 = -INFINITY;
    float lrun0 = 0.f, lrun1 = 0.f;

    for (int kb = 0; kb <= qb; ++kb) {
        __syncthreads();   // previous iteration's MMAs done before overwriting K/V
        for (int e = tid; e < 128 * 16; e += 256) {
            int r = e >> 4, c8 = (e & 15) * 8;
            size_t go = (size_t)(kb * 128 + r) * DHD + c8;
            *reinterpret_cast<uint4*>(&sKh[r * FL_PITCH + c8]) = *reinterpret_cast<const uint4*>(kbh + go);
            *reinterpret_cast<uint4*>(&sKl[r * FL_PITCH + c8]) = *reinterpret_cast<const uint4*>(kbl + go);
            *reinterpret_cast<uint4*>(&sVh[r * FL_PITCH + c8]) = *reinterpret_cast<const uint4*>(vbh + go);
            *reinterpret_cast<uint4*>(&sVl[r * FL_PITCH + c8]) = *reinterpret_cast<const uint4*>(vbl + go);
        }
        __syncthreads();

        // S = Q K^T (3-term split), strip [16 rows][128 keys] per warp
        float S[16][4];
        #pragma unroll
        for (int i = 0; i < 16; ++i)
            #pragma unroll
            for (int j = 0; j < 4; ++j) S[i][j] = 0.f;

        #pragma unroll
        for (int ks = 0; ks < 8; ++ks) {
            uint32_t qf[2][4];
            {
                int r = wid * 16 + (lane & 15);
                int c = ks * 16 + (lane >> 4) * 8;
                ldsm4(qf[0], s2u(&sQh[r * FL_PITCH + c]));
                ldsm4(qf[1], s2u(&sQl[r * FL_PITCH + c]));
            }
            #pragma unroll
            for (int nt = 0; nt < 16; ++nt) {
                uint32_t bh[2], bl[2];
                int r = nt * 8 + (lane & 7);
                int c = ks * 16 + ((lane >> 3) & 1) * 8;
                ldsm2(bh, s2u(&sKh[r * FL_PITCH + c]));
                ldsm2(bl, s2u(&sKl[r * FL_PITCH + c]));
                mma16816(S[nt], qf[0], bh);
                mma16816(S[nt], qf[0], bl);
                mma16816(S[nt], qf[1], bh);
            }
        }

        // scale + causal mask (diagonal block only)
        bool diag = (kb == qb);
        #pragma unroll
        for (int nt = 0; nt < 16; ++nt)
            #pragma unroll
            for (int j = 0; j < 4; ++j) {
                float v = S[nt][j] * scale;
                if (diag) {
                    int n = nt * 8 + tg * 2 + (j & 1);
                    int m = wid * 16 + g + ((j >> 1) ? 8 : 0);
                    if (n > m) v = -INFINITY;
                }
                S[nt][j] = v;
            }

        // row max (per thread, then across tg lanes)
        float mx0 = -INFINITY, mx1 = -INFINITY;
        #pragma unroll
        for (int nt = 0; nt < 16; ++nt) {
            mx0 = fmaxf(mx0, fmaxf(S[nt][0], S[nt][1]));
            mx1 = fmaxf(mx1, fmaxf(S[nt][2], S[nt][3]));
        }
        mx0 = fmaxf(mx0, __shfl_xor_sync(0xffffffffu, mx0, 1));
        mx0 = fmaxf(mx0, __shfl_xor_sync(0xffffffffu, mx0, 2));
        mx1 = fmaxf(mx1, __shfl_xor_sync(0xffffffffu, mx1, 1));
        mx1 = fmaxf(mx1, __shfl_xor_sync(0xffffffffu, mx1, 2));

        float mn0 = fmaxf(mrun0, mx0);
        float mn1 = fmaxf(mrun1, mx1);
        float al0 = expf(mrun0 - mn0);
        float al1 = expf(mrun1 - mn1);
        mrun0 = mn0; mrun1 = mn1;

        float ls0 = 0.f, ls1 = 0.f;
        #pragma unroll
        for (int nt = 0; nt < 16; ++nt) {
            float e0 = expf(S[nt][0] - mn0);
            float e1 = expf(S[nt][1] - mn0);
            float e2 = expf(S[nt][2] - mn1);
            float e3 = expf(S[nt][3] - mn1);
            S[nt][0] = e0; S[nt][1] = e1; S[nt][2] = e2; S[nt][3] = e3;
            ls0 += e0 + e1;
            ls1 += e2 + e3;
        }
        lrun0 = lrun0 * al0 + ls0;
        lrun1 = lrun1 * al1 + ls1;

        #pragma unroll
        for (int nt = 0; nt < 16; ++nt) {
            accO[nt][0] *= al0; accO[nt][1] *= al0;
            accO[nt][2] *= al1; accO[nt][3] *= al1;
        }

        // O += P V  (kk-outer to keep P fragments transient)
        #pragma unroll
        for (int kk = 0; kk < 8; ++kk) {
            uint32_t ph[4], pl[4];
            {
                float v00 = S[2 * kk][0],     v01 = S[2 * kk][1];
                float v02 = S[2 * kk][2],     v03 = S[2 * kk][3];
                float v10 = S[2 * kk + 1][0], v11 = S[2 * kk + 1][1];
                float v12 = S[2 * kk + 1][2], v13 = S[2 * kk + 1][3];
                float h00 = __bfloat162float(__float2bfloat16(v00));
                float h01 = __bfloat162float(__float2bfloat16(v01));
                float h02 = __bfloat162float(__float2bfloat16(v02));
                float h03 = __bfloat162float(__float2bfloat16(v03));
                float h10 = __bfloat162float(__float2bfloat16(v10));
                float h11 = __bfloat162float(__float2bfloat16(v11));
                float h12 = __bfloat162float(__float2bfloat16(v12));
                float h13 = __bfloat162float(__float2bfloat16(v13));
                ph[0] = packb2(h00, h01); ph[1] = packb2(h02, h03);
                ph[2] = packb2(h10, h11); ph[3] = packb2(h12, h13);
                pl[0] = packb2(v00 - h00, v01 - h01); pl[1] = packb2(v02 - h02, v03 - h03);
                pl[2] = packb2(v10 - h10, v11 - h11); pl[3] = packb2(v12 - h12, v13 - h13);
            }
            #pragma unroll
            for (int ndt = 0; ndt < 16; ++ndt) {
                uint32_t vh2[2], vl2[2];
                int rr = kk * 16 + (lane & 15);
                int cc = ndt * 8;
                ldsm2t(vh2, s2u(&sVh[rr * FL_PITCH + cc]));
                ldsm2t(vl2, s2u(&sVl[rr * FL_PITCH + cc]));
                mma16816(accO[ndt], ph, vh2);
                mma16816(accO[ndt], ph, vl2);
                mma16816(accO[ndt], pl, vh2);
            }
        }
    }

    // finalize: reduce l over tg lanes, divide, write split ao
    lrun0 += __shfl_xor_sync(0xffffffffu, lrun0, 1);
    lrun0 += __shfl_xor_sync(0xffffffffu, lrun0, 2);
    lrun1 += __shfl_xor_sync(0xffffffffu, lrun1, 1);
    lrun1 += __shfl_xor_sync(0xffffffffu, lrun1, 2);
    float inv0 = 1.0f / lrun0;
    float inv1 = 1.0f / lrun1;

    size_t obase = (size_t)z * TT * DHD;
    #pragma unroll
    for (int ndt = 0; ndt < 16; ++ndt)
        #pragma unroll
        for (int j = 0; j < 4; ++j) {
            int m = row0 + wid * 16 + g + ((j >> 1) ? 8 : 0);
            int n = ndt * 8 + tg * 2 + (j & 1);
            float v = accO[ndt][j] * ((j >> 1) ? inv1 : inv0);
            size_t idx = obase + (size_t)m * DHD + n;
            split2(v, &aoh[idx], &aol[idx]);
        }
}

// ---------------- host ----------------
#define SYMADDR(var, sym) cudaGetSymbolAddress((void**)&var, sym)

extern "C" void kernel_launch(void* const* d_in, const int* in_sizes, int n_in,
                              void* d_out, int out_size) {
    const float* x   = (const float*)d_in[0];
    const float* l3  = (const float*)d_in[1];
    const float* wq  = (const float*)d_in[2];
    const float* wk  = (const float*)d_in[3];
    const float* wv  = (const float*)d_in[4];
    const float* wo  = (const float*)d_in[5];
    const float* rw1 = (const float*)d_in[6];
    const float* rb1 = (const float*)d_in[7];
    const float* rw2 = (const float*)d_in[8];
    const float* rb2 = (const float*)d_in[9];

    float* out     = (float*)d_out;
    float* kh_out  = out    + (size_t)BB * TT * DD;
    float* vh_out  = kh_out + (size_t)BB * TT * DD;
    float* lam_out = vh_out + (size_t)BB * TT * DD;

    float *l2, *hdn;
    SYMADDR(l2, g_l2); SYMADDR(hdn, g_hdn);

    __nv_bfloat16 *xs_h,*xs_l, *wqs_h,*wqs_l, *wks_h,*wks_l, *wvs_h,*wvs_l,
                  *wos_h,*wos_l, *rw1s_h,*rw1s_l, *qs_h,*qs_l, *fs_h,*fs_l,
                  *khs_h,*khs_l, *vhs_h,*vhs_l, *aos_h,*aos_l;
    SYMADDR(xs_h, g_xs_h);     SYMADDR(xs_l, g_xs_l);
    SYMADDR(wqs_h, g_wqs_h);   SYMADDR(wqs_l, g_wqs_l);
    SYMADDR(wks_h, g_wks_h);   SYMADDR(wks_l, g_wks_l);
    SYMADDR(wvs_h, g_wvs_h);   SYMADDR(wvs_l, g_wvs_l);
    SYMADDR(wos_h, g_wos_h);   SYMADDR(wos_l, g_wos_l);
    SYMADDR(rw1s_h, g_rw1s_h); SYMADDR(rw1s_l, g_rw1s_l);
    SYMADDR(qs_h, g_qs_h);     SYMADDR(qs_l, g_qs_l);
    SYMADDR(fs_h, g_fs_h);     SYMADDR(fs_l, g_fs_l);
    SYMADDR(khs_h, g_khs_h);   SYMADDR(khs_l, g_khs_l);
    SYMADDR(vhs_h, g_vhs_h);   SYMADDR(vhs_l, g_vhs_l);
    SYMADDR(aos_h, g_aos_h);   SYMADDR(aos_l, g_aos_l);

    const int M = BB * TT;
    const float scale = 1.0f / sqrtf((float)DHD);
    const size_t ND = (size_t)BB * TT * DD;
    const size_t NW = (size_t)DD * DD;

    // raise dynamic smem limits (idempotent)
    cudaFuncSetAttribute(mma_gemm<M_Q>,   cudaFuncAttributeMaxDynamicSharedMemorySize, GEMM_SMEM);
    cudaFuncSetAttribute(mma_gemm<M_HDN>, cudaFuncAttributeMaxDynamicSharedMemorySize, GEMM_SMEM);
    cudaFuncSetAttribute(mma_gemm<M_KV>,  cudaFuncAttributeMaxDynamicSharedMemorySize, GEMM_SMEM);
    cudaFuncSetAttribute(mma_gemm<M_OUT>, cudaFuncAttributeMaxDynamicSharedMemorySize, GEMM_SMEM);
    cudaFuncSetAttribute(flash_kernel,    cudaFuncAttributeMaxDynamicSharedMemorySize, FLASH_SMEM);

    // splits
    split_kernel<<<(unsigned)((ND + 255) / 256), 256>>>(x, xs_h, xs_l, ND);
    split4_kernel<<<(unsigned)((NW + 255) / 256), 256>>>(
        wq, wk, wv, wo, wqs_h, wqs_l, wks_h, wks_l, wvs_h, wvs_l, wos_h, wos_l, NW);
    split_kernel<<<(unsigned)((NW / 2 + 255) / 256), 256>>>(rw1, rw1s_h, rw1s_l, NW / 2);

    // EMA level
    ema_kernel<<<(BB * DD + 255) / 256, 256>>>(x, l2);

    // q = x @ wq^T
    mma_gemm<M_Q><<<dim3(DD / BN, M / BM), 256, GEMM_SMEM>>>(
        xs_h, xs_l, wqs_h, wqs_l, nullptr, nullptr, qs_h, qs_l, M, DD, DD, DD, DD);

    // hdn = silu(q @ rw1^T + rb1)
    mma_gemm<M_HDN><<<dim3(DHALF / BN, M / BM), 256, GEMM_SMEM>>>(
        qs_h, qs_l, rw1s_h, rw1s_l, rb1, hdn, nullptr, nullptr, M, DHALF, DD, DD, DD);

    // lam
    router_kernel<<<(M + 7) / 8, 256>>>(hdn, rw2, rb2, lam_out);

    // fused
    fuse_split_kernel<<<(unsigned)((ND + 255) / 256), 256>>>(x, l2, l3, lam_out, fs_h, fs_l);

    // kh / vh
    mma_gemm<M_KV><<<dim3(DD / BN, M / BM), 256, GEMM_SMEM>>>(
        fs_h, fs_l, wks_h, wks_l, nullptr, kh_out, khs_h, khs_l, M, DD, DD, DD, DD);
    mma_gemm<M_KV><<<dim3(DD / BN, M / BM), 256, GEMM_SMEM>>>(
        fs_h, fs_l, wvs_h, wvs_l, nullptr, vh_out, vhs_h, vhs_l, M, DD, DD, DD, DD);

    // flash attention -> ao (split)
    flash_kernel<<<dim3(TT / 128, BB * HH), 256, FLASH_SMEM>>>(
        qs_h, qs_l, khs_h, khs_l, vhs_h, vhs_l, aos_h, aos_l, scale);

    // out = concat_heads(ao) @ wo^T
    mma_gemm<M_OUT><<<dim3(DD / BN, M / BM), 256, GEMM_SMEM>>>(
        aos_h, aos_l, wos_h, wos_l, nullptr, out, nullptr, nullptr, M, DD, DD, DD, DD);
}

// round 5
// speedup vs baseline: 2.5182x; 1.1240x over previous
#include <cuda_runtime.h>
#include <cuda_bf16.h>
#include <math.h>
#include <stdint.h>

#define BB 2
#define TT 1024
#define DD 2048
#define HH 16
#define DHD 128
#define DHALF 1024

#define BM 128
#define BN 128
#define BKS 32

// EMA chunking
#define NC 16
#define CL 64
#define BETA 0.9f
#define OMB  0.1f
#define BETA_L 1.1790184577738599e-3f   // 0.9^64

// GEMM modes
#define M_Q 0
#define M_HDN 1
#define M_KV 2
#define M_OUT 3

// ---------------- device scratch ----------------
__device__ float g_l2[(size_t)BB*TT*DD];
__device__ float g_hdn[(size_t)BB*TT*DHALF];
__device__ float g_carryA[(size_t)BB*NC*DD];   // chunk-local end values
__device__ float g_carryB[(size_t)BB*NC*DD];   // carry-in per chunk

#define DECL_SPLIT(name, count) \
    __device__ __nv_bfloat16 name##_h[count]; \
    __device__ __nv_bfloat16 name##_l[count];

DECL_SPLIT(g_xs,   (size_t)BB*TT*DD)
DECL_SPLIT(g_wqs,  (size_t)DD*DD)
DECL_SPLIT(g_wks,  (size_t)DD*DD)
DECL_SPLIT(g_wvs,  (size_t)DD*DD)
DECL_SPLIT(g_wos,  (size_t)DD*DD)
DECL_SPLIT(g_rw1s, (size_t)DHALF*DD)
DECL_SPLIT(g_qs,   (size_t)BB*TT*DD)
DECL_SPLIT(g_fs,   (size_t)BB*TT*DD)
DECL_SPLIT(g_khs,  (size_t)BB*TT*DD)
DECL_SPLIT(g_vhs,  (size_t)BB*TT*DD)
DECL_SPLIT(g_aos,  (size_t)BB*TT*DD)

// ---------------- helpers ----------------
__device__ __forceinline__ void split2(float v, __nv_bfloat16* hi, __nv_bfloat16* lo) {
    __nv_bfloat16 h = __float2bfloat16(v);
    *hi = h;
    *lo = __float2bfloat16(v - __bfloat162float(h));
}
__device__ __forceinline__ uint32_t s2u(const void* p) {
    return (uint32_t)__cvta_generic_to_shared(p);
}
__device__ __forceinline__ void ldsm4(uint32_t* r, uint32_t addr) {
    asm volatile("ldmatrix.sync.aligned.m8n8.x4.shared.b16 {%0,%1,%2,%3}, [%4];"
                 : "=r"(r[0]), "=r"(r[1]), "=r"(r[2]), "=r"(r[3]) : "r"(addr));
}
__device__ __forceinline__ void ldsm2(uint32_t* r, uint32_t addr) {
    asm volatile("ldmatrix.sync.aligned.m8n8.x2.shared.b16 {%0,%1}, [%2];"
                 : "=r"(r[0]), "=r"(r[1]) : "r"(addr));
}
__device__ __forceinline__ void ldsm2t(uint32_t* r, uint32_t addr) {
    asm volatile("ldmatrix.sync.aligned.m8n8.x2.trans.shared.b16 {%0,%1}, [%2];"
                 : "=r"(r[0]), "=r"(r[1]) : "r"(addr));
}
__device__ __forceinline__ void mma16816(float* c, const uint32_t* a, const uint32_t* b) {
    asm volatile("mma.sync.aligned.m16n8k16.row.col.f32.bf16.bf16.f32 "
                 "{%0,%1,%2,%3}, {%4,%5,%6,%7}, {%8,%9}, {%0,%1,%2,%3};"
                 : "+f"(c[0]), "+f"(c[1]), "+f"(c[2]), "+f"(c[3])
                 : "r"(a[0]), "r"(a[1]), "r"(a[2]), "r"(a[3]), "r"(b[0]), "r"(b[1]));
}
__device__ __forceinline__ void cp16(uint32_t saddr, const void* g) {
    asm volatile("cp.async.cg.shared.global [%0], [%1], 16;" :: "r"(saddr), "l"(g));
}
__device__ __forceinline__ void cp_commit() {
    asm volatile("cp.async.commit_group;");
}
template<int N> __device__ __forceinline__ void cp_wait() {
    asm volatile("cp.async.wait_group %0;" :: "n"(N));
}
__device__ __forceinline__ uint32_t packb2(float lo_k, float hi_k) {
    __nv_bfloat162 t = __floats2bfloat162_rn(lo_k, hi_k);
    return *reinterpret_cast<uint32_t*>(&t);
}

// ---------------- elementwise kernels ----------------
__global__ void split_kernel(const float* __restrict__ s,
                             __nv_bfloat16* __restrict__ hi,
                             __nv_bfloat16* __restrict__ lo, size_t n) {
    size_t i = (size_t)blockIdx.x * blockDim.x + threadIdx.x;
    if (i < n) split2(s[i], &hi[i], &lo[i]);
}

__global__ void split4_kernel(const float* __restrict__ a, const float* __restrict__ b,
                              const float* __restrict__ c, const float* __restrict__ d,
                              __nv_bfloat16* __restrict__ ah, __nv_bfloat16* __restrict__ al,
                              __nv_bfloat16* __restrict__ bh, __nv_bfloat16* __restrict__ bl,
                              __nv_bfloat16* __restrict__ ch, __nv_bfloat16* __restrict__ cl,
                              __nv_bfloat16* __restrict__ dh, __nv_bfloat16* __restrict__ dl,
                              size_t n) {
    size_t i = (size_t)blockIdx.x * blockDim.x + threadIdx.x;
    if (i >= n) return;
    split2(a[i], &ah[i], &al[i]);
    split2(b[i], &bh[i], &bl[i]);
    split2(c[i], &ch[i], &cl[i]);
    split2(d[i], &dh[i], &dl[i]);
}

// ---- chunk-parallel EMA ----
// A: per (b, chunk, c): local scan of chunk from 0, store end value
__global__ void ema_chunk_kernel(const float* __restrict__ x, float* __restrict__ carryA) {
    int idx = blockIdx.x * blockDim.x + threadIdx.x;       // (b*NC + chunk)*DD + c
    if (idx >= BB * NC * DD) return;
    int c = idx % DD;
    int bc = idx / DD;
    int chunk = bc % NC;
    int b = bc / NC;
    const float* xp = x + (size_t)b * TT * DD + (size_t)chunk * CL * DD + c;
    float s = 0.f;
    #pragma unroll 8
    for (int t = 0; t < CL; ++t)
        s = BETA * s + OMB * xp[(size_t)t * DD];
    carryA[idx] = s;
}

// B: per (b, c): propagate carries across chunks
__global__ void ema_carry_kernel(const float* __restrict__ carryA, float* __restrict__ carryB) {
    int idx = blockIdx.x * blockDim.x + threadIdx.x;       // b*DD + c
    if (idx >= BB * DD) return;
    int c = idx % DD;
    int b = idx / DD;
    float cin = 0.f;
    #pragma unroll
    for (int j = 0; j < NC; ++j) {
        size_t off = ((size_t)b * NC + j) * DD + c;
        carryB[off] = cin;
        cin = BETA_L * cin + carryA[off];
    }
}

// C: per (b, chunk, c): rescan with carry-in, write outputs
__global__ void ema_final_kernel(const float* __restrict__ x, const float* __restrict__ carryB,
                                 float* __restrict__ l2) {
    int idx = blockIdx.x * blockDim.x + threadIdx.x;
    if (idx >= BB * NC * DD) return;
    int c = idx % DD;
    int bc = idx / DD;
    int chunk = bc % NC;
    int b = bc / NC;
    size_t base = (size_t)b * TT * DD + (size_t)chunk * CL * DD + c;
    const float* xp = x + base;
    float* op = l2 + base;
    float s = carryB[idx];
    #pragma unroll 8
    for (int t = 0; t < CL; ++t) {
        s = BETA * s + OMB * xp[(size_t)t * DD];
        op[(size_t)t * DD] = s;
    }
}

__global__ void router_kernel(const float* __restrict__ hdn,
                              const float* __restrict__ rw2,
                              const float* __restrict__ rb2,
                              float* __restrict__ lam) {
    int row  = blockIdx.x * (blockDim.x / 32) + (threadIdx.x / 32);
    int lane = threadIdx.x & 31;
    if (row >= BB * TT) return;
    const float* hp = hdn + (size_t)row * DHALF;
    float a0 = 0.f, a1 = 0.f, a2 = 0.f;
    for (int i = lane; i < DHALF; i += 32) {
        float h = hp[i];
        a0 += h * rw2[0 * DHALF + i];
        a1 += h * rw2[1 * DHALF + i];
        a2 += h * rw2[2 * DHALF + i];
    }
    #pragma unroll
    for (int o = 16; o > 0; o >>= 1) {
        a0 += __shfl_xor_sync(0xffffffffu, a0, o);
        a1 += __shfl_xor_sync(0xffffffffu, a1, o);
        a2 += __shfl_xor_sync(0xffffffffu, a2, o);
    }
    if (lane == 0) {
        float z0 = a0 + rb2[0], z1 = a1 + rb2[1], z2 = a2 + rb2[2];
        float m = fmaxf(z0, fmaxf(z1, z2));
        float e0 = expf(z0 - m), e1 = expf(z1 - m), e2 = expf(z2 - m);
        float inv = 1.0f / (e0 + e1 + e2);
        lam[(size_t)row * 3 + 0] = e0 * inv;
        lam[(size_t)row * 3 + 1] = e1 * inv;
        lam[(size_t)row * 3 + 2] = e2 * inv;
    }
}

__global__ void fuse_split_kernel(const float* __restrict__ x,
                                  const float* __restrict__ l2,
                                  const float* __restrict__ l3,
                                  const float* __restrict__ lam,
                                  __nv_bfloat16* __restrict__ fhi,
                                  __nv_bfloat16* __restrict__ flo) {
    size_t i = (size_t)blockIdx.x * blockDim.x + threadIdx.x;
    if (i >= (size_t)BB * TT * DD) return;
    int c = (int)(i % DD);
    size_t row = i / DD;
    int b = (int)(row / TT);
    float a0 = lam[row * 3 + 0];
    float a1 = lam[row * 3 + 1];
    float a2 = lam[row * 3 + 2];
    float f = a0 * x[i] + a1 * l2[i] + a2 * l3[(size_t)b * DD + c];
    split2(f, &fhi[i], &flo[i]);
}

// ---------------- pipelined split-bf16 tensor-core GEMM ----------------
#define GEMM_SMEM (2 * 2 * BM * 40 * 2 * 2)

template<int MODE>
__global__ void __launch_bounds__(256) mma_gemm(
    const __nv_bfloat16* __restrict__ Ahi, const __nv_bfloat16* __restrict__ Alo,
    const __nv_bfloat16* __restrict__ Bhi, const __nv_bfloat16* __restrict__ Blo,
    const float* __restrict__ bias,
    float* __restrict__ Cf,
    __nv_bfloat16* __restrict__ Chi, __nv_bfloat16* __restrict__ Clo,
    int M, int N, int K, int lda, int ldb)
{
    extern __shared__ __align__(16) char dynsmem[];
    __nv_bfloat16* sA = reinterpret_cast<__nv_bfloat16*>(dynsmem);
    __nv_bfloat16* sB = sA + 2 * 2 * BM * 40;

    int tid = threadIdx.x;
    int lane = tid & 31;
    int warp = tid >> 5;
    int wm = warp >> 2;
    int wn = warp & 3;
    int row0 = blockIdx.y * BM;
    int col0 = blockIdx.x * BN;

    float acc[4][4][4];
    #pragma unroll
    for (int a = 0; a < 4; ++a)
        #pragma unroll
        for (int b = 0; b < 4; ++b)
            #pragma unroll
            for (int c = 0; c < 4; ++c) acc[a][b][c] = 0.f;

    auto issue = [&](int k0, int st) {
        #pragma unroll
        for (int it = 0; it < 2; ++it) {
            int e = tid + it * 256;
            int r = e >> 2;
            int kc = (e & 3) * 8;
            size_t ao;
            if (MODE == M_OUT) {
                int gm = row0 + r, gk = k0 + kc;
                int b = gm >> 10, t = gm & (TT - 1);
                int h = gk >> 7, c = gk & (DHD - 1);
                ao = (((size_t)b * HH + h) * TT + t) * DHD + c;
            } else {
                ao = (size_t)(row0 + r) * lda + k0 + kc;
            }
            cp16(s2u(&sA[((st * 2 + 0) * BM + r) * 40 + kc]), Ahi + ao);
            cp16(s2u(&sA[((st * 2 + 1) * BM + r) * 40 + kc]), Alo + ao);
            size_t bo = (size_t)(col0 + r) * ldb + k0 + kc;
            cp16(s2u(&sB[((st * 2 + 0) * BM + r) * 40 + kc]), Bhi + bo);
            cp16(s2u(&sB[((st * 2 + 1) * BM + r) * 40 + kc]), Blo + bo);
        }
    };

    int nIter = K / BKS;
    issue(0, 0);
    cp_commit();

    for (int i = 0; i < nIter; ++i) {
        int st = i & 1;
        if (i + 1 < nIter) {
            issue((i + 1) * BKS, (i + 1) & 1);
            cp_commit();
            cp_wait<1>();
        } else {
            cp_wait<0>();
        }
        __syncthreads();

        #pragma unroll
        for (int ks = 0; ks < BKS; ks += 16) {
            uint32_t afr[2][4][4];
            uint32_t bfr[2][4][2];
            #pragma unroll
            for (int mt = 0; mt < 4; ++mt) {
                int r = wm * 64 + mt * 16 + (lane & 15);
                int c = ks + (lane >> 4) * 8;
                ldsm4(afr[0][mt], s2u(&sA[((st * 2 + 0) * BM + r) * 40 + c]));
                ldsm4(afr[1][mt], s2u(&sA[((st * 2 + 1) * BM + r) * 40 + c]));
            }
            #pragma unroll
            for (int nt = 0; nt < 4; ++nt) {
                int r = wn * 32 + nt * 8 + (lane & 7);
                int c = ks + ((lane >> 3) & 1) * 8;
                ldsm2(bfr[0][nt], s2u(&sB[((st * 2 + 0) * BM + r) * 40 + c]));
                ldsm2(bfr[1][nt], s2u(&sB[((st * 2 + 1) * BM + r) * 40 + c]));
            }
            #pragma unroll
            for (int mt = 0; mt < 4; ++mt)
                #pragma unroll
                for (int nt = 0; nt < 4; ++nt) {
                    mma16816(acc[mt][nt], afr[0][mt], bfr[0][nt]);
                    mma16816(acc[mt][nt], afr[0][mt], bfr[1][nt]);
                    mma16816(acc[mt][nt], afr[1][mt], bfr[0][nt]);
                }
        }
        __syncthreads();
    }

    int g = lane >> 2, tg = lane & 3;
    #pragma unroll
    for (int mt = 0; mt < 4; ++mt)
        #pragma unroll
        for (int nt = 0; nt < 4; ++nt)
            #pragma unroll
            for (int i = 0; i < 4; ++i) {
                int m = row0 + wm * 64 + mt * 16 + g + (i >> 1) * 8;
                int n = col0 + wn * 32 + nt * 8 + tg * 2 + (i & 1);
                float v = acc[mt][nt][i];
                if (MODE == M_Q) {
                    size_t idx = (size_t)m * N + n;
                    split2(v, &Chi[idx], &Clo[idx]);
                } else if (MODE == M_HDN) {
                    v += bias[n];
                    Cf[(size_t)m * N + n] = v / (1.f + expf(-v));
                } else if (MODE == M_KV) {
                    int b = m >> 10, t = m & (TT - 1);
                    int h = n >> 7, c = n & (DHD - 1);
                    size_t idx = (((size_t)b * HH + h) * TT + t) * DHD + c;
                    Cf[idx] = v;
                    split2(v, &Chi[idx], &Clo[idx]);
                } else {
                    Cf[(size_t)m * N + n] = v;
                }
            }
}

// ---------------- flash attention ----------------
#define FL_PITCH 136
#define FL_TILE  (128 * FL_PITCH)
#define FLASH_SMEM (6 * FL_TILE * 2)

__global__ void __launch_bounds__(256) flash_kernel(
    const __nv_bfloat16* __restrict__ qh_, const __nv_bfloat16* __restrict__ ql_,
    const __nv_bfloat16* __restrict__ khh, const __nv_bfloat16* __restrict__ khl,
    const __nv_bfloat16* __restrict__ vhh, const __nv_bfloat16* __restrict__ vhl,
    __nv_bfloat16* __restrict__ aoh, __nv_bfloat16* __restrict__ aol,
    float scale)
{
    extern __shared__ __align__(16) char fsm[];
    __nv_bfloat16* sQh = reinterpret_cast<__nv_bfloat16*>(fsm);
    __nv_bfloat16* sQl = sQh + FL_TILE;
    __nv_bfloat16* sKh = sQl + FL_TILE;
    __nv_bfloat16* sKl = sKh + FL_TILE;
    __nv_bfloat16* sVh = sKl + FL_TILE;
    __nv_bfloat16* sVl = sVh + FL_TILE;

    int tid = threadIdx.x;
    int lane = tid & 31;
    int wid = tid >> 5;
    int g = lane >> 2, tg = lane & 3;

    int qb = gridDim.x - 1 - blockIdx.x;   // heavy (diagonal-rich) blocks first
    int z = blockIdx.y;
    int b = z / HH, h = z % HH;
    int row0 = qb * 128;

    const __nv_bfloat16* qbh = qh_ + (size_t)b * TT * DD + (size_t)h * DHD;
    const __nv_bfloat16* qbl = ql_ + (size_t)b * TT * DD + (size_t)h * DHD;
    const __nv_bfloat16* kbh = khh + (size_t)z * TT * DHD;
    const __nv_bfloat16* kbl = khl + (size_t)z * TT * DHD;
    const __nv_bfloat16* vbh = vhh + (size_t)z * TT * DHD;
    const __nv_bfloat16* vbl = vhl + (size_t)z * TT * DHD;

    for (int e = tid; e < 128 * 16; e += 256) {
        int r = e >> 4, c8 = (e & 15) * 8;
        *reinterpret_cast<uint4*>(&sQh[r * FL_PITCH + c8]) =
            *reinterpret_cast<const uint4*>(qbh + (size_t)(row0 + r) * DD + c8);
        *reinterpret_cast<uint4*>(&sQl[r * FL_PITCH + c8]) =
            *reinterpret_cast<const uint4*>(qbl + (size_t)(row0 + r) * DD + c8);
    }

    float accO[16][4];
    #pragma unroll
    for (int i = 0; i < 16; ++i)
        #pragma unroll
        for (int j = 0; j < 4; ++j) accO[i][j] = 0.f;
    float mrun0 = -INFINITY, mrun1 = -INFINITY;
    float lrun0 = 0.f, lrun1 = 0.f;

    for (int kb = 0; kb <= qb; ++kb) {
        __syncthreads();
        for (int e = tid; e < 128 * 16; e += 256) {
            int r = e >> 4, c8 = (e & 15) * 8;
            size_t go = (size_t)(kb * 128 + r) * DHD + c8;
            *reinterpret_cast<uint4*>(&sKh[r * FL_PITCH + c8]) = *reinterpret_cast<const uint4*>(kbh + go);
            *reinterpret_cast<uint4*>(&sKl[r * FL_PITCH + c8]) = *reinterpret_cast<const uint4*>(kbl + go);
            *reinterpret_cast<uint4*>(&sVh[r * FL_PITCH + c8]) = *reinterpret_cast<const uint4*>(vbh + go);
            *reinterpret_cast<uint4*>(&sVl[r * FL_PITCH + c8]) = *reinterpret_cast<const uint4*>(vbl + go);
        }
        __syncthreads();

        float S[16][4];
        #pragma unroll
        for (int i = 0; i < 16; ++i)
            #pragma unroll
            for (int j = 0; j < 4; ++j) S[i][j] = 0.f;

        #pragma unroll
        for (int ks = 0; ks < 8; ++ks) {
            uint32_t qf[2][4];
            {
                int r = wid * 16 + (lane & 15);
                int c = ks * 16 + (lane >> 4) * 8;
                ldsm4(qf[0], s2u(&sQh[r * FL_PITCH + c]));
                ldsm4(qf[1], s2u(&sQl[r * FL_PITCH + c]));
            }
            #pragma unroll
            for (int nt = 0; nt < 16; ++nt) {
                uint32_t bh[2], bl[2];
                int r = nt * 8 + (lane & 7);
                int c = ks * 16 + ((lane >> 3) & 1) * 8;
                ldsm2(bh, s2u(&sKh[r * FL_PITCH + c]));
                ldsm2(bl, s2u(&sKl[r * FL_PITCH + c]));
                mma16816(S[nt], qf[0], bh);
                mma16816(S[nt], qf[0], bl);
                mma16816(S[nt], qf[1], bh);
            }
        }

        bool diag = (kb == qb);
        #pragma unroll
        for (int nt = 0; nt < 16; ++nt)
            #pragma unroll
            for (int j = 0; j < 4; ++j) {
                float v = S[nt][j] * scale;
                if (diag) {
                    int n = nt * 8 + tg * 2 + (j & 1);
                    int m = wid * 16 + g + ((j >> 1) ? 8 : 0);
                    if (n > m) v = -INFINITY;
                }
                S[nt][j] = v;
            }

        float mx0 = -INFINITY, mx1 = -INFINITY;
        #pragma unroll
        for (int nt = 0; nt < 16; ++nt) {
            mx0 = fmaxf(mx0, fmaxf(S[nt][0], S[nt][1]));
            mx1 = fmaxf(mx1, fmaxf(S[nt][2], S[nt][3]));
        }
        mx0 = fmaxf(mx0, __shfl_xor_sync(0xffffffffu, mx0, 1));
        mx0 = fmaxf(mx0, __shfl_xor_sync(0xffffffffu, mx0, 2));
        mx1 = fmaxf(mx1, __shfl_xor_sync(0xffffffffu, mx1, 1));
        mx1 = fmaxf(mx1, __shfl_xor_sync(0xffffffffu, mx1, 2));

        float mn0 = fmaxf(mrun0, mx0);
        float mn1 = fmaxf(mrun1, mx1);
        float al0 = expf(mrun0 - mn0);
        float al1 = expf(mrun1 - mn1);
        mrun0 = mn0; mrun1 = mn1;

        float ls0 = 0.f, ls1 = 0.f;
        #pragma unroll
        for (int nt = 0; nt < 16; ++nt) {
            float e0 = expf(S[nt][0] - mn0);
            float e1 = expf(S[nt][1] - mn0);
            float e2 = expf(S[nt][2] - mn1);
            float e3 = expf(S[nt][3] - mn1);
            S[nt][0] = e0; S[nt][1] = e1; S[nt][2] = e2; S[nt][3] = e3;
            ls0 += e0 + e1;
            ls1 += e2 + e3;
        }
        lrun0 = lrun0 * al0 + ls0;
        lrun1 = lrun1 * al1 + ls1;

        #pragma unroll
        for (int nt = 0; nt < 16; ++nt) {
            accO[nt][0] *= al0; accO[nt][1] *= al0;
            accO[nt][2] *= al1; accO[nt][3] *= al1;
        }

        #pragma unroll
        for (int kk = 0; kk < 8; ++kk) {
            uint32_t ph[4], pl[4];
            {
                float v00 = S[2 * kk][0],     v01 = S[2 * kk][1];
                float v02 = S[2 * kk][2],     v03 = S[2 * kk][3];
                float v10 = S[2 * kk + 1][0], v11 = S[2 * kk + 1][1];
                float v12 = S[2 * kk + 1][2], v13 = S[2 * kk + 1][3];
                float h00 = __bfloat162float(__float2bfloat16(v00));
                float h01 = __bfloat162float(__float2bfloat16(v01));
                float h02 = __bfloat162float(__float2bfloat16(v02));
                float h03 = __bfloat162float(__float2bfloat16(v03));
                float h10 = __bfloat162float(__float2bfloat16(v10));
                float h11 = __bfloat162float(__float2bfloat16(v11));
                float h12 = __bfloat162float(__float2bfloat16(v12));
                float h13 = __bfloat162float(__float2bfloat16(v13));
                ph[0] = packb2(h00, h01); ph[1] = packb2(h02, h03);
                ph[2] = packb2(h10, h11); ph[3] = packb2(h12, h13);
                pl[0] = packb2(v00 - h00, v01 - h01); pl[1] = packb2(v02 - h02, v03 - h03);
                pl[2] = packb2(v10 - h10, v11 - h11); pl[3] = packb2(v12 - h12, v13 - h13);
            }
            #pragma unroll
            for (int ndt = 0; ndt < 16; ++ndt) {
                uint32_t vh2[2], vl2[2];
                int rr = kk * 16 + (lane & 15);
                int cc = ndt * 8;
                ldsm2t(vh2, s2u(&sVh[rr * FL_PITCH + cc]));
                ldsm2t(vl2, s2u(&sVl[rr * FL_PITCH + cc]));
                mma16816(accO[ndt], ph, vh2);
                mma16816(accO[ndt], ph, vl2);
                mma16816(accO[ndt], pl, vh2);
            }
        }
    }

    lrun0 += __shfl_xor_sync(0xffffffffu, lrun0, 1);
    lrun0 += __shfl_xor_sync(0xffffffffu, lrun0, 2);
    lrun1 += __shfl_xor_sync(0xffffffffu, lrun1, 1);
    lrun1 += __shfl_xor_sync(0xffffffffu, lrun1, 2);
    float inv0 = 1.0f / lrun0;
    float inv1 = 1.0f / lrun1;

    size_t obase = (size_t)z * TT * DHD;
    #pragma unroll
    for (int ndt = 0; ndt < 16; ++ndt)
        #pragma unroll
        for (int j = 0; j < 4; ++j) {
            int m = row0 + wid * 16 + g + ((j >> 1) ? 8 : 0);
            int n = ndt * 8 + tg * 2 + (j & 1);
            float v = accO[ndt][j] * ((j >> 1) ? inv1 : inv0);
            size_t idx = obase + (size_t)m * DHD + n;
            split2(v, &aoh[idx], &aol[idx]);
        }
}

// ---------------- host ----------------
#define SYMADDR(var, sym) cudaGetSymbolAddress((void**)&var, sym)

extern "C" void kernel_launch(void* const* d_in, const int* in_sizes, int n_in,
                              void* d_out, int out_size) {
    const float* x   = (const float*)d_in[0];
    const float* l3  = (const float*)d_in[1];
    const float* wq  = (const float*)d_in[2];
    const float* wk  = (const float*)d_in[3];
    const float* wv  = (const float*)d_in[4];
    const float* wo  = (const float*)d_in[5];
    const float* rw1 = (const float*)d_in[6];
    const float* rb1 = (const float*)d_in[7];
    const float* rw2 = (const float*)d_in[8];
    const float* rb2 = (const float*)d_in[9];

    float* out     = (float*)d_out;
    float* kh_out  = out    + (size_t)BB * TT * DD;
    float* vh_out  = kh_out + (size_t)BB * TT * DD;
    float* lam_out = vh_out + (size_t)BB * TT * DD;

    float *l2, *hdn, *carryA, *carryB;
    SYMADDR(l2, g_l2); SYMADDR(hdn, g_hdn);
    SYMADDR(carryA, g_carryA); SYMADDR(carryB, g_carryB);

    __nv_bfloat16 *xs_h,*xs_l, *wqs_h,*wqs_l, *wks_h,*wks_l, *wvs_h,*wvs_l,
                  *wos_h,*wos_l, *rw1s_h,*rw1s_l, *qs_h,*qs_l, *fs_h,*fs_l,
                  *khs_h,*khs_l, *vhs_h,*vhs_l, *aos_h,*aos_l;
    SYMADDR(xs_h, g_xs_h);     SYMADDR(xs_l, g_xs_l);
    SYMADDR(wqs_h, g_wqs_h);   SYMADDR(wqs_l, g_wqs_l);
    SYMADDR(wks_h, g_wks_h);   SYMADDR(wks_l, g_wks_l);
    SYMADDR(wvs_h, g_wvs_h);   SYMADDR(wvs_l, g_wvs_l);
    SYMADDR(wos_h, g_wos_h);   SYMADDR(wos_l, g_wos_l);
    SYMADDR(rw1s_h, g_rw1s_h); SYMADDR(rw1s_l, g_rw1s_l);
    SYMADDR(qs_h, g_qs_h);     SYMADDR(qs_l, g_qs_l);
    SYMADDR(fs_h, g_fs_h);     SYMADDR(fs_l, g_fs_l);
    SYMADDR(khs_h, g_khs_h);   SYMADDR(khs_l, g_khs_l);
    SYMADDR(vhs_h, g_vhs_h);   SYMADDR(vhs_l, g_vhs_l);
    SYMADDR(aos_h, g_aos_h);   SYMADDR(aos_l, g_aos_l);

    const int M = BB * TT;
    const float scale = 1.0f / sqrtf((float)DHD);
    const size_t ND = (size_t)BB * TT * DD;
    const size_t NW = (size_t)DD * DD;

    cudaFuncSetAttribute(mma_gemm<M_Q>,   cudaFuncAttributeMaxDynamicSharedMemorySize, GEMM_SMEM);
    cudaFuncSetAttribute(mma_gemm<M_HDN>, cudaFuncAttributeMaxDynamicSharedMemorySize, GEMM_SMEM);
    cudaFuncSetAttribute(mma_gemm<M_KV>,  cudaFuncAttributeMaxDynamicSharedMemorySize, GEMM_SMEM);
    cudaFuncSetAttribute(mma_gemm<M_OUT>, cudaFuncAttributeMaxDynamicSharedMemorySize, GEMM_SMEM);
    cudaFuncSetAttribute(flash_kernel,    cudaFuncAttributeMaxDynamicSharedMemorySize, FLASH_SMEM);

    // splits
    split_kernel<<<(unsigned)((ND + 255) / 256), 256>>>(x, xs_h, xs_l, ND);
    split4_kernel<<<(unsigned)((NW + 255) / 256), 256>>>(
        wq, wk, wv, wo, wqs_h, wqs_l, wks_h, wks_l, wvs_h, wvs_l, wos_h, wos_l, NW);
    split_kernel<<<(unsigned)((NW / 2 + 255) / 256), 256>>>(rw1, rw1s_h, rw1s_l, NW / 2);

    // chunk-parallel EMA
    ema_chunk_kernel<<<(BB * NC * DD + 255) / 256, 256>>>(x, carryA);
    ema_carry_kernel<<<(BB * DD + 255) / 256, 256>>>(carryA, carryB);
    ema_final_kernel<<<(BB * NC * DD + 255) / 256, 256>>>(x, carryB, l2);

    // q = x @ wq^T
    mma_gemm<M_Q><<<dim3(DD / BN, M / BM), 256, GEMM_SMEM>>>(
        xs_h, xs_l, wqs_h, wqs_l, nullptr, nullptr, qs_h, qs_l, M, DD, DD, DD, DD);

    // hdn = silu(q @ rw1^T + rb1)
    mma_gemm<M_HDN><<<dim3(DHALF / BN, M / BM), 256, GEMM_SMEM>>>(
        qs_h, qs_l, rw1s_h, rw1s_l, rb1, hdn, nullptr, nullptr, M, DHALF, DD, DD, DD);

    // lam
    router_kernel<<<(M + 7) / 8, 256>>>(hdn, rw2, rb2, lam_out);

    // fused
    fuse_split_kernel<<<(unsigned)((ND + 255) / 256), 256>>>(x, l2, l3, lam_out, fs_h, fs_l);

    // kh / vh
    mma_gemm<M_KV><<<dim3(DD / BN, M / BM), 256, GEMM_SMEM>>>(
        fs_h, fs_l, wks_h, wks_l, nullptr, kh_out, khs_h, khs_l, M, DD, DD, DD, DD);
    mma_gemm<M_KV><<<dim3(DD / BN, M / BM), 256, GEMM_SMEM>>>(
        fs_h, fs_l, wvs_h, wvs_l, nullptr, vh_out, vhs_h, vhs_l, M, DD, DD, DD, DD);

    // flash attention -> ao (split)
    flash_kernel<<<dim3(TT / 128, BB * HH), 256, FLASH_SMEM>>>(
        qs_h, qs_l, khs_h, khs_l, vhs_h, vhs_l, aos_h, aos_l, scale);

    // out = concat_heads(ao) @ wo^T
    mma_gemm<M_OUT><<<dim3(DD / BN, M / BM), 256, GEMM_SMEM>>>(
        aos_h, aos_l, wos_h, wos_l, nullptr, out, nullptr, nullptr, M, DD, DD, DD, DD);
}

// round 7
// speedup vs baseline: 2.5478x; 1.0117x over previous
#include <cuda_runtime.h>
#include <cuda_bf16.h>
#include <math.h>
#include <stdint.h>

#define BB 2
#define TT 1024
#define DD 2048
#define HH 16
#define DHD 128
#define DHALF 1024

#define BM 128
#define BN 128
#define BKS 32

// EMA chunking
#define NC 16
#define CL 64
#define BETA 0.9f
#define OMB  0.1f
#define BETA_L 1.1790184577738599e-3f   // 0.9^64

// GEMM modes
#define M_Q 0
#define M_HDN 1
#define M_KV 2
#define M_OUT 3

// ---------------- device scratch ----------------
__device__ float g_l2[(size_t)BB*TT*DD];
__device__ float g_hdn[(size_t)BB*TT*DHALF];
__device__ float g_carryA[(size_t)BB*NC*DD];
__device__ float g_carryB[(size_t)BB*NC*DD];

#define DECL_SPLIT(name, count) \
    __device__ __nv_bfloat16 name##_h[count]; \
    __device__ __nv_bfloat16 name##_l[count];

DECL_SPLIT(g_xs,   (size_t)BB*TT*DD)
DECL_SPLIT(g_wqs,  (size_t)DD*DD)
DECL_SPLIT(g_wks,  (size_t)DD*DD)
DECL_SPLIT(g_wvs,  (size_t)DD*DD)
DECL_SPLIT(g_wos,  (size_t)DD*DD)
DECL_SPLIT(g_rw1s, (size_t)DHALF*DD)
DECL_SPLIT(g_qs,   (size_t)BB*TT*DD)
DECL_SPLIT(g_fs,   (size_t)BB*TT*DD)
DECL_SPLIT(g_khs,  (size_t)BB*TT*DD)
DECL_SPLIT(g_vhs,  (size_t)BB*TT*DD)
DECL_SPLIT(g_aos,  (size_t)BB*TT*DD)

// ---------------- helpers ----------------
__device__ __forceinline__ void split2(float v, __nv_bfloat16* hi, __nv_bfloat16* lo) {
    __nv_bfloat16 h = __float2bfloat16(v);
    *hi = h;
    *lo = __float2bfloat16(v - __bfloat162float(h));
}
__device__ __forceinline__ uint32_t s2u(const void* p) {
    return (uint32_t)__cvta_generic_to_shared(p);
}
__device__ __forceinline__ void ldsm4(uint32_t* r, uint32_t addr) {
    asm volatile("ldmatrix.sync.aligned.m8n8.x4.shared.b16 {%0,%1,%2,%3}, [%4];"
                 : "=r"(r[0]), "=r"(r[1]), "=r"(r[2]), "=r"(r[3]) : "r"(addr));
}
__device__ __forceinline__ void ldsm2(uint32_t* r, uint32_t addr) {
    asm volatile("ldmatrix.sync.aligned.m8n8.x2.shared.b16 {%0,%1}, [%2];"
                 : "=r"(r[0]), "=r"(r[1]) : "r"(addr));
}
__device__ __forceinline__ void ldsm2t(uint32_t* r, uint32_t addr) {
    asm volatile("ldmatrix.sync.aligned.m8n8.x2.trans.shared.b16 {%0,%1}, [%2];"
                 : "=r"(r[0]), "=r"(r[1]) : "r"(addr));
}
__device__ __forceinline__ void mma16816(float* c, const uint32_t* a, const uint32_t* b) {
    asm volatile("mma.sync.aligned.m16n8k16.row.col.f32.bf16.bf16.f32 "
                 "{%0,%1,%2,%3}, {%4,%5,%6,%7}, {%8,%9}, {%0,%1,%2,%3};"
                 : "+f"(c[0]), "+f"(c[1]), "+f"(c[2]), "+f"(c[3])
                 : "r"(a[0]), "r"(a[1]), "r"(a[2]), "r"(a[3]), "r"(b[0]), "r"(b[1]));
}
__device__ __forceinline__ void cp16(uint32_t saddr, const void* g) {
    asm volatile("cp.async.cg.shared.global [%0], [%1], 16;" :: "r"(saddr), "l"(g));
}
__device__ __forceinline__ void cp_commit() {
    asm volatile("cp.async.commit_group;");
}
template<int N> __device__ __forceinline__ void cp_wait() {
    asm volatile("cp.async.wait_group %0;" :: "n"(N));
}
__device__ __forceinline__ uint32_t packb2(float lo_k, float hi_k) {
    __nv_bfloat162 t = __floats2bfloat162_rn(lo_k, hi_k);
    return *reinterpret_cast<uint32_t*>(&t);
}

// ---------------- elementwise kernels ----------------
__global__ void split_kernel(const float* __restrict__ s,
                             __nv_bfloat16* __restrict__ hi,
                             __nv_bfloat16* __restrict__ lo, size_t n) {
    size_t i = (size_t)blockIdx.x * blockDim.x + threadIdx.x;
    if (i < n) split2(s[i], &hi[i], &lo[i]);
}

__global__ void split4_kernel(const float* __restrict__ a, const float* __restrict__ b,
                              const float* __restrict__ c, const float* __restrict__ d,
                              __nv_bfloat16* __restrict__ ah, __nv_bfloat16* __restrict__ al,
                              __nv_bfloat16* __restrict__ bh, __nv_bfloat16* __restrict__ bl,
                              __nv_bfloat16* __restrict__ ch, __nv_bfloat16* __restrict__ cl,
                              __nv_bfloat16* __restrict__ dh, __nv_bfloat16* __restrict__ dl,
                              size_t n) {
    size_t i = (size_t)blockIdx.x * blockDim.x + threadIdx.x;
    if (i >= n) return;
    split2(a[i], &ah[i], &al[i]);
    split2(b[i], &bh[i], &bl[i]);
    split2(c[i], &ch[i], &cl[i]);
    split2(d[i], &dh[i], &dl[i]);
}

__global__ void ema_chunk_kernel(const float* __restrict__ x, float* __restrict__ carryA) {
    int idx = blockIdx.x * blockDim.x + threadIdx.x;
    if (idx >= BB * NC * DD) return;
    int c = idx % DD;
    int bc = idx / DD;
    int chunk = bc % NC;
    int b = bc / NC;
    const float* xp = x + (size_t)b * TT * DD + (size_t)chunk * CL * DD + c;
    float s = 0.f;
    #pragma unroll 8
    for (int t = 0; t < CL; ++t)
        s = BETA * s + OMB * xp[(size_t)t * DD];
    carryA[idx] = s;
}

__global__ void ema_carry_kernel(const float* __restrict__ carryA, float* __restrict__ carryB) {
    int idx = blockIdx.x * blockDim.x + threadIdx.x;
    if (idx >= BB * DD) return;
    int c = idx % DD;
    int b = idx / DD;
    float cin = 0.f;
    #pragma unroll
    for (int j = 0; j < NC; ++j) {
        size_t off = ((size_t)b * NC + j) * DD + c;
        carryB[off] = cin;
        cin = BETA_L * cin + carryA[off];
    }
}

__global__ void ema_final_kernel(const float* __restrict__ x, const float* __restrict__ carryB,
                                 float* __restrict__ l2) {
    int idx = blockIdx.x * blockDim.x + threadIdx.x;
    if (idx >= BB * NC * DD) return;
    int c = idx % DD;
    int bc = idx / DD;
    int chunk = bc % NC;
    int b = bc / NC;
    size_t base = (size_t)b * TT * DD + (size_t)chunk * CL * DD + c;
    const float* xp = x + base;
    float* op = l2 + base;
    float s = carryB[idx];
    #pragma unroll 8
    for (int t = 0; t < CL; ++t) {
        s = BETA * s + OMB * xp[(size_t)t * DD];
        op[(size_t)t * DD] = s;
    }
}

__global__ void router_kernel(const float* __restrict__ hdn,
                              const float* __restrict__ rw2,
                              const float* __restrict__ rb2,
                              float* __restrict__ lam) {
    int row  = blockIdx.x * (blockDim.x / 32) + (threadIdx.x / 32);
    int lane = threadIdx.x & 31;
    if (row >= BB * TT) return;
    const float* hp = hdn + (size_t)row * DHALF;
    float a0 = 0.f, a1 = 0.f, a2 = 0.f;
    for (int i = lane; i < DHALF; i += 32) {
        float h = hp[i];
        a0 += h * rw2[0 * DHALF + i];
        a1 += h * rw2[1 * DHALF + i];
        a2 += h * rw2[2 * DHALF + i];
    }
    #pragma unroll
    for (int o = 16; o > 0; o >>= 1) {
        a0 += __shfl_xor_sync(0xffffffffu, a0, o);
        a1 += __shfl_xor_sync(0xffffffffu, a1, o);
        a2 += __shfl_xor_sync(0xffffffffu, a2, o);
    }
    if (lane == 0) {
        float z0 = a0 + rb2[0], z1 = a1 + rb2[1], z2 = a2 + rb2[2];
        float m = fmaxf(z0, fmaxf(z1, z2));
        float e0 = expf(z0 - m), e1 = expf(z1 - m), e2 = expf(z2 - m);
        float inv = 1.0f / (e0 + e1 + e2);
        lam[(size_t)row * 3 + 0] = e0 * inv;
        lam[(size_t)row * 3 + 1] = e1 * inv;
        lam[(size_t)row * 3 + 2] = e2 * inv;
    }
}

__global__ void fuse_split_kernel(const float* __restrict__ x,
                                  const float* __restrict__ l2,
                                  const float* __restrict__ l3,
                                  const float* __restrict__ lam,
                                  __nv_bfloat16* __restrict__ fhi,
                                  __nv_bfloat16* __restrict__ flo) {
    size_t i = (size_t)blockIdx.x * blockDim.x + threadIdx.x;
    if (i >= (size_t)BB * TT * DD) return;
    int c = (int)(i % DD);
    size_t row = i / DD;
    int b = (int)(row / TT);
    float a0 = lam[row * 3 + 0];
    float a1 = lam[row * 3 + 1];
    float a2 = lam[row * 3 + 2];
    float f = a0 * x[i] + a1 * l2[i] + a2 * l3[(size_t)b * DD + c];
    split2(f, &fhi[i], &flo[i]);
}

// ---------------- pipelined split-bf16 tensor-core GEMM ----------------
// __launch_bounds__(256, 2): force <=128 regs so 2 CTAs fit per SM
// (single-wave grid + cross-CTA latency hiding during cp.async waits).
#define GEMM_SMEM (2 * 2 * BM * 40 * 2 * 2)

template<int MODE>
__global__ void __launch_bounds__(256, 2) mma_gemm(
    const __nv_bfloat16* __restrict__ Ahi, const __nv_bfloat16* __restrict__ Alo,
    const __nv_bfloat16* __restrict__ Bhi, const __nv_bfloat16* __restrict__ Blo,
    const float* __restrict__ bias,
    float* __restrict__ Cf,
    __nv_bfloat16* __restrict__ Chi, __nv_bfloat16* __restrict__ Clo,
    int M, int N, int K, int lda, int ldb)
{
    extern __shared__ __align__(16) char dynsmem[];
    __nv_bfloat16* sA = reinterpret_cast<__nv_bfloat16*>(dynsmem);
    __nv_bfloat16* sB = sA + 2 * 2 * BM * 40;

    int tid = threadIdx.x;
    int lane = tid & 31;
    int warp = tid >> 5;
    int wm = warp >> 2;
    int wn = warp & 3;
    int row0 = blockIdx.y * BM;
    int col0 = blockIdx.x * BN;

    float acc[4][4][4];
    #pragma unroll
    for (int a = 0; a < 4; ++a)
        #pragma unroll
        for (int b = 0; b < 4; ++b)
            #pragma unroll
            for (int c = 0; c < 4; ++c) acc[a][b][c] = 0.f;

    auto issue = [&](int k0, int st) {
        #pragma unroll
        for (int it = 0; it < 2; ++it) {
            int e = tid + it * 256;
            int r = e >> 2;
            int kc = (e & 3) * 8;
            size_t ao;
            if (MODE == M_OUT) {
                int gm = row0 + r, gk = k0 + kc;
                int b = gm >> 10, t = gm & (TT - 1);
                int h = gk >> 7, c = gk & (DHD - 1);
                ao = (((size_t)b * HH + h) * TT + t) * DHD + c;
            } else {
                ao = (size_t)(row0 + r) * lda + k0 + kc;
            }
            cp16(s2u(&sA[((st * 2 + 0) * BM + r) * 40 + kc]), Ahi + ao);
            cp16(s2u(&sA[((st * 2 + 1) * BM + r) * 40 + kc]), Alo + ao);
            size_t bo = (size_t)(col0 + r) * ldb + k0 + kc;
            cp16(s2u(&sB[((st * 2 + 0) * BM + r) * 40 + kc]), Bhi + bo);
            cp16(s2u(&sB[((st * 2 + 1) * BM + r) * 40 + kc]), Blo + bo);
        }
    };

    int nIter = K / BKS;
    issue(0, 0);
    cp_commit();

    for (int i = 0; i < nIter; ++i) {
        int st = i & 1;
        if (i + 1 < nIter) {
            issue((i + 1) * BKS, (i + 1) & 1);
            cp_commit();
            cp_wait<1>();
        } else {
            cp_wait<0>();
        }
        __syncthreads();

        #pragma unroll
        for (int ks = 0; ks < BKS; ks += 16) {
            uint32_t afr[2][4][4];
            uint32_t bfr[2][4][2];
            #pragma unroll
            for (int mt = 0; mt < 4; ++mt) {
                int r = wm * 64 + mt * 16 + (lane & 15);
                int c = ks + (lane >> 4) * 8;
                ldsm4(afr[0][mt], s2u(&sA[((st * 2 + 0) * BM + r) * 40 + c]));
                ldsm4(afr[1][mt], s2u(&sA[((st * 2 + 1) * BM + r) * 40 + c]));
            }
            #pragma unroll
            for (int nt = 0; nt < 4; ++nt) {
                int r = wn * 32 + nt * 8 + (lane & 7);
                int c = ks + ((lane >> 3) & 1) * 8;
                ldsm2(bfr[0][nt], s2u(&sB[((st * 2 + 0) * BM + r) * 40 + c]));
                ldsm2(bfr[1][nt], s2u(&sB[((st * 2 + 1) * BM + r) * 40 + c]));
            }
            #pragma unroll
            for (int mt = 0; mt < 4; ++mt)
                #pragma unroll
                for (int nt = 0; nt < 4; ++nt) {
                    mma16816(acc[mt][nt], afr[0][mt], bfr[0][nt]);
                    mma16816(acc[mt][nt], afr[0][mt], bfr[1][nt]);
                    mma16816(acc[mt][nt], afr[1][mt], bfr[0][nt]);
                }
        }
        __syncthreads();
    }

    int g = lane >> 2, tg = lane & 3;
    #pragma unroll
    for (int mt = 0; mt < 4; ++mt)
        #pragma unroll
        for (int nt = 0; nt < 4; ++nt)
            #pragma unroll
            for (int i = 0; i < 4; ++i) {
                int m = row0 + wm * 64 + mt * 16 + g + (i >> 1) * 8;
                int n = col0 + wn * 32 + nt * 8 + tg * 2 + (i & 1);
                float v = acc[mt][nt][i];
                if (MODE == M_Q) {
                    size_t idx = (size_t)m * N + n;
                    split2(v, &Chi[idx], &Clo[idx]);
                } else if (MODE == M_HDN) {
                    v += bias[n];
                    Cf[(size_t)m * N + n] = v / (1.f + expf(-v));
                } else if (MODE == M_KV) {
                    int b = m >> 10, t = m & (TT - 1);
                    int h = n >> 7, c = n & (DHD - 1);
                    size_t idx = (((size_t)b * HH + h) * TT + t) * DHD + c;
                    Cf[idx] = v;
                    split2(v, &Chi[idx], &Clo[idx]);
                } else {
                    Cf[(size_t)m * N + n] = v;
                }
            }
}

// ---------------- flash attention ----------------
#define FL_PITCH 136
#define FL_TILE  (128 * FL_PITCH)
#define FLASH_SMEM (6 * FL_TILE * 2)

__global__ void __launch_bounds__(256) flash_kernel(
    const __nv_bfloat16* __restrict__ qh_, const __nv_bfloat16* __restrict__ ql_,
    const __nv_bfloat16* __restrict__ khh, const __nv_bfloat16* __restrict__ khl,
    const __nv_bfloat16* __restrict__ vhh, const __nv_bfloat16* __restrict__ vhl,
    __nv_bfloat16* __restrict__ aoh, __nv_bfloat16* __restrict__ aol,
    float scale)
{
    extern __shared__ __align__(16) char fsm[];
    __nv_bfloat16* sQh = reinterpret_cast<__nv_bfloat16*>(fsm);
    __nv_bfloat16* sQl = sQh + FL_TILE;
    __nv_bfloat16* sKh = sQl + FL_TILE;
    __nv_bfloat16* sKl = sKh + FL_TILE;
    __nv_bfloat16* sVh = sKl + FL_TILE;
    __nv_bfloat16* sVl = sVh + FL_TILE;

    int tid = threadIdx.x;
    int lane = tid & 31;
    int wid = tid >> 5;
    int g = lane >> 2, tg = lane & 3;

    int qb = gridDim.x - 1 - blockIdx.x;
    int z = blockIdx.y;
    int b = z / HH, h = z % HH;
    int row0 = qb * 128;

    const __nv_bfloat16* qbh = qh_ + (size_t)b * TT * DD + (size_t)h * DHD;
    const __nv_bfloat16* qbl = ql_ + (size_t)b * TT * DD + (size_t)h * DHD;
    const __nv_bfloat16* kbh = khh + (size_t)z * TT * DHD;
    const __nv_bfloat16* kbl = khl + (size_t)z * TT * DHD;
    const __nv_bfloat16* vbh = vhh + (size_t)z * TT * DHD;
    const __nv_bfloat16* vbl = vhl + (size_t)z * TT * DHD;

    for (int e = tid; e < 128 * 16; e += 256) {
        int r = e >> 4, c8 = (e & 15) * 8;
        *reinterpret_cast<uint4*>(&sQh[r * FL_PITCH + c8]) =
            *reinterpret_cast<const uint4*>(qbh + (size_t)(row0 + r) * DD + c8);
        *reinterpret_cast<uint4*>(&sQl[r * FL_PITCH + c8]) =
            *reinterpret_cast<const uint4*>(qbl + (size_t)(row0 + r) * DD + c8);
    }

    float accO[16][4];
    #pragma unroll
    for (int i = 0; i < 16; ++i)
        #pragma unroll
        for (int j = 0; j < 4; ++j) accO[i][j] = 0.f;
    float mrun0 = -INFINITY, mrun1 = -INFINITY;
    float lrun0 = 0.f, lrun1 = 0.f;

    for (int kb = 0; kb <= qb; ++kb) {
        __syncthreads();
        for (int e = tid; e < 128 * 16; e += 256) {
            int r = e >> 4, c8 = (e & 15) * 8;
            size_t go = (size_t)(kb * 128 + r) * DHD + c8;
            *reinterpret_cast<uint4*>(&sKh[r * FL_PITCH + c8]) = *reinterpret_cast<const uint4*>(kbh + go);
            *reinterpret_cast<uint4*>(&sKl[r * FL_PITCH + c8]) = *reinterpret_cast<const uint4*>(kbl + go);
            *reinterpret_cast<uint4*>(&sVh[r * FL_PITCH + c8]) = *reinterpret_cast<const uint4*>(vbh + go);
            *reinterpret_cast<uint4*>(&sVl[r * FL_PITCH + c8]) = *reinterpret_cast<const uint4*>(vbl + go);
        }
        __syncthreads();

        float S[16][4];
        #pragma unroll
        for (int i = 0; i < 16; ++i)
            #pragma unroll
            for (int j = 0; j < 4; ++j) S[i][j] = 0.f;

        #pragma unroll
        for (int ks = 0; ks < 8; ++ks) {
            uint32_t qf[2][4];
            {
                int r = wid * 16 + (lane & 15);
                int c = ks * 16 + (lane >> 4) * 8;
                ldsm4(qf[0], s2u(&sQh[r * FL_PITCH + c]));
                ldsm4(qf[1], s2u(&sQl[r * FL_PITCH + c]));
            }
            #pragma unroll
            for (int nt = 0; nt < 16; ++nt) {
                uint32_t bh[2], bl[2];
                int r = nt * 8 + (lane & 7);
                int c = ks * 16 + ((lane >> 3) & 1) * 8;
                ldsm2(bh, s2u(&sKh[r * FL_PITCH + c]));
                ldsm2(bl, s2u(&sKl[r * FL_PITCH + c]));
                mma16816(S[nt], qf[0], bh);
                mma16816(S[nt], qf[0], bl);
                mma16816(S[nt], qf[1], bh);
            }
        }

        bool diag = (kb == qb);
        #pragma unroll
        for (int nt = 0; nt < 16; ++nt)
            #pragma unroll
            for (int j = 0; j < 4; ++j) {
                float v = S[nt][j] * scale;
                if (diag) {
                    int n = nt * 8 + tg * 2 + (j & 1);
                    int m = wid * 16 + g + ((j >> 1) ? 8 : 0);
                    if (n > m) v = -INFINITY;
                }
                S[nt][j] = v;
            }

        float mx0 = -INFINITY, mx1 = -INFINITY;
        #pragma unroll
        for (int nt = 0; nt < 16; ++nt) {
            mx0 = fmaxf(mx0, fmaxf(S[nt][0], S[nt][1]));
            mx1 = fmaxf(mx1, fmaxf(S[nt][2], S[nt][3]));
        }
        mx0 = fmaxf(mx0, __shfl_xor_sync(0xffffffffu, mx0, 1));
        mx0 = fmaxf(mx0, __shfl_xor_sync(0xffffffffu, mx0, 2));
        mx1 = fmaxf(mx1, __shfl_xor_sync(0xffffffffu, mx1, 1));
        mx1 = fmaxf(mx1, __shfl_xor_sync(0xffffffffu, mx1, 2));

        float mn0 = fmaxf(mrun0, mx0);
        float mn1 = fmaxf(mrun1, mx1);
        float al0 = expf(mrun0 - mn0);
        float al1 = expf(mrun1 - mn1);
        mrun0 = mn0; mrun1 = mn1;

        float ls0 = 0.f, ls1 = 0.f;
        #pragma unroll
        for (int nt = 0; nt < 16; ++nt) {
            float e0 = expf(S[nt][0] - mn0);
            float e1 = expf(S[nt][1] - mn0);
            float e2 = expf(S[nt][2] - mn1);
            float e3 = expf(S[nt][3] - mn1);
            S[nt][0] = e0; S[nt][1] = e1; S[nt][2] = e2; S[nt][3] = e3;
            ls0 += e0 + e1;
            ls1 += e2 + e3;
        }
        lrun0 = lrun0 * al0 + ls0;
        lrun1 = lrun1 * al1 + ls1;

        #pragma unroll
        for (int nt = 0; nt < 16; ++nt) {
            accO[nt][0] *= al0; accO[nt][1] *= al0;
            accO[nt][2] *= al1; accO[nt][3] *= al1;
        }

        #pragma unroll
        for (int kk = 0; kk < 8; ++kk) {
            uint32_t ph[4], pl[4];
            {
                float v00 = S[2 * kk][0],     v01 = S[2 * kk][1];
                float v02 = S[2 * kk][2],     v03 = S[2 * kk][3];
                float v10 = S[2 * kk + 1][0], v11 = S[2 * kk + 1][1];
                float v12 = S[2 * kk + 1][2], v13 = S[2 * kk + 1][3];
                float h00 = __bfloat162float(__float2bfloat16(v00));
                float h01 = __bfloat162float(__float2bfloat16(v01));
                float h02 = __bfloat162float(__float2bfloat16(v02));
                float h03 = __bfloat162float(__float2bfloat16(v03));
                float h10 = __bfloat162float(__float2bfloat16(v10));
                float h11 = __bfloat162float(__float2bfloat16(v11));
                float h12 = __bfloat162float(__float2bfloat16(v12));
                float h13 = __bfloat162float(__float2bfloat16(v13));
                ph[0] = packb2(h00, h01); ph[1] = packb2(h02, h03);
                ph[2] = packb2(h10, h11); ph[3] = packb2(h12, h13);
                pl[0] = packb2(v00 - h00, v01 - h01); pl[1] = packb2(v02 - h02, v03 - h03);
                pl[2] = packb2(v10 - h10, v11 - h11); pl[3] = packb2(v12 - h12, v13 - h13);
            }
            #pragma unroll
            for (int ndt = 0; ndt < 16; ++ndt) {
                uint32_t vh2[2], vl2[2];
                int rr = kk * 16 + (lane & 15);
                int cc = ndt * 8;
                ldsm2t(vh2, s2u(&sVh[rr * FL_PITCH + cc]));
                ldsm2t(vl2, s2u(&sVl[rr * FL_PITCH + cc]));
                mma16816(accO[ndt], ph, vh2);
                mma16816(accO[ndt], ph, vl2);
                mma16816(accO[ndt], pl, vh2);
            }
        }
    }

    lrun0 += __shfl_xor_sync(0xffffffffu, lrun0, 1);
    lrun0 += __shfl_xor_sync(0xffffffffu, lrun0, 2);
    lrun1 += __shfl_xor_sync(0xffffffffu, lrun1, 1);
    lrun1 += __shfl_xor_sync(0xffffffffu, lrun1, 2);
    float inv0 = 1.0f / lrun0;
    float inv1 = 1.0f / lrun1;

    size_t obase = (size_t)z * TT * DHD;
    #pragma unroll
    for (int ndt = 0; ndt < 16; ++ndt)
        #pragma unroll
        for (int j = 0; j < 4; ++j) {
            int m = row0 + wid * 16 + g + ((j >> 1) ? 8 : 0);
            int n = ndt * 8 + tg * 2 + (j & 1);
            float v = accO[ndt][j] * ((j >> 1) ? inv1 : inv0);
            size_t idx = obase + (size_t)m * DHD + n;
            split2(v, &aoh[idx], &aol[idx]);
        }
}

// ---------------- host ----------------
#define SYMADDR(var, sym) cudaGetSymbolAddress((void**)&var, sym)

extern "C" void kernel_launch(void* const* d_in, const int* in_sizes, int n_in,
                              void* d_out, int out_size) {
    const float* x   = (const float*)d_in[0];
    const float* l3  = (const float*)d_in[1];
    const float* wq  = (const float*)d_in[2];
    const float* wk  = (const float*)d_in[3];
    const float* wv  = (const float*)d_in[4];
    const float* wo  = (const float*)d_in[5];
    const float* rw1 = (const float*)d_in[6];
    const float* rb1 = (const float*)d_in[7];
    const float* rw2 = (const float*)d_in[8];
    const float* rb2 = (const float*)d_in[9];

    float* out     = (float*)d_out;
    float* kh_out  = out    + (size_t)BB * TT * DD;
    float* vh_out  = kh_out + (size_t)BB * TT * DD;
    float* lam_out = vh_out + (size_t)BB * TT * DD;

    float *l2, *hdn, *carryA, *carryB;
    SYMADDR(l2, g_l2); SYMADDR(hdn, g_hdn);
    SYMADDR(carryA, g_carryA); SYMADDR(carryB, g_carryB);

    __nv_bfloat16 *xs_h,*xs_l, *wqs_h,*wqs_l, *wks_h,*wks_l, *wvs_h,*wvs_l,
                  *wos_h,*wos_l, *rw1s_h,*rw1s_l, *qs_h,*qs_l, *fs_h,*fs_l,
                  *khs_h,*khs_l, *vhs_h,*vhs_l, *aos_h,*aos_l;
    SYMADDR(xs_h, g_xs_h);     SYMADDR(xs_l, g_xs_l);
    SYMADDR(wqs_h, g_wqs_h);   SYMADDR(wqs_l, g_wqs_l);
    SYMADDR(wks_h, g_wks_h);   SYMADDR(wks_l, g_wks_l);
    SYMADDR(wvs_h, g_wvs_h);   SYMADDR(wvs_l, g_wvs_l);
    SYMADDR(wos_h, g_wos_h);   SYMADDR(wos_l, g_wos_l);
    SYMADDR(rw1s_h, g_rw1s_h); SYMADDR(rw1s_l, g_rw1s_l);
    SYMADDR(qs_h, g_qs_h);     SYMADDR(qs_l, g_qs_l);
    SYMADDR(fs_h, g_fs_h);     SYMADDR(fs_l, g_fs_l);
    SYMADDR(khs_h, g_khs_h);   SYMADDR(khs_l, g_khs_l);
    SYMADDR(vhs_h, g_vhs_h);   SYMADDR(vhs_l, g_vhs_l);
    SYMADDR(aos_h, g_aos_h);   SYMADDR(aos_l, g_aos_l);

    const int M = BB * TT;
    const float scale = 1.0f / sqrtf((float)DHD);
    const size_t ND = (size_t)BB * TT * DD;
    const size_t NW = (size_t)DD * DD;

    cudaFuncSetAttribute(mma_gemm<M_Q>,   cudaFuncAttributeMaxDynamicSharedMemorySize, GEMM_SMEM);
    cudaFuncSetAttribute(mma_gemm<M_HDN>, cudaFuncAttributeMaxDynamicSharedMemorySize, GEMM_SMEM);
    cudaFuncSetAttribute(mma_gemm<M_KV>,  cudaFuncAttributeMaxDynamicSharedMemorySize, GEMM_SMEM);
    cudaFuncSetAttribute(mma_gemm<M_OUT>, cudaFuncAttributeMaxDynamicSharedMemorySize, GEMM_SMEM);
    cudaFuncSetAttribute(flash_kernel,    cudaFuncAttributeMaxDynamicSharedMemorySize, FLASH_SMEM);

    // splits
    split_kernel<<<(unsigned)((ND + 255) / 256), 256>>>(x, xs_h, xs_l, ND);
    split4_kernel<<<(unsigned)((NW + 255) / 256), 256>>>(
        wq, wk, wv, wo, wqs_h, wqs_l, wks_h, wks_l, wvs_h, wvs_l, wos_h, wos_l, NW);
    split_kernel<<<(unsigned)((NW / 2 + 255) / 256), 256>>>(rw1, rw1s_h, rw1s_l, NW / 2);

    // chunk-parallel EMA
    ema_chunk_kernel<<<(BB * NC * DD + 255) / 256, 256>>>(x, carryA);
    ema_carry_kernel<<<(BB * DD + 255) / 256, 256>>>(carryA, carryB);
    ema_final_kernel<<<(BB * NC * DD + 255) / 256, 256>>>(x, carryB, l2);

    // q = x @ wq^T
    mma_gemm<M_Q><<<dim3(DD / BN, M / BM), 256, GEMM_SMEM>>>(
        xs_h, xs_l, wqs_h, wqs_l, nullptr, nullptr, qs_h, qs_l, M, DD, DD, DD, DD);

    // hdn = silu(q @ rw1^T + rb1)
    mma_gemm<M_HDN><<<dim3(DHALF / BN, M / BM), 256, GEMM_SMEM>>>(
        qs_h, qs_l, rw1s_h, rw1s_l, rb1, hdn, nullptr, nullptr, M, DHALF, DD, DD, DD);

    // lam
    router_kernel<<<(M + 7) / 8, 256>>>(hdn, rw2, rb2, lam_out);

    // fused
    fuse_split_kernel<<<(unsigned)((ND + 255) / 256), 256>>>(x, l2, l3, lam_out, fs_h, fs_l);

    // kh / vh
    mma_gemm<M_KV><<<dim3(DD / BN, M / BM), 256, GEMM_SMEM>>>(
        fs_h, fs_l, wks_h, wks_l, nullptr, kh_out, khs_h, khs_l, M, DD, DD, DD, DD);
    mma_gemm<M_KV><<<dim3(DD / BN, M / BM), 256, GEMM_SMEM>>>(
        fs_h, fs_l, wvs_h, wvs_l, nullptr, vh_out, vhs_h, vhs_l, M, DD, DD, DD, DD);

    // flash attention -> ao (split)
    flash_kernel<<<dim3(TT / 128, BB * HH), 256, FLASH_SMEM>>>(
        qs_h, qs_l, khs_h, khs_l, vhs_h, vhs_l, aos_h, aos_l, scale);

    // out = concat_heads(ao) @ wo^T
    mma_gemm<M_OUT><<<dim3(DD / BN, M / BM), 256, GEMM_SMEM>>>(
        aos_h, aos_l, wos_h, wos_l, nullptr, out, nullptr, nullptr, M, DD, DD, DD, DD);
}

// round 8
// speedup vs baseline: 2.6435x; 1.0376x over previous
#include <cuda_runtime.h>
#include <cuda_bf16.h>
#include <math.h>
#include <stdint.h>

#define BB 2
#define TT 1024
#define DD 2048
#define HH 16
#define DHD 128
#define DHALF 1024

#define BM 128
#define BN 128
#define BKS 32

// EMA chunking: 64 chunks of 16 steps
#define NC 64
#define CL 16
#define BETA 0.9f
#define OMB  0.1f
#define BETA_L 0.1853020188851841f   // 0.9^16

// GEMM modes
#define M_Q 0
#define M_HDN 1
#define M_KV 2
#define M_OUT 3

// ---------------- device scratch ----------------
__device__ float g_hdn[(size_t)BB*TT*DHALF];
__device__ float g_carryA[(size_t)BB*NC*DD];
__device__ float g_carryB[(size_t)BB*NC*DD];

#define DECL_SPLIT(name, count) \
    __device__ __nv_bfloat16 name##_h[count]; \
    __device__ __nv_bfloat16 name##_l[count];

DECL_SPLIT(g_xs,   (size_t)BB*TT*DD)
DECL_SPLIT(g_wqs,  (size_t)DD*DD)
DECL_SPLIT(g_wks,  (size_t)DD*DD)
DECL_SPLIT(g_wvs,  (size_t)DD*DD)
DECL_SPLIT(g_wos,  (size_t)DD*DD)
DECL_SPLIT(g_rw1s, (size_t)DHALF*DD)
DECL_SPLIT(g_qs,   (size_t)BB*TT*DD)
DECL_SPLIT(g_fs,   (size_t)BB*TT*DD)
DECL_SPLIT(g_khs,  (size_t)BB*TT*DD)
DECL_SPLIT(g_vhs,  (size_t)BB*TT*DD)
DECL_SPLIT(g_aos,  (size_t)BB*TT*DD)

// ---------------- helpers ----------------
__device__ __forceinline__ void split2(float v, __nv_bfloat16* hi, __nv_bfloat16* lo) {
    __nv_bfloat16 h = __float2bfloat16(v);
    *hi = h;
    *lo = __float2bfloat16(v - __bfloat162float(h));
}
__device__ __forceinline__ uint32_t s2u(const void* p) {
    return (uint32_t)__cvta_generic_to_shared(p);
}
__device__ __forceinline__ void ldsm4(uint32_t* r, uint32_t addr) {
    asm volatile("ldmatrix.sync.aligned.m8n8.x4.shared.b16 {%0,%1,%2,%3}, [%4];"
                 : "=r"(r[0]), "=r"(r[1]), "=r"(r[2]), "=r"(r[3]) : "r"(addr));
}
__device__ __forceinline__ void ldsm2(uint32_t* r, uint32_t addr) {
    asm volatile("ldmatrix.sync.aligned.m8n8.x2.shared.b16 {%0,%1}, [%2];"
                 : "=r"(r[0]), "=r"(r[1]) : "r"(addr));
}
__device__ __forceinline__ void ldsm2t(uint32_t* r, uint32_t addr) {
    asm volatile("ldmatrix.sync.aligned.m8n8.x2.trans.shared.b16 {%0,%1}, [%2];"
                 : "=r"(r[0]), "=r"(r[1]) : "r"(addr));
}
__device__ __forceinline__ void mma16816(float* c, const uint32_t* a, const uint32_t* b) {
    asm volatile("mma.sync.aligned.m16n8k16.row.col.f32.bf16.bf16.f32 "
                 "{%0,%1,%2,%3}, {%4,%5,%6,%7}, {%8,%9}, {%0,%1,%2,%3};"
                 : "+f"(c[0]), "+f"(c[1]), "+f"(c[2]), "+f"(c[3])
                 : "r"(a[0]), "r"(a[1]), "r"(a[2]), "r"(a[3]), "r"(b[0]), "r"(b[1]));
}
__device__ __forceinline__ void cp16(uint32_t saddr, const void* g) {
    asm volatile("cp.async.cg.shared.global [%0], [%1], 16;" :: "r"(saddr), "l"(g));
}
__device__ __forceinline__ void cp_commit() {
    asm volatile("cp.async.commit_group;");
}
template<int N> __device__ __forceinline__ void cp_wait() {
    asm volatile("cp.async.wait_group %0;" :: "n"(N));
}
__device__ __forceinline__ uint32_t packb2(float lo_k, float hi_k) {
    __nv_bfloat162 t = __floats2bfloat162_rn(lo_k, hi_k);   // .x = low half
    return *reinterpret_cast<uint32_t*>(&t);
}

// split float4 -> hi uint2 (4 bf16) + lo uint2
__device__ __forceinline__ void split4v(float4 v, uint2* hi, uint2* lo) {
    __nv_bfloat16 h0 = __float2bfloat16(v.x);
    __nv_bfloat16 h1 = __float2bfloat16(v.y);
    __nv_bfloat16 h2 = __float2bfloat16(v.z);
    __nv_bfloat16 h3 = __float2bfloat16(v.w);
    float r0 = v.x - __bfloat162float(h0);
    float r1 = v.y - __bfloat162float(h1);
    float r2 = v.z - __bfloat162float(h2);
    float r3 = v.w - __bfloat162float(h3);
    __nv_bfloat162 p01; p01.x = h0; p01.y = h1;
    __nv_bfloat162 p23; p23.x = h2; p23.y = h3;
    hi->x = *reinterpret_cast<uint32_t*>(&p01);
    hi->y = *reinterpret_cast<uint32_t*>(&p23);
    lo->x = packb2(r0, r1);
    lo->y = packb2(r2, r3);
}

// ---------------- elementwise kernels (vectorized x4) ----------------
__global__ void split_v4_kernel(const float4* __restrict__ s,
                                uint2* __restrict__ hi, uint2* __restrict__ lo, int n4) {
    int i = blockIdx.x * blockDim.x + threadIdx.x;
    if (i >= n4) return;
    uint2 h, l;
    split4v(s[i], &h, &l);
    hi[i] = h; lo[i] = l;
}

__global__ void split4_v4_kernel(const float4* __restrict__ a, const float4* __restrict__ b,
                                 const float4* __restrict__ c, const float4* __restrict__ d,
                                 uint2* __restrict__ ah, uint2* __restrict__ al,
                                 uint2* __restrict__ bh, uint2* __restrict__ bl,
                                 uint2* __restrict__ ch, uint2* __restrict__ cl,
                                 uint2* __restrict__ dh, uint2* __restrict__ dl, int n4) {
    int i = blockIdx.x * blockDim.x + threadIdx.x;
    if (i >= n4) return;
    uint2 h, l;
    split4v(a[i], &h, &l); ah[i] = h; al[i] = l;
    split4v(b[i], &h, &l); bh[i] = h; bl[i] = l;
    split4v(c[i], &h, &l); ch[i] = h; cl[i] = l;
    split4v(d[i], &h, &l); dh[i] = h; dl[i] = l;
}

// ---- chunk-parallel EMA (NC=64 chunks of CL=16), float4-vectorized ----
#define D4 (DD / 4)

__global__ void ema_chunk_v4(const float4* __restrict__ x4, float4* __restrict__ carryA4) {
    int idx = blockIdx.x * blockDim.x + threadIdx.x;     // (b*NC + chunk)*D4 + c4
    if (idx >= BB * NC * D4) return;
    int c4 = idx % D4;
    int bc = idx / D4;
    int chunk = bc % NC;
    int b = bc / NC;
    const float4* xp = x4 + ((size_t)b * TT + (size_t)chunk * CL) * D4 + c4;
    float4 s = make_float4(0.f, 0.f, 0.f, 0.f);
    #pragma unroll
    for (int t = 0; t < CL; ++t) {
        float4 v = xp[(size_t)t * D4];
        s.x = BETA * s.x + OMB * v.x;
        s.y = BETA * s.y + OMB * v.y;
        s.z = BETA * s.z + OMB * v.z;
        s.w = BETA * s.w + OMB * v.w;
    }
    carryA4[idx] = s;
}

__global__ void ema_carry_v4(const float4* __restrict__ carryA4, float4* __restrict__ carryB4) {
    int idx = blockIdx.x * blockDim.x + threadIdx.x;     // b*D4 + c4
    if (idx >= BB * D4) return;
    int c4 = idx % D4;
    int b = idx / D4;
    float4 cin = make_float4(0.f, 0.f, 0.f, 0.f);
    #pragma unroll
    for (int j = 0; j < NC; ++j) {
        size_t off = ((size_t)b * NC + j) * D4 + c4;
        carryB4[off] = cin;
        float4 a = carryA4[off];
        cin.x = BETA_L * cin.x + a.x;
        cin.y = BETA_L * cin.y + a.y;
        cin.z = BETA_L * cin.z + a.z;
        cin.w = BETA_L * cin.w + a.w;
    }
}

// rescan + fuse + split, all in one pass (no l2 materialization)
__global__ void ema_fuse_v4(const float4* __restrict__ x4, const float4* __restrict__ carryB4,
                            const float4* __restrict__ l34, const float* __restrict__ lam,
                            uint2* __restrict__ fh4, uint2* __restrict__ fl4) {
    int idx = blockIdx.x * blockDim.x + threadIdx.x;
    if (idx >= BB * NC * D4) return;
    int c4 = idx % D4;
    int bc = idx / D4;
    int chunk = bc % NC;
    int b = bc / NC;
    size_t base = ((size_t)b * TT + (size_t)chunk * CL) * D4 + c4;
    float4 s = carryB4[idx];
    float4 m = l34[(size_t)b * D4 + c4];
    int row0 = b * TT + chunk * CL;
    #pragma unroll
    for (int t = 0; t < CL; ++t) {
        float4 v = x4[base + (size_t)t * D4];
        s.x = BETA * s.x + OMB * v.x;
        s.y = BETA * s.y + OMB * v.y;
        s.z = BETA * s.z + OMB * v.z;
        s.w = BETA * s.w + OMB * v.w;
        int row = row0 + t;
        float a0 = lam[(size_t)row * 3 + 0];
        float a1 = lam[(size_t)row * 3 + 1];
        float a2 = lam[(size_t)row * 3 + 2];
        float4 f;
        f.x = a0 * v.x + a1 * s.x + a2 * m.x;
        f.y = a0 * v.y + a1 * s.y + a2 * m.y;
        f.z = a0 * v.z + a1 * s.z + a2 * m.z;
        f.w = a0 * v.w + a1 * s.w + a2 * m.w;
        uint2 h, l;
        split4v(f, &h, &l);
        fh4[base + (size_t)t * D4] = h;
        fl4[base + (size_t)t * D4] = l;
    }
}

__global__ void router_kernel(const float* __restrict__ hdn,
                              const float* __restrict__ rw2,
                              const float* __restrict__ rb2,
                              float* __restrict__ lam) {
    int row  = blockIdx.x * (blockDim.x / 32) + (threadIdx.x / 32);
    int lane = threadIdx.x & 31;
    if (row >= BB * TT) return;
    const float* hp = hdn + (size_t)row * DHALF;
    float a0 = 0.f, a1 = 0.f, a2 = 0.f;
    for (int i = lane; i < DHALF; i += 32) {
        float h = hp[i];
        a0 += h * rw2[0 * DHALF + i];
        a1 += h * rw2[1 * DHALF + i];
        a2 += h * rw2[2 * DHALF + i];
    }
    #pragma unroll
    for (int o = 16; o > 0; o >>= 1) {
        a0 += __shfl_xor_sync(0xffffffffu, a0, o);
        a1 += __shfl_xor_sync(0xffffffffu, a1, o);
        a2 += __shfl_xor_sync(0xffffffffu, a2, o);
    }
    if (lane == 0) {
        float z0 = a0 + rb2[0], z1 = a1 + rb2[1], z2 = a2 + rb2[2];
        float m = fmaxf(z0, fmaxf(z1, z2));
        float e0 = expf(z0 - m), e1 = expf(z1 - m), e2 = expf(z2 - m);
        float inv = 1.0f / (e0 + e1 + e2);
        lam[(size_t)row * 3 + 0] = e0 * inv;
        lam[(size_t)row * 3 + 1] = e1 * inv;
        lam[(size_t)row * 3 + 2] = e2 * inv;
    }
}

// ---------------- pipelined split-bf16 tensor-core GEMM ----------------
#define GEMM_SMEM (2 * 2 * BM * 40 * 2 * 2)

template<int MODE>
__global__ void __launch_bounds__(256, 2) mma_gemm(
    const __nv_bfloat16* __restrict__ Ahi, const __nv_bfloat16* __restrict__ Alo,
    const __nv_bfloat16* __restrict__ Bhi, const __nv_bfloat16* __restrict__ Blo,
    const float* __restrict__ bias,
    float* __restrict__ Cf,
    __nv_bfloat16* __restrict__ Chi, __nv_bfloat16* __restrict__ Clo,
    int M, int N, int K, int lda, int ldb)
{
    extern __shared__ __align__(16) char dynsmem[];
    __nv_bfloat16* sA = reinterpret_cast<__nv_bfloat16*>(dynsmem);
    __nv_bfloat16* sB = sA + 2 * 2 * BM * 40;

    int tid = threadIdx.x;
    int lane = tid & 31;
    int warp = tid >> 5;
    int wm = warp >> 2;
    int wn = warp & 3;
    int row0 = blockIdx.y * BM;
    int col0 = blockIdx.x * BN;

    float acc[4][4][4];
    #pragma unroll
    for (int a = 0; a < 4; ++a)
        #pragma unroll
        for (int b = 0; b < 4; ++b)
            #pragma unroll
            for (int c = 0; c < 4; ++c) acc[a][b][c] = 0.f;

    auto issue = [&](int k0, int st) {
        #pragma unroll
        for (int it = 0; it < 2; ++it) {
            int e = tid + it * 256;
            int r = e >> 2;
            int kc = (e & 3) * 8;
            size_t ao;
            if (MODE == M_OUT) {
                int gm = row0 + r, gk = k0 + kc;
                int b = gm >> 10, t = gm & (TT - 1);
                int h = gk >> 7, c = gk & (DHD - 1);
                ao = (((size_t)b * HH + h) * TT + t) * DHD + c;
            } else {
                ao = (size_t)(row0 + r) * lda + k0 + kc;
            }
            cp16(s2u(&sA[((st * 2 + 0) * BM + r) * 40 + kc]), Ahi + ao);
            cp16(s2u(&sA[((st * 2 + 1) * BM + r) * 40 + kc]), Alo + ao);
            size_t bo = (size_t)(col0 + r) * ldb + k0 + kc;
            cp16(s2u(&sB[((st * 2 + 0) * BM + r) * 40 + kc]), Bhi + bo);
            cp16(s2u(&sB[((st * 2 + 1) * BM + r) * 40 + kc]), Blo + bo);
        }
    };

    int nIter = K / BKS;
    issue(0, 0);
    cp_commit();

    for (int i = 0; i < nIter; ++i) {
        int st = i & 1;
        if (i + 1 < nIter) {
            issue((i + 1) * BKS, (i + 1) & 1);
            cp_commit();
            cp_wait<1>();
        } else {
            cp_wait<0>();
        }
        __syncthreads();

        #pragma unroll
        for (int ks = 0; ks < BKS; ks += 16) {
            uint32_t afr[2][4][4];
            uint32_t bfr[2][4][2];
            #pragma unroll
            for (int mt = 0; mt < 4; ++mt) {
                int r = wm * 64 + mt * 16 + (lane & 15);
                int c = ks + (lane >> 4) * 8;
                ldsm4(afr[0][mt], s2u(&sA[((st * 2 + 0) * BM + r) * 40 + c]));
                ldsm4(afr[1][mt], s2u(&sA[((st * 2 + 1) * BM + r) * 40 + c]));
            }
            #pragma unroll
            for (int nt = 0; nt < 4; ++nt) {
                int r = wn * 32 + nt * 8 + (lane & 7);
                int c = ks + ((lane >> 3) & 1) * 8;
                ldsm2(bfr[0][nt], s2u(&sB[((st * 2 + 0) * BM + r) * 40 + c]));
                ldsm2(bfr[1][nt], s2u(&sB[((st * 2 + 1) * BM + r) * 40 + c]));
            }
            #pragma unroll
            for (int mt = 0; mt < 4; ++mt)
                #pragma unroll
                for (int nt = 0; nt < 4; ++nt) {
                    mma16816(acc[mt][nt], afr[0][mt], bfr[0][nt]);
                    mma16816(acc[mt][nt], afr[0][mt], bfr[1][nt]);
                    mma16816(acc[mt][nt], afr[1][mt], bfr[0][nt]);
                }
        }
        __syncthreads();
    }

    int g = lane >> 2, tg = lane & 3;
    #pragma unroll
    for (int mt = 0; mt < 4; ++mt)
        #pragma unroll
        for (int nt = 0; nt < 4; ++nt)
            #pragma unroll
            for (int i = 0; i < 4; ++i) {
                int m = row0 + wm * 64 + mt * 16 + g + (i >> 1) * 8;
                int n = col0 + wn * 32 + nt * 8 + tg * 2 + (i & 1);
                float v = acc[mt][nt][i];
                if (MODE == M_Q) {
                    size_t idx = (size_t)m * N + n;
                    split2(v, &Chi[idx], &Clo[idx]);
                } else if (MODE == M_HDN) {
                    v += bias[n];
                    Cf[(size_t)m * N + n] = v / (1.f + expf(-v));
                } else if (MODE == M_KV) {
                    int b = m >> 10, t = m & (TT - 1);
                    int h = n >> 7, c = n & (DHD - 1);
                    size_t idx = (((size_t)b * HH + h) * TT + t) * DHD + c;
                    Cf[idx] = v;
                    split2(v, &Chi[idx], &Clo[idx]);
                } else {
                    Cf[(size_t)m * N + n] = v;
                }
            }
}

// ---------------- flash attention with cp.async K/V pipelining ----------------
#define FL_PITCH 136
#define FL_TILE  (128 * FL_PITCH)
#define FLASH_SMEM (6 * FL_TILE * 2)

__global__ void __launch_bounds__(256) flash_kernel(
    const __nv_bfloat16* __restrict__ qh_, const __nv_bfloat16* __restrict__ ql_,
    const __nv_bfloat16* __restrict__ khh, const __nv_bfloat16* __restrict__ khl,
    const __nv_bfloat16* __restrict__ vhh, const __nv_bfloat16* __restrict__ vhl,
    __nv_bfloat16* __restrict__ aoh, __nv_bfloat16* __restrict__ aol,
    float scale)
{
    extern __shared__ __align__(16) char fsm[];
    __nv_bfloat16* sQh = reinterpret_cast<__nv_bfloat16*>(fsm);
    __nv_bfloat16* sQl = sQh + FL_TILE;
    __nv_bfloat16* sKh = sQl + FL_TILE;
    __nv_bfloat16* sKl = sKh + FL_TILE;
    __nv_bfloat16* sVh = sKl + FL_TILE;
    __nv_bfloat16* sVl = sVh + FL_TILE;

    int tid = threadIdx.x;
    int lane = tid & 31;
    int wid = tid >> 5;
    int g = lane >> 2, tg = lane & 3;

    int qb = gridDim.x - 1 - blockIdx.x;   // heavy blocks first
    int z = blockIdx.y;
    int b = z / HH, h = z % HH;
    int row0 = qb * 128;

    const __nv_bfloat16* qbh = qh_ + (size_t)b * TT * DD + (size_t)h * DHD;
    const __nv_bfloat16* qbl = ql_ + (size_t)b * TT * DD + (size_t)h * DHD;
    const __nv_bfloat16* kbh = khh + (size_t)z * TT * DHD;
    const __nv_bfloat16* kbl = khl + (size_t)z * TT * DHD;
    const __nv_bfloat16* vbh = vhh + (size_t)z * TT * DHD;
    const __nv_bfloat16* vbl = vhl + (size_t)z * TT * DHD;

    auto loadK = [&](int kb2) {
        for (int e = tid; e < 128 * 16; e += 256) {
            int r = e >> 4, c8 = (e & 15) * 8;
            size_t go = (size_t)(kb2 * 128 + r) * DHD + c8;
            cp16(s2u(&sKh[r * FL_PITCH + c8]), kbh + go);
            cp16(s2u(&sKl[r * FL_PITCH + c8]), kbl + go);
        }
    };
    auto loadV = [&](int kb2) {
        for (int e = tid; e < 128 * 16; e += 256) {
            int r = e >> 4, c8 = (e & 15) * 8;
            size_t go = (size_t)(kb2 * 128 + r) * DHD + c8;
            cp16(s2u(&sVh[r * FL_PITCH + c8]), vbh + go);
            cp16(s2u(&sVl[r * FL_PITCH + c8]), vbl + go);
        }
    };

    // stage Q tile (regular stores; visible after first __syncthreads)
    for (int e = tid; e < 128 * 16; e += 256) {
        int r = e >> 4, c8 = (e & 15) * 8;
        *reinterpret_cast<uint4*>(&sQh[r * FL_PITCH + c8]) =
            *reinterpret_cast<const uint4*>(qbh + (size_t)(row0 + r) * DD + c8);
        *reinterpret_cast<uint4*>(&sQl[r * FL_PITCH + c8]) =
            *reinterpret_cast<const uint4*>(qbl + (size_t)(row0 + r) * DD + c8);
    }
    loadK(0); cp_commit();
    loadV(0); cp_commit();

    float accO[16][4];
    #pragma unroll
    for (int i = 0; i < 16; ++i)
        #pragma unroll
        for (int j = 0; j < 4; ++j) accO[i][j] = 0.f;
    float mrun0 = -INFINITY, mrun1 = -INFINITY;
    float lrun0 = 0.f, lrun1 = 0.f;

    for (int kb = 0; kb <= qb; ++kb) {
        // wait for K(kb): outstanding = [K(kb), V(kb)]
        cp_wait<1>();
        __syncthreads();

        // ---- S = Q K^T ----
        float S[16][4];
        #pragma unroll
        for (int i = 0; i < 16; ++i)
            #pragma unroll
            for (int j = 0; j < 4; ++j) S[i][j] = 0.f;

        #pragma unroll
        for (int ks = 0; ks < 8; ++ks) {
            uint32_t qf[2][4];
            {
                int r = wid * 16 + (lane & 15);
                int c = ks * 16 + (lane >> 4) * 8;
                ldsm4(qf[0], s2u(&sQh[r * FL_PITCH + c]));
                ldsm4(qf[1], s2u(&sQl[r * FL_PITCH + c]));
            }
            #pragma unroll
            for (int nt = 0; nt < 16; ++nt) {
                uint32_t bh[2], bl[2];
                int r = nt * 8 + (lane & 7);
                int c = ks * 16 + ((lane >> 3) & 1) * 8;
                ldsm2(bh, s2u(&sKh[r * FL_PITCH + c]));
                ldsm2(bl, s2u(&sKl[r * FL_PITCH + c]));
                mma16816(S[nt], qf[0], bh);
                mma16816(S[nt], qf[0], bl);
                mma16816(S[nt], qf[1], bh);
            }
        }
        __syncthreads();                       // done reading K tile
        if (kb < qb) { loadK(kb + 1); cp_commit(); }   // K(kb+1) flies over softmax+PV

        // ---- scale + mask + online softmax (registers only) ----
        bool diag = (kb == qb);
        #pragma unroll
        for (int nt = 0; nt < 16; ++nt)
            #pragma unroll
            for (int j = 0; j < 4; ++j) {
                float v = S[nt][j] * scale;
                if (diag) {
                    int n = nt * 8 + tg * 2 + (j & 1);
                    int m = wid * 16 + g + ((j >> 1) ? 8 : 0);
                    if (n > m) v = -INFINITY;
                }
                S[nt][j] = v;
            }

        float mx0 = -INFINITY, mx1 = -INFINITY;
        #pragma unroll
        for (int nt = 0; nt < 16; ++nt) {
            mx0 = fmaxf(mx0, fmaxf(S[nt][0], S[nt][1]));
            mx1 = fmaxf(mx1, fmaxf(S[nt][2], S[nt][3]));
        }
        mx0 = fmaxf(mx0, __shfl_xor_sync(0xffffffffu, mx0, 1));
        mx0 = fmaxf(mx0, __shfl_xor_sync(0xffffffffu, mx0, 2));
        mx1 = fmaxf(mx1, __shfl_xor_sync(0xffffffffu, mx1, 1));
        mx1 = fmaxf(mx1, __shfl_xor_sync(0xffffffffu, mx1, 2));

        float mn0 = fmaxf(mrun0, mx0);
        float mn1 = fmaxf(mrun1, mx1);
        float al0 = expf(mrun0 - mn0);
        float al1 = expf(mrun1 - mn1);
        mrun0 = mn0; mrun1 = mn1;

        float ls0 = 0.f, ls1 = 0.f;
        #pragma unroll
        for (int nt = 0; nt < 16; ++nt) {
            float e0 = expf(S[nt][0] - mn0);
            float e1 = expf(S[nt][1] - mn0);
            float e2 = expf(S[nt][2] - mn1);
            float e3 = expf(S[nt][3] - mn1);
            S[nt][0] = e0; S[nt][1] = e1; S[nt][2] = e2; S[nt][3] = e3;
            ls0 += e0 + e1;
            ls1 += e2 + e3;
        }
        lrun0 = lrun0 * al0 + ls0;
        lrun1 = lrun1 * al1 + ls1;

        #pragma unroll
        for (int nt = 0; nt < 16; ++nt) {
            accO[nt][0] *= al0; accO[nt][1] *= al0;
            accO[nt][2] *= al1; accO[nt][3] *= al1;
        }

        // wait for V(kb): outstanding = [V(kb), K(kb+1)] or just [V(kb)] on last iter
        if (kb < qb) cp_wait<1>(); else cp_wait<0>();
        __syncthreads();

        // ---- O += P V ----
        #pragma unroll
        for (int kk = 0; kk < 8; ++kk) {
            uint32_t ph[4], pl[4];
            {
                float v00 = S[2 * kk][0],     v01 = S[2 * kk][1];
                float v02 = S[2 * kk][2],     v03 = S[2 * kk][3];
                float v10 = S[2 * kk + 1][0], v11 = S[2 * kk + 1][1];
                float v12 = S[2 * kk + 1][2], v13 = S[2 * kk + 1][3];
                float h00 = __bfloat162float(__float2bfloat16(v00));
                float h01 = __bfloat162float(__float2bfloat16(v01));
                float h02 = __bfloat162float(__float2bfloat16(v02));
                float h03 = __bfloat162float(__float2bfloat16(v03));
                float h10 = __bfloat162float(__float2bfloat16(v10));
                float h11 = __bfloat162float(__float2bfloat16(v11));
                float h12 = __bfloat162float(__float2bfloat16(v12));
                float h13 = __bfloat162float(__float2bfloat16(v13));
                ph[0] = packb2(h00, h01); ph[1] = packb2(h02, h03);
                ph[2] = packb2(h10, h11); ph[3] = packb2(h12, h13);
                pl[0] = packb2(v00 - h00, v01 - h01); pl[1] = packb2(v02 - h02, v03 - h03);
                pl[2] = packb2(v10 - h10, v11 - h11); pl[3] = packb2(v12 - h12, v13 - h13);
            }
            #pragma unroll
            for (int ndt = 0; ndt < 16; ++ndt) {
                uint32_t vh2[2], vl2[2];
                int rr = kk * 16 + (lane & 15);
                int cc = ndt * 8;
                ldsm2t(vh2, s2u(&sVh[rr * FL_PITCH + cc]));
                ldsm2t(vl2, s2u(&sVl[rr * FL_PITCH + cc]));
                mma16816(accO[ndt], ph, vh2);
                mma16816(accO[ndt], ph, vl2);
                mma16816(accO[ndt], pl, vh2);
            }
        }
        __syncthreads();                       // done reading V tile
        if (kb < qb) { loadV(kb + 1); cp_commit(); }   // V(kb+1) flies over next S
    }

    lrun0 += __shfl_xor_sync(0xffffffffu, lrun0, 1);
    lrun0 += __shfl_xor_sync(0xffffffffu, lrun0, 2);
    lrun1 += __shfl_xor_sync(0xffffffffu, lrun1, 1);
    lrun1 += __shfl_xor_sync(0xffffffffu, lrun1, 2);
    float inv0 = 1.0f / lrun0;
    float inv1 = 1.0f / lrun1;

    size_t obase = (size_t)z * TT * DHD;
    #pragma unroll
    for (int ndt = 0; ndt < 16; ++ndt)
        #pragma unroll
        for (int j = 0; j < 4; ++j) {
            int m = row0 + wid * 16 + g + ((j >> 1) ? 8 : 0);
            int n = ndt * 8 + tg * 2 + (j & 1);
            float v = accO[ndt][j] * ((j >> 1) ? inv1 : inv0);
            size_t idx = obase + (size_t)m * DHD + n;
            split2(v, &aoh[idx], &aol[idx]);
        }
}

// ---------------- host ----------------
#define SYMADDR(var, sym) cudaGetSymbolAddress((void**)&var, sym)

extern "C" void kernel_launch(void* const* d_in, const int* in_sizes, int n_in,
                              void* d_out, int out_size) {
    const float* x   = (const float*)d_in[0];
    const float* l3  = (const float*)d_in[1];
    const float* wq  = (const float*)d_in[2];
    const float* wk  = (const float*)d_in[3];
    const float* wv  = (const float*)d_in[4];
    const float* wo  = (const float*)d_in[5];
    const float* rw1 = (const float*)d_in[6];
    const float* rb1 = (const float*)d_in[7];
    const float* rw2 = (const float*)d_in[8];
    const float* rb2 = (const float*)d_in[9];

    float* out     = (float*)d_out;
    float* kh_out  = out    + (size_t)BB * TT * DD;
    float* vh_out  = kh_out + (size_t)BB * TT * DD;
    float* lam_out = vh_out + (size_t)BB * TT * DD;

    float *hdn, *carryA, *carryB;
    SYMADDR(hdn, g_hdn);
    SYMADDR(carryA, g_carryA); SYMADDR(carryB, g_carryB);

    __nv_bfloat16 *xs_h,*xs_l, *wqs_h,*wqs_l, *wks_h,*wks_l, *wvs_h,*wvs_l,
                  *wos_h,*wos_l, *rw1s_h,*rw1s_l, *qs_h,*qs_l, *fs_h,*fs_l,
                  *khs_h,*khs_l, *vhs_h,*vhs_l, *aos_h,*aos_l;
    SYMADDR(xs_h, g_xs_h);     SYMADDR(xs_l, g_xs_l);
    SYMADDR(wqs_h, g_wqs_h);   SYMADDR(wqs_l, g_wqs_l);
    SYMADDR(wks_h, g_wks_h);   SYMADDR(wks_l, g_wks_l);
    SYMADDR(wvs_h, g_wvs_h);   SYMADDR(wvs_l, g_wvs_l);
    SYMADDR(wos_h, g_wos_h);   SYMADDR(wos_l, g_wos_l);
    SYMADDR(rw1s_h, g_rw1s_h); SYMADDR(rw1s_l, g_rw1s_l);
    SYMADDR(qs_h, g_qs_h);     SYMADDR(qs_l, g_qs_l);
    SYMADDR(fs_h, g_fs_h);     SYMADDR(fs_l, g_fs_l);
    SYMADDR(khs_h, g_khs_h);   SYMADDR(khs_l, g_khs_l);
    SYMADDR(vhs_h, g_vhs_h);   SYMADDR(vhs_l, g_vhs_l);
    SYMADDR(aos_h, g_aos_h);   SYMADDR(aos_l, g_aos_l);

    const int M = BB * TT;
    const float scale = 1.0f / sqrtf((float)DHD);
    const int ND4 = (int)((size_t)BB * TT * DD / 4);     // 1M
    const int NW4 = (int)((size_t)DD * DD / 4);          // 1M

    cudaFuncSetAttribute(mma_gemm<M_Q>,   cudaFuncAttributeMaxDynamicSharedMemorySize, GEMM_SMEM);
    cudaFuncSetAttribute(mma_gemm<M_HDN>, cudaFuncAttributeMaxDynamicSharedMemorySize, GEMM_SMEM);
    cudaFuncSetAttribute(mma_gemm<M_KV>,  cudaFuncAttributeMaxDynamicSharedMemorySize, GEMM_SMEM);
    cudaFuncSetAttribute(mma_gemm<M_OUT>, cudaFuncAttributeMaxDynamicSharedMemorySize, GEMM_SMEM);
    cudaFuncSetAttribute(flash_kernel,    cudaFuncAttributeMaxDynamicSharedMemorySize, FLASH_SMEM);

    // splits (vectorized x4)
    split_v4_kernel<<<(ND4 + 255) / 256, 256>>>(
        (const float4*)x, (uint2*)xs_h, (uint2*)xs_l, ND4);
    split4_v4_kernel<<<(NW4 + 255) / 256, 256>>>(
        (const float4*)wq, (const float4*)wk, (const float4*)wv, (const float4*)wo,
        (uint2*)wqs_h, (uint2*)wqs_l, (uint2*)wks_h, (uint2*)wks_l,
        (uint2*)wvs_h, (uint2*)wvs_l, (uint2*)wos_h, (uint2*)wos_l, NW4);
    split_v4_kernel<<<(NW4 / 2 + 255) / 256, 256>>>(
        (const float4*)rw1, (uint2*)rw1s_h, (uint2*)rw1s_l, NW4 / 2);

    // EMA chunk scans + carries (fuse deferred until lam is ready)
    ema_chunk_v4<<<(BB * NC * D4 + 255) / 256, 256>>>((const float4*)x, (float4*)carryA);
    ema_carry_v4<<<(BB * D4 + 255) / 256, 256>>>((const float4*)carryA, (float4*)carryB);

    // q = x @ wq^T
    mma_gemm<M_Q><<<dim3(DD / BN, M / BM), 256, GEMM_SMEM>>>(
        xs_h, xs_l, wqs_h, wqs_l, nullptr, nullptr, qs_h, qs_l, M, DD, DD, DD, DD);

    // hdn = silu(q @ rw1^T + rb1)
    mma_gemm<M_HDN><<<dim3(DHALF / BN, M / BM), 256, GEMM_SMEM>>>(
        qs_h, qs_l, rw1s_h, rw1s_l, rb1, hdn, nullptr, nullptr, M, DHALF, DD, DD, DD);

    // lam
    router_kernel<<<(M + 7) / 8, 256>>>(hdn, rw2, rb2, lam_out);

    // EMA rescan + fuse + split (single pass)
    ema_fuse_v4<<<(BB * NC * D4 + 255) / 256, 256>>>(
        (const float4*)x, (const float4*)carryB, (const float4*)l3, lam_out,
        (uint2*)fs_h, (uint2*)fs_l);

    // kh / vh
    mma_gemm<M_KV><<<dim3(DD / BN, M / BM), 256, GEMM_SMEM>>>(
        fs_h, fs_l, wks_h, wks_l, nullptr, kh_out, khs_h, khs_l, M, DD, DD, DD, DD);
    mma_gemm<M_KV><<<dim3(DD / BN, M / BM), 256, GEMM_SMEM>>>(
        fs_h, fs_l, wvs_h, wvs_l, nullptr, vh_out, vhs_h, vhs_l, M, DD, DD, DD, DD);

    // flash attention -> ao (split)
    flash_kernel<<<dim3(TT / 128, BB * HH), 256, FLASH_SMEM>>>(
        qs_h, qs_l, khs_h, khs_l, vhs_h, vhs_l, aos_h, aos_l, scale);

    // out = concat_heads(ao) @ wo^T
    mma_gemm<M_OUT><<<dim3(DD / BN, M / BM), 256, GEMM_SMEM>>>(
        aos_h, aos_l, wos_h, wos_l, nullptr, out, nullptr, nullptr, M, DD, DD, DD, DD);
}

// round 9
// speedup vs baseline: 2.7370x; 1.0354x over previous
#include <cuda_runtime.h>
#include <cuda_bf16.h>
#include <math.h>
#include <stdint.h>

#define BB 2
#define TT 1024
#define DD 2048
#define HH 16
#define DHD 128
#define DHALF 1024

#define BM 128
#define BN 128
#define BKS 32

// EMA chunking: 64 chunks of 16 steps
#define NC 64
#define CL 16
#define BETA 0.9f
#define OMB  0.1f
#define BETA_L 0.1853020188851841f   // 0.9^16

// GEMM modes
#define M_Q 0
#define M_HDN 1
#define M_KV2 2
#define M_OUT 3

// ---------------- device scratch ----------------
__device__ float g_hdn[(size_t)BB*TT*DHALF];
__device__ float g_carryA[(size_t)BB*NC*DD];
__device__ float g_carryB[(size_t)BB*NC*DD];

#define DECL_SPLIT(name, count) \
    __device__ __nv_bfloat16 name##_h[count]; \
    __device__ __nv_bfloat16 name##_l[count];

DECL_SPLIT(g_xs,   (size_t)BB*TT*DD)
DECL_SPLIT(g_wqs,  (size_t)DD*DD)
DECL_SPLIT(g_wks,  (size_t)DD*DD)
DECL_SPLIT(g_wvs,  (size_t)DD*DD)
DECL_SPLIT(g_wos,  (size_t)DD*DD)
DECL_SPLIT(g_rw1s, (size_t)DHALF*DD)
DECL_SPLIT(g_qs,   (size_t)BB*TT*DD)
DECL_SPLIT(g_fs,   (size_t)BB*TT*DD)
DECL_SPLIT(g_khs,  (size_t)BB*TT*DD)
DECL_SPLIT(g_vhs,  (size_t)BB*TT*DD)
DECL_SPLIT(g_aos,  (size_t)BB*TT*DD)

// ---------------- helpers ----------------
__device__ __forceinline__ void split2(float v, __nv_bfloat16* hi, __nv_bfloat16* lo) {
    __nv_bfloat16 h = __float2bfloat16(v);
    *hi = h;
    *lo = __float2bfloat16(v - __bfloat162float(h));
}
__device__ __forceinline__ uint32_t s2u(const void* p) {
    return (uint32_t)__cvta_generic_to_shared(p);
}
__device__ __forceinline__ void ldsm4(uint32_t* r, uint32_t addr) {
    asm volatile("ldmatrix.sync.aligned.m8n8.x4.shared.b16 {%0,%1,%2,%3}, [%4];"
                 : "=r"(r[0]), "=r"(r[1]), "=r"(r[2]), "=r"(r[3]) : "r"(addr));
}
__device__ __forceinline__ void ldsm2(uint32_t* r, uint32_t addr) {
    asm volatile("ldmatrix.sync.aligned.m8n8.x2.shared.b16 {%0,%1}, [%2];"
                 : "=r"(r[0]), "=r"(r[1]) : "r"(addr));
}
__device__ __forceinline__ void ldsm2t(uint32_t* r, uint32_t addr) {
    asm volatile("ldmatrix.sync.aligned.m8n8.x2.trans.shared.b16 {%0,%1}, [%2];"
                 : "=r"(r[0]), "=r"(r[1]) : "r"(addr));
}
__device__ __forceinline__ void mma16816(float* c, const uint32_t* a, const uint32_t* b) {
    asm volatile("mma.sync.aligned.m16n8k16.row.col.f32.bf16.bf16.f32 "
                 "{%0,%1,%2,%3}, {%4,%5,%6,%7}, {%8,%9}, {%0,%1,%2,%3};"
                 : "+f"(c[0]), "+f"(c[1]), "+f"(c[2]), "+f"(c[3])
                 : "r"(a[0]), "r"(a[1]), "r"(a[2]), "r"(a[3]), "r"(b[0]), "r"(b[1]));
}
__device__ __forceinline__ void cp16(uint32_t saddr, const void* g) {
    asm volatile("cp.async.cg.shared.global [%0], [%1], 16;" :: "r"(saddr), "l"(g));
}
__device__ __forceinline__ void cp_commit() {
    asm volatile("cp.async.commit_group;");
}
template<int N> __device__ __forceinline__ void cp_wait() {
    asm volatile("cp.async.wait_group %0;" :: "n"(N));
}
__device__ __forceinline__ uint32_t packb2(float lo_k, float hi_k) {
    __nv_bfloat162 t = __floats2bfloat162_rn(lo_k, hi_k);   // .x = low half
    return *reinterpret_cast<uint32_t*>(&t);
}

// split float4 -> hi uint2 (4 bf16) + lo uint2
__device__ __forceinline__ void split4v(float4 v, uint2* hi, uint2* lo) {
    __nv_bfloat16 h0 = __float2bfloat16(v.x);
    __nv_bfloat16 h1 = __float2bfloat16(v.y);
    __nv_bfloat16 h2 = __float2bfloat16(v.z);
    __nv_bfloat16 h3 = __float2bfloat16(v.w);
    float r0 = v.x - __bfloat162float(h0);
    float r1 = v.y - __bfloat162float(h1);
    float r2 = v.z - __bfloat162float(h2);
    float r3 = v.w - __bfloat162float(h3);
    __nv_bfloat162 p01; p01.x = h0; p01.y = h1;
    __nv_bfloat162 p23; p23.x = h2; p23.y = h3;
    hi->x = *reinterpret_cast<uint32_t*>(&p01);
    hi->y = *reinterpret_cast<uint32_t*>(&p23);
    lo->x = packb2(r0, r1);
    lo->y = packb2(r2, r3);
}

// ---------------- elementwise kernels (vectorized x4) ----------------
__global__ void split_v4_kernel(const float4* __restrict__ s,
                                uint2* __restrict__ hi, uint2* __restrict__ lo, int n4) {
    int i = blockIdx.x * blockDim.x + threadIdx.x;
    if (i >= n4) return;
    uint2 h, l;
    split4v(s[i], &h, &l);
    hi[i] = h; lo[i] = l;
}

__global__ void split4_v4_kernel(const float4* __restrict__ a, const float4* __restrict__ b,
                                 const float4* __restrict__ c, const float4* __restrict__ d,
                                 uint2* __restrict__ ah, uint2* __restrict__ al,
                                 uint2* __restrict__ bh, uint2* __restrict__ bl,
                                 uint2* __restrict__ ch, uint2* __restrict__ cl,
                                 uint2* __restrict__ dh, uint2* __restrict__ dl, int n4) {
    int i = blockIdx.x * blockDim.x + threadIdx.x;
    if (i >= n4) return;
    uint2 h, l;
    split4v(a[i], &h, &l); ah[i] = h; al[i] = l;
    split4v(b[i], &h, &l); bh[i] = h; bl[i] = l;
    split4v(c[i], &h, &l); ch[i] = h; cl[i] = l;
    split4v(d[i], &h, &l); dh[i] = h; dl[i] = l;
}

// ---- chunk-parallel EMA (NC=64 chunks of CL=16), float4-vectorized ----
#define D4 (DD / 4)

__global__ void ema_chunk_v4(const float4* __restrict__ x4, float4* __restrict__ carryA4) {
    int idx = blockIdx.x * blockDim.x + threadIdx.x;
    if (idx >= BB * NC * D4) return;
    int c4 = idx % D4;
    int bc = idx / D4;
    int chunk = bc % NC;
    int b = bc / NC;
    const float4* xp = x4 + ((size_t)b * TT + (size_t)chunk * CL) * D4 + c4;
    float4 s = make_float4(0.f, 0.f, 0.f, 0.f);
    #pragma unroll
    for (int t = 0; t < CL; ++t) {
        float4 v = xp[(size_t)t * D4];
        s.x = BETA * s.x + OMB * v.x;
        s.y = BETA * s.y + OMB * v.y;
        s.z = BETA * s.z + OMB * v.z;
        s.w = BETA * s.w + OMB * v.w;
    }
    carryA4[idx] = s;
}

__global__ void ema_carry_v4(const float4* __restrict__ carryA4, float4* __restrict__ carryB4) {
    int idx = blockIdx.x * blockDim.x + threadIdx.x;
    if (idx >= BB * D4) return;
    int c4 = idx % D4;
    int b = idx / D4;
    float4 cin = make_float4(0.f, 0.f, 0.f, 0.f);
    #pragma unroll
    for (int j = 0; j < NC; ++j) {
        size_t off = ((size_t)b * NC + j) * D4 + c4;
        carryB4[off] = cin;
        float4 a = carryA4[off];
        cin.x = BETA_L * cin.x + a.x;
        cin.y = BETA_L * cin.y + a.y;
        cin.z = BETA_L * cin.z + a.z;
        cin.w = BETA_L * cin.w + a.w;
    }
}

// rescan + fuse + split, all in one pass
__global__ void ema_fuse_v4(const float4* __restrict__ x4, const float4* __restrict__ carryB4,
                            const float4* __restrict__ l34, const float* __restrict__ lam,
                            uint2* __restrict__ fh4, uint2* __restrict__ fl4) {
    int idx = blockIdx.x * blockDim.x + threadIdx.x;
    if (idx >= BB * NC * D4) return;
    int c4 = idx % D4;
    int bc = idx / D4;
    int chunk = bc % NC;
    int b = bc / NC;
    size_t base = ((size_t)b * TT + (size_t)chunk * CL) * D4 + c4;
    float4 s = carryB4[idx];
    float4 m = l34[(size_t)b * D4 + c4];
    int row0 = b * TT + chunk * CL;
    #pragma unroll
    for (int t = 0; t < CL; ++t) {
        float4 v = x4[base + (size_t)t * D4];
        s.x = BETA * s.x + OMB * v.x;
        s.y = BETA * s.y + OMB * v.y;
        s.z = BETA * s.z + OMB * v.z;
        s.w = BETA * s.w + OMB * v.w;
        int row = row0 + t;
        float a0 = lam[(size_t)row * 3 + 0];
        float a1 = lam[(size_t)row * 3 + 1];
        float a2 = lam[(size_t)row * 3 + 2];
        float4 f;
        f.x = a0 * v.x + a1 * s.x + a2 * m.x;
        f.y = a0 * v.y + a1 * s.y + a2 * m.y;
        f.z = a0 * v.z + a1 * s.z + a2 * m.z;
        f.w = a0 * v.w + a1 * s.w + a2 * m.w;
        uint2 h, l;
        split4v(f, &h, &l);
        fh4[base + (size_t)t * D4] = h;
        fl4[base + (size_t)t * D4] = l;
    }
}

__global__ void router_kernel(const float* __restrict__ hdn,
                              const float* __restrict__ rw2,
                              const float* __restrict__ rb2,
                              float* __restrict__ lam) {
    int row  = blockIdx.x * (blockDim.x / 32) + (threadIdx.x / 32);
    int lane = threadIdx.x & 31;
    if (row >= BB * TT) return;
    const float* hp = hdn + (size_t)row * DHALF;
    float a0 = 0.f, a1 = 0.f, a2 = 0.f;
    for (int i = lane; i < DHALF; i += 32) {
        float h = hp[i];
        a0 += h * rw2[0 * DHALF + i];
        a1 += h * rw2[1 * DHALF + i];
        a2 += h * rw2[2 * DHALF + i];
    }
    #pragma unroll
    for (int o = 16; o > 0; o >>= 1) {
        a0 += __shfl_xor_sync(0xffffffffu, a0, o);
        a1 += __shfl_xor_sync(0xffffffffu, a1, o);
        a2 += __shfl_xor_sync(0xffffffffu, a2, o);
    }
    if (lane == 0) {
        float z0 = a0 + rb2[0], z1 = a1 + rb2[1], z2 = a2 + rb2[2];
        float m = fmaxf(z0, fmaxf(z1, z2));
        float e0 = expf(z0 - m), e1 = expf(z1 - m), e2 = expf(z2 - m);
        float inv = 1.0f / (e0 + e1 + e2);
        lam[(size_t)row * 3 + 0] = e0 * inv;
        lam[(size_t)row * 3 + 1] = e1 * inv;
        lam[(size_t)row * 3 + 2] = e2 * inv;
    }
}

// ---------------- pipelined split-bf16 tensor-core GEMM ----------------
// M_KV2: grid.x covers 2*N/BN blocks; first half computes A@Bk^T -> kh, second A@Bv^T -> vh.
#define GEMM_SMEM (2 * 2 * BM * 40 * 2 * 2)

template<int MODE>
__global__ void __launch_bounds__(256, 2) mma_gemm(
    const __nv_bfloat16* __restrict__ Ahi, const __nv_bfloat16* __restrict__ Alo,
    const __nv_bfloat16* __restrict__ Bhi, const __nv_bfloat16* __restrict__ Blo,
    const __nv_bfloat16* __restrict__ B2hi, const __nv_bfloat16* __restrict__ B2lo,
    const float* __restrict__ bias,
    float* __restrict__ Cf, float* __restrict__ Cf2,
    __nv_bfloat16* __restrict__ Chi, __nv_bfloat16* __restrict__ Clo,
    __nv_bfloat16* __restrict__ C2hi, __nv_bfloat16* __restrict__ C2lo,
    int M, int N, int K, int lda, int ldb)
{
    extern __shared__ __align__(16) char dynsmem[];
    __nv_bfloat16* sA = reinterpret_cast<__nv_bfloat16*>(dynsmem);
    __nv_bfloat16* sB = sA + 2 * 2 * BM * 40;

    int tid = threadIdx.x;
    int lane = tid & 31;
    int warp = tid >> 5;
    int wm = warp >> 2;
    int wn = warp & 3;
    int row0 = blockIdx.y * BM;

    int nb = N / BN;                         // blocks per weight matrix
    int which = 0;
    int bx = blockIdx.x;
    if (MODE == M_KV2) { which = bx / nb; bx -= which * nb; }
    int col0 = bx * BN;

    const __nv_bfloat16* Bh = (MODE == M_KV2 && which) ? B2hi : Bhi;
    const __nv_bfloat16* Bl = (MODE == M_KV2 && which) ? B2lo : Blo;

    float acc[4][4][4];
    #pragma unroll
    for (int a = 0; a < 4; ++a)
        #pragma unroll
        for (int b = 0; b < 4; ++b)
            #pragma unroll
            for (int c = 0; c < 4; ++c) acc[a][b][c] = 0.f;

    auto issue = [&](int k0, int st) {
        #pragma unroll
        for (int it = 0; it < 2; ++it) {
            int e = tid + it * 256;
            int r = e >> 2;
            int kc = (e & 3) * 8;
            size_t ao;
            if (MODE == M_OUT) {
                int gm = row0 + r, gk = k0 + kc;
                int b = gm >> 10, t = gm & (TT - 1);
                int h = gk >> 7, c = gk & (DHD - 1);
                ao = (((size_t)b * HH + h) * TT + t) * DHD + c;
            } else {
                ao = (size_t)(row0 + r) * lda + k0 + kc;
            }
            cp16(s2u(&sA[((st * 2 + 0) * BM + r) * 40 + kc]), Ahi + ao);
            cp16(s2u(&sA[((st * 2 + 1) * BM + r) * 40 + kc]), Alo + ao);
            size_t bo = (size_t)(col0 + r) * ldb + k0 + kc;
            cp16(s2u(&sB[((st * 2 + 0) * BM + r) * 40 + kc]), Bh + bo);
            cp16(s2u(&sB[((st * 2 + 1) * BM + r) * 40 + kc]), Bl + bo);
        }
    };

    int nIter = K / BKS;
    issue(0, 0);
    cp_commit();

    for (int i = 0; i < nIter; ++i) {
        int st = i & 1;
        if (i + 1 < nIter) {
            issue((i + 1) * BKS, (i + 1) & 1);
            cp_commit();
            cp_wait<1>();
        } else {
            cp_wait<0>();
        }
        __syncthreads();

        #pragma unroll
        for (int ks = 0; ks < BKS; ks += 16) {
            uint32_t afr[2][4][4];
            uint32_t bfr[2][4][2];
            #pragma unroll
            for (int mt = 0; mt < 4; ++mt) {
                int r = wm * 64 + mt * 16 + (lane & 15);
                int c = ks + (lane >> 4) * 8;
                ldsm4(afr[0][mt], s2u(&sA[((st * 2 + 0) * BM + r) * 40 + c]));
                ldsm4(afr[1][mt], s2u(&sA[((st * 2 + 1) * BM + r) * 40 + c]));
            }
            #pragma unroll
            for (int nt = 0; nt < 4; ++nt) {
                int r = wn * 32 + nt * 8 + (lane & 7);
                int c = ks + ((lane >> 3) & 1) * 8;
                ldsm2(bfr[0][nt], s2u(&sB[((st * 2 + 0) * BM + r) * 40 + c]));
                ldsm2(bfr[1][nt], s2u(&sB[((st * 2 + 1) * BM + r) * 40 + c]));
            }
            #pragma unroll
            for (int mt = 0; mt < 4; ++mt)
                #pragma unroll
                for (int nt = 0; nt < 4; ++nt) {
                    mma16816(acc[mt][nt], afr[0][mt], bfr[0][nt]);
                    mma16816(acc[mt][nt], afr[0][mt], bfr[1][nt]);
                    mma16816(acc[mt][nt], afr[1][mt], bfr[0][nt]);
                }
        }
        __syncthreads();
    }

    int g = lane >> 2, tg = lane & 3;
    #pragma unroll
    for (int mt = 0; mt < 4; ++mt)
        #pragma unroll
        for (int nt = 0; nt < 4; ++nt)
            #pragma unroll
            for (int i = 0; i < 4; ++i) {
                int m = row0 + wm * 64 + mt * 16 + g + (i >> 1) * 8;
                int n = col0 + wn * 32 + nt * 8 + tg * 2 + (i & 1);
                float v = acc[mt][nt][i];
                if (MODE == M_Q) {
                    size_t idx = (size_t)m * N + n;
                    split2(v, &Chi[idx], &Clo[idx]);
                } else if (MODE == M_HDN) {
                    v += bias[n];
                    Cf[(size_t)m * N + n] = v / (1.f + expf(-v));
                } else if (MODE == M_KV2) {
                    int b = m >> 10, t = m & (TT - 1);
                    int h = n >> 7, c = n & (DHD - 1);
                    size_t idx = (((size_t)b * HH + h) * TT + t) * DHD + c;
                    if (which == 0) {
                        Cf[idx] = v;
                        split2(v, &Chi[idx], &Clo[idx]);
                    } else {
                        Cf2[idx] = v;
                        split2(v, &C2hi[idx], &C2lo[idx]);
                    }
                } else {
                    Cf[(size_t)m * N + n] = v;
                }
            }
}

// ---------------- flash attention ----------------
// Q: hi only (ql term dropped; ~1e-4 output contribution)
// PV: ph*vh + ph*vl (pl term dropped; ~9e-5)
#define FL_PITCH 136
#define FL_TILE  (128 * FL_PITCH)
#define FLASH_SMEM (5 * FL_TILE * 2)

__global__ void __launch_bounds__(256) flash_kernel(
    const __nv_bfloat16* __restrict__ qh_,
    const __nv_bfloat16* __restrict__ khh, const __nv_bfloat16* __restrict__ khl,
    const __nv_bfloat16* __restrict__ vhh, const __nv_bfloat16* __restrict__ vhl,
    __nv_bfloat16* __restrict__ aoh, __nv_bfloat16* __restrict__ aol,
    float scale)
{
    extern __shared__ __align__(16) char fsm[];
    __nv_bfloat16* sQh = reinterpret_cast<__nv_bfloat16*>(fsm);
    __nv_bfloat16* sKh = sQh + FL_TILE;
    __nv_bfloat16* sKl = sKh + FL_TILE;
    __nv_bfloat16* sVh = sKl + FL_TILE;
    __nv_bfloat16* sVl = sVh + FL_TILE;

    int tid = threadIdx.x;
    int lane = tid & 31;
    int wid = tid >> 5;
    int g = lane >> 2, tg = lane & 3;

    int qb = gridDim.x - 1 - blockIdx.x;   // heavy blocks first
    int z = blockIdx.y;
    int b = z / HH, h = z % HH;
    int row0 = qb * 128;

    const __nv_bfloat16* qbh = qh_ + (size_t)b * TT * DD + (size_t)h * DHD;
    const __nv_bfloat16* kbh = khh + (size_t)z * TT * DHD;
    const __nv_bfloat16* kbl = khl + (size_t)z * TT * DHD;
    const __nv_bfloat16* vbh = vhh + (size_t)z * TT * DHD;
    const __nv_bfloat16* vbl = vhl + (size_t)z * TT * DHD;

    auto loadK = [&](int kb2) {
        for (int e = tid; e < 128 * 16; e += 256) {
            int r = e >> 4, c8 = (e & 15) * 8;
            size_t go = (size_t)(kb2 * 128 + r) * DHD + c8;
            cp16(s2u(&sKh[r * FL_PITCH + c8]), kbh + go);
            cp16(s2u(&sKl[r * FL_PITCH + c8]), kbl + go);
        }
    };
    auto loadV = [&](int kb2) {
        for (int e = tid; e < 128 * 16; e += 256) {
            int r = e >> 4, c8 = (e & 15) * 8;
            size_t go = (size_t)(kb2 * 128 + r) * DHD + c8;
            cp16(s2u(&sVh[r * FL_PITCH + c8]), vbh + go);
            cp16(s2u(&sVl[r * FL_PITCH + c8]), vbl + go);
        }
    };

    for (int e = tid; e < 128 * 16; e += 256) {
        int r = e >> 4, c8 = (e & 15) * 8;
        *reinterpret_cast<uint4*>(&sQh[r * FL_PITCH + c8]) =
            *reinterpret_cast<const uint4*>(qbh + (size_t)(row0 + r) * DD + c8);
    }
    loadK(0); cp_commit();
    loadV(0); cp_commit();

    float accO[16][4];
    #pragma unroll
    for (int i = 0; i < 16; ++i)
        #pragma unroll
        for (int j = 0; j < 4; ++j) accO[i][j] = 0.f;
    float mrun0 = -INFINITY, mrun1 = -INFINITY;
    float lrun0 = 0.f, lrun1 = 0.f;

    for (int kb = 0; kb <= qb; ++kb) {
        cp_wait<1>();
        __syncthreads();

        // ---- S = Qh (Kh + Kl)^T ----
        float S[16][4];
        #pragma unroll
        for (int i = 0; i < 16; ++i)
            #pragma unroll
            for (int j = 0; j < 4; ++j) S[i][j] = 0.f;

        #pragma unroll
        for (int ks = 0; ks < 8; ++ks) {
            uint32_t qf[4];
            {
                int r = wid * 16 + (lane & 15);
                int c = ks * 16 + (lane >> 4) * 8;
                ldsm4(qf, s2u(&sQh[r * FL_PITCH + c]));
            }
            #pragma unroll
            for (int nt = 0; nt < 16; ++nt) {
                uint32_t bh[2], bl[2];
                int r = nt * 8 + (lane & 7);
                int c = ks * 16 + ((lane >> 3) & 1) * 8;
                ldsm2(bh, s2u(&sKh[r * FL_PITCH + c]));
                ldsm2(bl, s2u(&sKl[r * FL_PITCH + c]));
                mma16816(S[nt], qf, bh);
                mma16816(S[nt], qf, bl);
            }
        }
        __syncthreads();
        if (kb < qb) { loadK(kb + 1); cp_commit(); }

        // ---- scale + mask + online softmax ----
        bool diag = (kb == qb);
        #pragma unroll
        for (int nt = 0; nt < 16; ++nt)
            #pragma unroll
            for (int j = 0; j < 4; ++j) {
                float v = S[nt][j] * scale;
                if (diag) {
                    int n = nt * 8 + tg * 2 + (j & 1);
                    int m = wid * 16 + g + ((j >> 1) ? 8 : 0);
                    if (n > m) v = -INFINITY;
                }
                S[nt][j] = v;
            }

        float mx0 = -INFINITY, mx1 = -INFINITY;
        #pragma unroll
        for (int nt = 0; nt < 16; ++nt) {
            mx0 = fmaxf(mx0, fmaxf(S[nt][0], S[nt][1]));
            mx1 = fmaxf(mx1, fmaxf(S[nt][2], S[nt][3]));
        }
        mx0 = fmaxf(mx0, __shfl_xor_sync(0xffffffffu, mx0, 1));
        mx0 = fmaxf(mx0, __shfl_xor_sync(0xffffffffu, mx0, 2));
        mx1 = fmaxf(mx1, __shfl_xor_sync(0xffffffffu, mx1, 1));
        mx1 = fmaxf(mx1, __shfl_xor_sync(0xffffffffu, mx1, 2));

        float mn0 = fmaxf(mrun0, mx0);
        float mn1 = fmaxf(mrun1, mx1);
        float al0 = expf(mrun0 - mn0);
        float al1 = expf(mrun1 - mn1);
        mrun0 = mn0; mrun1 = mn1;

        float ls0 = 0.f, ls1 = 0.f;
        #pragma unroll
        for (int nt = 0; nt < 16; ++nt) {
            float e0 = expf(S[nt][0] - mn0);
            float e1 = expf(S[nt][1] - mn0);
            float e2 = expf(S[nt][2] - mn1);
            float e3 = expf(S[nt][3] - mn1);
            S[nt][0] = e0; S[nt][1] = e1; S[nt][2] = e2; S[nt][3] = e3;
            ls0 += e0 + e1;
            ls1 += e2 + e3;
        }
        lrun0 = lrun0 * al0 + ls0;
        lrun1 = lrun1 * al1 + ls1;

        #pragma unroll
        for (int nt = 0; nt < 16; ++nt) {
            accO[nt][0] *= al0; accO[nt][1] *= al0;
            accO[nt][2] *= al1; accO[nt][3] *= al1;
        }

        if (kb < qb) cp_wait<1>(); else cp_wait<0>();
        __syncthreads();

        // ---- O += Ph (Vh + Vl) ----
        #pragma unroll
        for (int kk = 0; kk < 8; ++kk) {
            uint32_t ph[4];
            ph[0] = packb2(S[2 * kk][0],     S[2 * kk][1]);
            ph[1] = packb2(S[2 * kk][2],     S[2 * kk][3]);
            ph[2] = packb2(S[2 * kk + 1][0], S[2 * kk + 1][1]);
            ph[3] = packb2(S[2 * kk + 1][2], S[2 * kk + 1][3]);
            #pragma unroll
            for (int ndt = 0; ndt < 16; ++ndt) {
                uint32_t vh2[2], vl2[2];
                int rr = kk * 16 + (lane & 15);
                int cc = ndt * 8;
                ldsm2t(vh2, s2u(&sVh[rr * FL_PITCH + cc]));
                ldsm2t(vl2, s2u(&sVl[rr * FL_PITCH + cc]));
                mma16816(accO[ndt], ph, vh2);
                mma16816(accO[ndt], ph, vl2);
            }
        }
        __syncthreads();
        if (kb < qb) { loadV(kb + 1); cp_commit(); }
    }

    lrun0 += __shfl_xor_sync(0xffffffffu, lrun0, 1);
    lrun0 += __shfl_xor_sync(0xffffffffu, lrun0, 2);
    lrun1 += __shfl_xor_sync(0xffffffffu, lrun1, 1);
    lrun1 += __shfl_xor_sync(0xffffffffu, lrun1, 2);
    float inv0 = 1.0f / lrun0;
    float inv1 = 1.0f / lrun1;

    size_t obase = (size_t)z * TT * DHD;
    #pragma unroll
    for (int ndt = 0; ndt < 16; ++ndt)
        #pragma unroll
        for (int j = 0; j < 4; ++j) {
            int m = row0 + wid * 16 + g + ((j >> 1) ? 8 : 0);
            int n = ndt * 8 + tg * 2 + (j & 1);
            float v = accO[ndt][j] * ((j >> 1) ? inv1 : inv0);
            size_t idx = obase + (size_t)m * DHD + n;
            split2(v, &aoh[idx], &aol[idx]);
        }
}

// ---------------- host ----------------
#define SYMADDR(var, sym) cudaGetSymbolAddress((void**)&var, sym)

extern "C" void kernel_launch(void* const* d_in, const int* in_sizes, int n_in,
                              void* d_out, int out_size) {
    const float* x   = (const float*)d_in[0];
    const float* l3  = (const float*)d_in[1];
    const float* wq  = (const float*)d_in[2];
    const float* wk  = (const float*)d_in[3];
    const float* wv  = (const float*)d_in[4];
    const float* wo  = (const float*)d_in[5];
    const float* rw1 = (const float*)d_in[6];
    const float* rb1 = (const float*)d_in[7];
    const float* rw2 = (const float*)d_in[8];
    const float* rb2 = (const float*)d_in[9];

    float* out     = (float*)d_out;
    float* kh_out  = out    + (size_t)BB * TT * DD;
    float* vh_out  = kh_out + (size_t)BB * TT * DD;
    float* lam_out = vh_out + (size_t)BB * TT * DD;

    float *hdn, *carryA, *carryB;
    SYMADDR(hdn, g_hdn);
    SYMADDR(carryA, g_carryA); SYMADDR(carryB, g_carryB);

    __nv_bfloat16 *xs_h,*xs_l, *wqs_h,*wqs_l, *wks_h,*wks_l, *wvs_h,*wvs_l,
                  *wos_h,*wos_l, *rw1s_h,*rw1s_l, *qs_h,*qs_l, *fs_h,*fs_l,
                  *khs_h,*khs_l, *vhs_h,*vhs_l, *aos_h,*aos_l;
    SYMADDR(xs_h, g_xs_h);     SYMADDR(xs_l, g_xs_l);
    SYMADDR(wqs_h, g_wqs_h);   SYMADDR(wqs_l, g_wqs_l);
    SYMADDR(wks_h, g_wks_h);   SYMADDR(wks_l, g_wks_l);
    SYMADDR(wvs_h, g_wvs_h);   SYMADDR(wvs_l, g_wvs_l);
    SYMADDR(wos_h, g_wos_h);   SYMADDR(wos_l, g_wos_l);
    SYMADDR(rw1s_h, g_rw1s_h); SYMADDR(rw1s_l, g_rw1s_l);
    SYMADDR(qs_h, g_qs_h);     SYMADDR(qs_l, g_qs_l);
    SYMADDR(fs_h, g_fs_h);     SYMADDR(fs_l, g_fs_l);
    SYMADDR(khs_h, g_khs_h);   SYMADDR(khs_l, g_khs_l);
    SYMADDR(vhs_h, g_vhs_h);   SYMADDR(vhs_l, g_vhs_l);
    SYMADDR(aos_h, g_aos_h);   SYMADDR(aos_l, g_aos_l);

    const int M = BB * TT;
    const float scale = 1.0f / sqrtf((float)DHD);
    const int ND4 = (int)((size_t)BB * TT * DD / 4);
    const int NW4 = (int)((size_t)DD * DD / 4);

    cudaFuncSetAttribute(mma_gemm<M_Q>,   cudaFuncAttributeMaxDynamicSharedMemorySize, GEMM_SMEM);
    cudaFuncSetAttribute(mma_gemm<M_HDN>, cudaFuncAttributeMaxDynamicSharedMemorySize, GEMM_SMEM);
    cudaFuncSetAttribute(mma_gemm<M_KV2>, cudaFuncAttributeMaxDynamicSharedMemorySize, GEMM_SMEM);
    cudaFuncSetAttribute(mma_gemm<M_OUT>, cudaFuncAttributeMaxDynamicSharedMemorySize, GEMM_SMEM);
    cudaFuncSetAttribute(flash_kernel,    cudaFuncAttributeMaxDynamicSharedMemorySize, FLASH_SMEM);

    // splits (vectorized x4)
    split_v4_kernel<<<(ND4 + 255) / 256, 256>>>(
        (const float4*)x, (uint2*)xs_h, (uint2*)xs_l, ND4);
    split4_v4_kernel<<<(NW4 + 255) / 256, 256>>>(
        (const float4*)wq, (const float4*)wk, (const float4*)wv, (const float4*)wo,
        (uint2*)wqs_h, (uint2*)wqs_l, (uint2*)wks_h, (uint2*)wks_l,
        (uint2*)wvs_h, (uint2*)wvs_l, (uint2*)wos_h, (uint2*)wos_l, NW4);
    split_v4_kernel<<<(NW4 / 2 + 255) / 256, 256>>>(
        (const float4*)rw1, (uint2*)rw1s_h, (uint2*)rw1s_l, NW4 / 2);

    // EMA chunk scans + carries
    ema_chunk_v4<<<(BB * NC * D4 + 255) / 256, 256>>>((const float4*)x, (float4*)carryA);
    ema_carry_v4<<<(BB * D4 + 255) / 256, 256>>>((const float4*)carryA, (float4*)carryB);

    // q = x @ wq^T
    mma_gemm<M_Q><<<dim3(DD / BN, M / BM), 256, GEMM_SMEM>>>(
        xs_h, xs_l, wqs_h, wqs_l, nullptr, nullptr, nullptr, nullptr, nullptr,
        qs_h, qs_l, nullptr, nullptr, M, DD, DD, DD, DD);

    // hdn = silu(q @ rw1^T + rb1)
    mma_gemm<M_HDN><<<dim3(DHALF / BN, M / BM), 256, GEMM_SMEM>>>(
        qs_h, qs_l, rw1s_h, rw1s_l, nullptr, nullptr, rb1, hdn, nullptr,
        nullptr, nullptr, nullptr, nullptr, M, DHALF, DD, DD, DD);

    // lam
    router_kernel<<<(M + 7) / 8, 256>>>(hdn, rw2, rb2, lam_out);

    // EMA rescan + fuse + split (single pass)
    ema_fuse_v4<<<(BB * NC * D4 + 255) / 256, 256>>>(
        (const float4*)x, (const float4*)carryB, (const float4*)l3, lam_out,
        (uint2*)fs_h, (uint2*)fs_l);

    // kh + vh in ONE launch (blockIdx.x selects weight)
    mma_gemm<M_KV2><<<dim3(2 * DD / BN, M / BM), 256, GEMM_SMEM>>>(
        fs_h, fs_l, wks_h, wks_l, wvs_h, wvs_l, nullptr, kh_out, vh_out,
        khs_h, khs_l, vhs_h, vhs_l, M, DD, DD, DD, DD);

    // flash attention -> ao (split)
    flash_kernel<<<dim3(TT / 128, BB * HH), 256, FLASH_SMEM>>>(
        qs_h, khs_h, khs_l, vhs_h, vhs_l, aos_h, aos_l, scale);

    // out = concat_heads(ao) @ wo^T
    mma_gemm<M_OUT><<<dim3(DD / BN, M / BM), 256, GEMM_SMEM>>>(
        aos_h, aos_l, wos_h, wos_l, nullptr, nullptr, nullptr, out, nullptr,
        nullptr, nullptr, nullptr, nullptr, M, DD, DD, DD, DD);
}